// round 1
// baseline (speedup 1.0000x reference)
#include <cuda_runtime.h>
#include <math.h>

#define BB 8
#define SEQ 1024
#define HID 1152
#define NHEAD 16
#define HDIM 72
#define DFF 4608
#define MROWS (BB*SEQ)      // 8192
#define MOD6 (6*HID)        // 6912

// ------------------------- scratch (__device__ globals, no allocs) ----------
__device__ float g_silu_c[BB*HID];
__device__ float g_mod[BB*MOD6];
__device__ float g_ai[MROWS*HID];
__device__ float g_qkv[(size_t)MROWS*3*HID];
__device__ float g_q[MROWS*HID];
__device__ float g_k[MROWS*HID];
__device__ float g_v[MROWS*HID];
__device__ float g_o[MROWS*HID];
__device__ float g_proj[MROWS*HID];
__device__ float g_x1[MROWS*HID];
__device__ float g_mi[MROWS*HID];
__device__ float g_hbuf[(size_t)MROWS*DFF];
__device__ float g_mlp[MROWS*HID];

// ------------------------- silu(c) ------------------------------------------
__global__ void silu_kernel(const float* __restrict__ c) {
    int i = blockIdx.x * 256 + threadIdx.x;
    if (i < BB*HID) {
        float s = c[i];
        g_silu_c[i] = s / (1.f + expf(-s));
    }
}

// ------------------------- adaLN: mod = silu_c @ w_ada + b_ada --------------
__global__ void adaln_kernel(const float* __restrict__ w_ada,
                             const float* __restrict__ b_ada) {
    int j = blockIdx.x * 256 + threadIdx.x;
    int b = blockIdx.y;
    if (j >= MOD6) return;
    float acc = b_ada[j];
    const float* cs = &g_silu_c[b*HID];
    for (int k = 0; k < HID; k++)
        acc += cs[k] * w_ada[(size_t)k*MOD6 + j];
    g_mod[b*MOD6 + j] = acc;
}

// --------------- fused (optional residual+gate) + LN + modulate -------------
// x1 = x + g[b]*res (if res != null);  mi = LN(x1)*(1+sc) + sh
__global__ void modulate_kernel(const float* __restrict__ x,
                                const float* __restrict__ res,
                                int sh_seg, int sc_seg, int g_seg,
                                float* __restrict__ x1_out,
                                float* __restrict__ mi_out) {
    int r = blockIdx.x;
    int b = r / SEQ;
    const float* modb = &g_mod[b*MOD6];
    const float* xr = x + (size_t)r*HID;
    const float* rr = res ? res + (size_t)r*HID : nullptr;

    float s = 0.f, ss = 0.f;
    for (int ch = threadIdx.x; ch < HID; ch += 256) {
        float val = xr[ch];
        if (rr) val += modb[g_seg*HID + ch] * rr[ch];
        s += val; ss += val*val;
    }
    // block reduce
    int lane = threadIdx.x & 31, wid = threadIdx.x >> 5;
    #pragma unroll
    for (int o = 16; o; o >>= 1) {
        s  += __shfl_xor_sync(0xffffffffu, s, o);
        ss += __shfl_xor_sync(0xffffffffu, ss, o);
    }
    __shared__ float sh1[8], sh2[8];
    if (lane == 0) { sh1[wid] = s; sh2[wid] = ss; }
    __syncthreads();
    if (threadIdx.x == 0) {
        float a = 0.f, bb = 0.f;
        #pragma unroll
        for (int i = 0; i < 8; i++) { a += sh1[i]; bb += sh2[i]; }
        sh1[0] = a; sh2[0] = bb;
    }
    __syncthreads();
    float tsum = sh1[0], tssq = sh2[0];
    float mean = tsum * (1.f/HID);
    float var  = tssq * (1.f/HID) - mean*mean;
    float inv  = rsqrtf(var + 1e-6f);

    for (int ch = threadIdx.x; ch < HID; ch += 256) {
        float val = xr[ch];
        if (rr) val += modb[g_seg*HID + ch] * rr[ch];
        if (x1_out) x1_out[(size_t)r*HID + ch] = val;
        float y = (val - mean) * inv;
        mi_out[(size_t)r*HID + ch] = y * (1.f + modb[sc_seg*HID + ch]) + modb[sh_seg*HID + ch];
    }
}

// ------------------------- generic fp32 tiled GEMM --------------------------
// C[M,N] = A[M,K] @ W[K,N] + bias;  act: 0 none, 1 gelu(tanh)
__global__ void __launch_bounds__(256)
gemm_kernel(const float* __restrict__ A, const float* __restrict__ W,
            const float* __restrict__ bias, float* __restrict__ C,
            int M, int N, int K, int act) {
    __shared__ float As[16][65];   // padded to kill STS conflicts
    __shared__ float Bs[16][64];
    int tid = threadIdx.x;
    int tx = tid & 15, ty = tid >> 4;
    int row0 = blockIdx.y * 64, col0 = blockIdx.x * 64;

    float acc[4][4] = {};

    for (int k0 = 0; k0 < K; k0 += 16) {
        #pragma unroll
        for (int l = 0; l < 4; l++) {
            int idx = tid + l*256;
            int r = idx >> 4, kk = idx & 15;
            As[kk][r] = A[(size_t)(row0 + r)*K + k0 + kk];
        }
        #pragma unroll
        for (int l = 0; l < 4; l++) {
            int idx = tid + l*256;
            int kk = idx >> 6, c = idx & 63;
            Bs[kk][c] = W[(size_t)(k0 + kk)*N + col0 + c];
        }
        __syncthreads();
        #pragma unroll
        for (int kk = 0; kk < 16; kk++) {
            float a0 = As[kk][ty*4+0];
            float a1 = As[kk][ty*4+1];
            float a2 = As[kk][ty*4+2];
            float a3 = As[kk][ty*4+3];
            float4 bv = *(const float4*)&Bs[kk][tx*4];
            acc[0][0] += a0*bv.x; acc[0][1] += a0*bv.y; acc[0][2] += a0*bv.z; acc[0][3] += a0*bv.w;
            acc[1][0] += a1*bv.x; acc[1][1] += a1*bv.y; acc[1][2] += a1*bv.z; acc[1][3] += a1*bv.w;
            acc[2][0] += a2*bv.x; acc[2][1] += a2*bv.y; acc[2][2] += a2*bv.z; acc[2][3] += a2*bv.w;
            acc[3][0] += a3*bv.x; acc[3][1] += a3*bv.y; acc[3][2] += a3*bv.z; acc[3][3] += a3*bv.w;
        }
        __syncthreads();
    }
    #pragma unroll
    for (int i = 0; i < 4; i++) {
        #pragma unroll
        for (int j = 0; j < 4; j++) {
            int col = col0 + tx*4 + j;
            float cv = acc[i][j] + bias[col];
            if (act == 1) {
                float u = cv;
                float u3 = u*u*u;
                cv = 0.5f * u * (1.f + tanhf(0.7978845608028654f * (u + 0.044715f*u3)));
            }
            C[(size_t)(row0 + ty*4 + i)*N + col] = cv;
        }
    }
}

// ------------------------- qk-norm + reshape to [B,NH,N,HD] -----------------
__global__ void qknorm_kernel(const float* __restrict__ qn_w, const float* __restrict__ qn_b,
                              const float* __restrict__ kn_w, const float* __restrict__ kn_b) {
    int id = blockIdx.x * 8 + (threadIdx.x >> 5);
    if (id >= MROWS*48) return;
    int lane = threadIdx.x & 31;
    int r = id / 48;
    int rem = id % 48;
    int w = rem / 16;      // 0=q,1=k,2=v
    int h = rem % 16;

    const float* src = &g_qkv[(size_t)r*3456 + w*1152 + h*72];
    float v0 = src[lane];
    float v1 = src[lane + 32];
    float v2 = (lane < 8) ? src[lane + 64] : 0.f;

    int b = r / SEQ, n = r % SEQ;
    float* dst = (w == 0 ? g_q : (w == 1 ? g_k : g_v))
                 + (((size_t)(b*NHEAD + h)*SEQ + n)*HDIM);

    if (w == 2) {
        dst[lane] = v0; dst[lane+32] = v1;
        if (lane < 8) dst[lane+64] = v2;
        return;
    }
    float s = v0 + v1 + v2;
    float ss = v0*v0 + v1*v1 + v2*v2;
    #pragma unroll
    for (int o = 16; o; o >>= 1) {
        s  += __shfl_xor_sync(0xffffffffu, s, o);
        ss += __shfl_xor_sync(0xffffffffu, ss, o);
    }
    float mean = s * (1.f/72.f);
    float var  = ss * (1.f/72.f) - mean*mean;
    float inv  = rsqrtf(var + 1e-5f);
    const float* ww = (w == 0) ? qn_w : kn_w;
    const float* wb = (w == 0) ? qn_b : kn_b;
    dst[lane]      = (v0 - mean)*inv*ww[lane]      + wb[lane];
    dst[lane + 32] = (v1 - mean)*inv*ww[lane + 32] + wb[lane + 32];
    if (lane < 8)
        dst[lane + 64] = (v2 - mean)*inv*ww[lane + 64] + wb[lane + 64];
}

// ------------------------- flash-style attention ----------------------------
// grid (8 qtiles, 16 heads, 8 batch), 128 threads, thread-per-query-row.
__global__ void __launch_bounds__(128) attn_kernel() {
    __shared__ float Ks[32][72];
    __shared__ float Vs[32][72];
    __shared__ float Ss[128][33];
    int b = blockIdx.z, h = blockIdx.y, q0 = blockIdx.x * 128;
    int t = threadIdx.x;
    size_t base = (size_t)(b*NHEAD + h) * SEQ * HDIM;
    const float scale = 0.11785113019775793f;   // 72^-0.5

    float q[72], acc[72];
    const float* qp = &g_q[base + (size_t)(q0 + t)*HDIM];
    #pragma unroll
    for (int d = 0; d < 72; d++) { q[d] = qp[d]; acc[d] = 0.f; }
    float m = -INFINITY, l = 0.f;

    for (int k0 = 0; k0 < SEQ; k0 += 32) {
        __syncthreads();
        const float* kt = &g_k[base + (size_t)k0*HDIM];
        const float* vt = &g_v[base + (size_t)k0*HDIM];
        for (int i = t; i < 32*72; i += 128) {
            ((float*)Ks)[i] = kt[i];
            ((float*)Vs)[i] = vt[i];
        }
        __syncthreads();

        float tmax = -INFINITY;
        for (int j = 0; j < 32; j++) {
            float s = 0.f;
            const float4* kp = (const float4*)Ks[j];
            #pragma unroll
            for (int dd = 0; dd < 18; dd++) {
                float4 kv = kp[dd];
                s += q[dd*4+0]*kv.x + q[dd*4+1]*kv.y + q[dd*4+2]*kv.z + q[dd*4+3]*kv.w;
            }
            s *= scale;
            Ss[t][j] = s;
            tmax = fmaxf(tmax, s);
        }
        float mnew = fmaxf(m, tmax);
        float corr = expf(m - mnew);
        l *= corr;
        #pragma unroll
        for (int d = 0; d < 72; d++) acc[d] *= corr;

        for (int j = 0; j < 32; j++) {
            float p = expf(Ss[t][j] - mnew);
            l += p;
            const float4* vp = (const float4*)Vs[j];
            #pragma unroll
            for (int dd = 0; dd < 18; dd++) {
                float4 vv = vp[dd];
                acc[dd*4+0] += p*vv.x; acc[dd*4+1] += p*vv.y;
                acc[dd*4+2] += p*vv.z; acc[dd*4+3] += p*vv.w;
            }
        }
        m = mnew;
    }
    float invl = 1.f / l;
    float* op = &g_o[(size_t)(b*SEQ + q0 + t)*HID + h*HDIM];
    #pragma unroll
    for (int d = 0; d < 72; d++) op[d] = acc[d] * invl;
}

// ------------------------- final gated residual -----------------------------
__global__ void final_kernel(float* __restrict__ out) {
    int i = blockIdx.x * 256 + threadIdx.x;
    if (i < MROWS*HID) {
        int b = i / (SEQ*HID);
        int ch = i % HID;
        out[i] = g_x1[i] + g_mod[b*MOD6 + 5*HID + ch] * g_mlp[i];
    }
}

// ---------------------------------------------------------------------------
extern "C" void kernel_launch(void* const* d_in, const int* in_sizes, int n_in,
                              void* d_out, int out_size) {
    const float* x      = (const float*)d_in[0];
    const float* c      = (const float*)d_in[1];
    const float* w_ada  = (const float*)d_in[2];
    const float* b_ada  = (const float*)d_in[3];
    const float* w_qkv  = (const float*)d_in[4];
    const float* b_qkv  = (const float*)d_in[5];
    const float* qn_w   = (const float*)d_in[6];
    const float* qn_b   = (const float*)d_in[7];
    const float* kn_w   = (const float*)d_in[8];
    const float* kn_b   = (const float*)d_in[9];
    const float* w_proj = (const float*)d_in[10];
    const float* b_proj = (const float*)d_in[11];
    const float* w_fc1  = (const float*)d_in[12];
    const float* b_fc1  = (const float*)d_in[13];
    const float* w_fc2  = (const float*)d_in[14];
    const float* b_fc2  = (const float*)d_in[15];
    float* out = (float*)d_out;

    float *p_ai, *p_qkv, *p_o, *p_proj, *p_x1, *p_mi, *p_h, *p_mlp;
    cudaGetSymbolAddress((void**)&p_ai,   g_ai);
    cudaGetSymbolAddress((void**)&p_qkv,  g_qkv);
    cudaGetSymbolAddress((void**)&p_o,    g_o);
    cudaGetSymbolAddress((void**)&p_proj, g_proj);
    cudaGetSymbolAddress((void**)&p_x1,   g_x1);
    cudaGetSymbolAddress((void**)&p_mi,   g_mi);
    cudaGetSymbolAddress((void**)&p_h,    g_hbuf);
    cudaGetSymbolAddress((void**)&p_mlp,  g_mlp);

    // 1. silu(c)
    silu_kernel<<<(BB*HID + 255)/256, 256>>>(c);
    // 2. adaLN modulation vector
    adaln_kernel<<<dim3(MOD6/256, BB), 256>>>(w_ada, b_ada);
    // 3. ai = modulate(x, sh_msa, sc_msa)
    modulate_kernel<<<MROWS, 256>>>(x, nullptr, 0, 1, -1, nullptr, p_ai);
    // 4. qkv = ai @ w_qkv + b
    gemm_kernel<<<dim3(3*HID/64, MROWS/64), 256>>>(p_ai, w_qkv, b_qkv, p_qkv,
                                                   MROWS, 3*HID, HID, 0);
    // 5. qk-norm + split/transpose
    qknorm_kernel<<<MROWS*48/8, 256>>>(qn_w, qn_b, kn_w, kn_b);
    // 6. attention
    attn_kernel<<<dim3(SEQ/128, NHEAD, BB), 128>>>();
    // 7. proj
    gemm_kernel<<<dim3(HID/64, MROWS/64), 256>>>(p_o, w_proj, b_proj, p_proj,
                                                 MROWS, HID, HID, 0);
    // 8. x1 = x + g_msa*proj ; mi = modulate(x1, sh_mlp, sc_mlp)
    modulate_kernel<<<MROWS, 256>>>(x, p_proj, 3, 4, 2, p_x1, p_mi);
    // 9. h = gelu(mi @ w_fc1 + b)
    gemm_kernel<<<dim3(DFF/64, MROWS/64), 256>>>(p_mi, w_fc1, b_fc1, p_h,
                                                 MROWS, DFF, HID, 1);
    // 10. mlp = h @ w_fc2 + b
    gemm_kernel<<<dim3(HID/64, MROWS/64), 256>>>(p_h, w_fc2, b_fc2, p_mlp,
                                                 MROWS, HID, DFF, 0);
    // 11. out = x1 + g_mlp*mlp
    final_kernel<<<(MROWS*HID + 255)/256, 256>>>(out);
}

// round 2
// speedup vs baseline: 2.5018x; 2.5018x over previous
#include <cuda_runtime.h>
#include <math.h>
#include <stdint.h>

#define BB 8
#define SEQ 1024
#define HID 1152
#define NHEAD 16
#define HDIM 72
#define DFF 4608
#define MROWS (BB*SEQ)      // 8192
#define MOD6 (6*HID)        // 6912

// ------------------------- scratch (__device__ globals, no allocs) ----------
__device__ float g_silu_c[BB*HID];
__device__ float g_mod[BB*MOD6];
__device__ float g_ai[MROWS*HID];
__device__ float g_qkv[(size_t)MROWS*3*HID];
__device__ float g_q[MROWS*HID];
__device__ float g_k[MROWS*HID];
__device__ float g_v[MROWS*HID];
__device__ float g_o[MROWS*HID];
__device__ float g_proj[MROWS*HID];
__device__ float g_x1[MROWS*HID];
__device__ float g_mi[MROWS*HID];
__device__ float g_hbuf[(size_t)MROWS*DFF];
__device__ float g_mlp[MROWS*HID];
// tf32-rounded weight copies
__device__ float g_wqkv[(size_t)HID*3*HID];
__device__ float g_wproj[(size_t)HID*HID];
__device__ float g_wfc1[(size_t)HID*DFF];
__device__ float g_wfc2[(size_t)DFF*HID];

// ------------------------- helpers ------------------------------------------
__device__ __forceinline__ float rna_tf32(float x) {
    float y;
    asm("cvt.rna.tf32.f32 %0, %1;" : "=f"(y) : "f"(x));
    return y;
}

__device__ __forceinline__ void cp16(float* smem_dst, const float* gsrc) {
    unsigned s = (unsigned)__cvta_generic_to_shared(smem_dst);
    asm volatile("cp.async.cg.shared.global [%0], [%1], 16;" :: "r"(s), "l"(gsrc));
}

__device__ __forceinline__ void mma_tf32(float4& d, const uint32_t* a, const uint32_t* b) {
    asm volatile(
        "mma.sync.aligned.m16n8k8.row.col.f32.tf32.tf32.f32 "
        "{%0,%1,%2,%3}, {%4,%5,%6,%7}, {%8,%9}, {%0,%1,%2,%3};"
        : "+f"(d.x), "+f"(d.y), "+f"(d.z), "+f"(d.w)
        : "r"(a[0]), "r"(a[1]), "r"(a[2]), "r"(a[3]), "r"(b[0]), "r"(b[1]));
}

// ------------------------- weight tf32 rounding -----------------------------
__global__ void cvt_tf32_kernel(const float* __restrict__ in, float* __restrict__ out, int n) {
    int i = blockIdx.x * 256 + threadIdx.x;
    if (i < n) out[i] = rna_tf32(in[i]);
}

// ------------------------- silu(c) ------------------------------------------
__global__ void silu_kernel(const float* __restrict__ c) {
    int i = blockIdx.x * 256 + threadIdx.x;
    if (i < BB*HID) {
        float s = c[i];
        g_silu_c[i] = s / (1.f + expf(-s));
    }
}

// ------------------------- adaLN: mod = silu_c @ w_ada + b_ada --------------
__global__ void adaln_kernel(const float* __restrict__ w_ada,
                             const float* __restrict__ b_ada) {
    int j = blockIdx.x * 256 + threadIdx.x;
    int b = blockIdx.y;
    if (j >= MOD6) return;
    float acc = b_ada[j];
    const float* cs = &g_silu_c[b*HID];
    for (int k = 0; k < HID; k++)
        acc += cs[k] * w_ada[(size_t)k*MOD6 + j];
    g_mod[b*MOD6 + j] = acc;
}

// --------------- fused (optional residual+gate) + LN + modulate -------------
// x1 = x + g[b]*res (if res != null);  mi = rna_tf32( LN(x1)*(1+sc) + sh )
__global__ void modulate_kernel(const float* __restrict__ x,
                                const float* __restrict__ res,
                                int sh_seg, int sc_seg, int g_seg,
                                float* __restrict__ x1_out,
                                float* __restrict__ mi_out) {
    int r = blockIdx.x;
    int b = r / SEQ;
    const float* modb = &g_mod[b*MOD6];
    const float* xr = x + (size_t)r*HID;
    const float* rr = res ? res + (size_t)r*HID : nullptr;

    float s = 0.f, ss = 0.f;
    for (int ch = threadIdx.x; ch < HID; ch += 256) {
        float val = xr[ch];
        if (rr) val += modb[g_seg*HID + ch] * rr[ch];
        s += val; ss += val*val;
    }
    int lane = threadIdx.x & 31, wid = threadIdx.x >> 5;
    #pragma unroll
    for (int o = 16; o; o >>= 1) {
        s  += __shfl_xor_sync(0xffffffffu, s, o);
        ss += __shfl_xor_sync(0xffffffffu, ss, o);
    }
    __shared__ float sh1[8], sh2[8];
    if (lane == 0) { sh1[wid] = s; sh2[wid] = ss; }
    __syncthreads();
    if (threadIdx.x == 0) {
        float a = 0.f, bb = 0.f;
        #pragma unroll
        for (int i = 0; i < 8; i++) { a += sh1[i]; bb += sh2[i]; }
        sh1[0] = a; sh2[0] = bb;
    }
    __syncthreads();
    float mean = sh1[0] * (1.f/HID);
    float var  = sh2[0] * (1.f/HID) - mean*mean;
    float inv  = rsqrtf(var + 1e-6f);

    for (int ch = threadIdx.x; ch < HID; ch += 256) {
        float val = xr[ch];
        if (rr) val += modb[g_seg*HID + ch] * rr[ch];
        if (x1_out) x1_out[(size_t)r*HID + ch] = val;
        float y = (val - mean) * inv;
        mi_out[(size_t)r*HID + ch] =
            rna_tf32(y * (1.f + modb[sc_seg*HID + ch]) + modb[sh_seg*HID + ch]);
    }
}

// ------------------------- tf32 tensor-core GEMM ----------------------------
// C[M,N] = A[M,K] @ W[K,N] + bias.  A, W pre-rounded to tf32.
// BM=128 BN=128 BK=32, 256 threads, 8 warps (2m x 4n), warp tile 64x32.
// act: 0 none, 1 gelu(tanh).  roundOut: round C to tf32 (when C feeds a GEMM).
#define AS_STR 36
#define BS_STR 136
#define A_SZ (128*AS_STR)   // 4608 floats
#define B_SZ (32*BS_STR)    // 4352 floats
#define GEMM_SMEM ((2*A_SZ + 2*B_SZ)*4)

__global__ void __launch_bounds__(256)
gemm_tc(const float* __restrict__ A, const float* __restrict__ W,
        const float* __restrict__ bias, float* __restrict__ C,
        int M, int N, int K, int act, int roundOut) {
    extern __shared__ float smp[];
    float* As = smp;            // [2][128][36]
    float* Bs = smp + 2*A_SZ;   // [2][32][136]

    int tid = threadIdx.x, lane = tid & 31, wid = tid >> 5;
    int wm = wid >> 2, wn = wid & 3;
    int row0 = blockIdx.y * 128, col0 = blockIdx.x * 128;
    int lr = lane >> 2, lc = lane & 3;

    float4 acc[4][4];
    #pragma unroll
    for (int i = 0; i < 4; i++)
        #pragma unroll
        for (int j = 0; j < 4; j++) acc[i][j] = make_float4(0.f,0.f,0.f,0.f);

    int KT = K >> 5;

    // producer lambda (stage kt -> buffer buf)
    auto load_stage = [&](int kt, int buf) {
        const float* gA = A + (size_t)row0*K + kt*32;
        #pragma unroll
        for (int i = 0; i < 4; i++) {
            int chunk = tid + i*256;
            int r = chunk >> 3, c4 = (chunk & 7) * 4;
            cp16(&As[buf*A_SZ + r*AS_STR + c4], gA + (size_t)r*K + c4);
        }
        const float* gB = W + (size_t)(kt*32)*N + col0;
        #pragma unroll
        for (int i = 0; i < 4; i++) {
            int chunk = tid + i*256;
            int r = chunk >> 5, c4 = (chunk & 31) * 4;
            cp16(&Bs[buf*B_SZ + r*BS_STR + c4], gB + (size_t)r*N + c4);
        }
        asm volatile("cp.async.commit_group;");
    };

    load_stage(0, 0);

    for (int kt = 0; kt < KT; kt++) {
        int buf = kt & 1;
        asm volatile("cp.async.wait_group 0;");
        __syncthreads();
        if (kt + 1 < KT) load_stage(kt + 1, buf ^ 1);

        const float* as = &As[buf*A_SZ];
        const float* bs = &Bs[buf*B_SZ];
        #pragma unroll
        for (int k8 = 0; k8 < 4; k8++) {
            uint32_t af[4][4];
            #pragma unroll
            for (int mi = 0; mi < 4; mi++) {
                int r = wm*64 + mi*16 + lr;
                int c = k8*8 + lc;
                af[mi][0] = __float_as_uint(as[r*AS_STR + c]);
                af[mi][1] = __float_as_uint(as[(r+8)*AS_STR + c]);
                af[mi][2] = __float_as_uint(as[r*AS_STR + c + 4]);
                af[mi][3] = __float_as_uint(as[(r+8)*AS_STR + c + 4]);
            }
            uint32_t bf[4][2];
            #pragma unroll
            for (int nj = 0; nj < 4; nj++) {
                int cc = wn*32 + nj*8 + lr;
                bf[nj][0] = __float_as_uint(bs[(k8*8 + lc)*BS_STR + cc]);
                bf[nj][1] = __float_as_uint(bs[(k8*8 + lc + 4)*BS_STR + cc]);
            }
            #pragma unroll
            for (int mi = 0; mi < 4; mi++)
                #pragma unroll
                for (int nj = 0; nj < 4; nj++)
                    mma_tf32(acc[mi][nj], af[mi], bf[nj]);
        }
        __syncthreads();
    }

    // epilogue
    #pragma unroll
    for (int mi = 0; mi < 4; mi++) {
        #pragma unroll
        for (int nj = 0; nj < 4; nj++) {
            int r = row0 + wm*64 + mi*16 + lr;
            int c = col0 + wn*32 + nj*8 + 2*lc;
            float v[4] = {acc[mi][nj].x, acc[mi][nj].y, acc[mi][nj].z, acc[mi][nj].w};
            float b0 = bias[c], b1 = bias[c+1];
            v[0] += b0; v[1] += b1; v[2] += b0; v[3] += b1;
            if (act == 1) {
                #pragma unroll
                for (int q = 0; q < 4; q++) {
                    float u = v[q];
                    v[q] = 0.5f * u * (1.f + tanhf(0.7978845608028654f * (u + 0.044715f*u*u*u)));
                }
            }
            if (roundOut) {
                #pragma unroll
                for (int q = 0; q < 4; q++) v[q] = rna_tf32(v[q]);
            }
            *(float2*)&C[(size_t)r*N + c]       = make_float2(v[0], v[1]);
            *(float2*)&C[(size_t)(r+8)*N + c]   = make_float2(v[2], v[3]);
        }
    }
}

// ------------------------- qk-norm + reshape to [B,NH,N,HD] -----------------
__global__ void qknorm_kernel(const float* __restrict__ qn_w, const float* __restrict__ qn_b,
                              const float* __restrict__ kn_w, const float* __restrict__ kn_b) {
    int id = blockIdx.x * 8 + (threadIdx.x >> 5);
    if (id >= MROWS*48) return;
    int lane = threadIdx.x & 31;
    int r = id / 48;
    int rem = id % 48;
    int w = rem / 16;      // 0=q,1=k,2=v
    int h = rem % 16;

    const float* src = &g_qkv[(size_t)r*3456 + w*1152 + h*72];
    float v0 = src[lane];
    float v1 = src[lane + 32];
    float v2 = (lane < 8) ? src[lane + 64] : 0.f;

    int b = r / SEQ, n = r % SEQ;
    float* dst = (w == 0 ? g_q : (w == 1 ? g_k : g_v))
                 + (((size_t)(b*NHEAD + h)*SEQ + n)*HDIM);

    if (w == 2) {
        dst[lane] = v0; dst[lane+32] = v1;
        if (lane < 8) dst[lane+64] = v2;
        return;
    }
    float s = v0 + v1 + v2;
    float ss = v0*v0 + v1*v1 + v2*v2;
    #pragma unroll
    for (int o = 16; o; o >>= 1) {
        s  += __shfl_xor_sync(0xffffffffu, s, o);
        ss += __shfl_xor_sync(0xffffffffu, ss, o);
    }
    float mean = s * (1.f/72.f);
    float var  = ss * (1.f/72.f) - mean*mean;
    float inv  = rsqrtf(var + 1e-5f);
    const float* ww = (w == 0) ? qn_w : kn_w;
    const float* wb = (w == 0) ? qn_b : kn_b;
    dst[lane]      = (v0 - mean)*inv*ww[lane]      + wb[lane];
    dst[lane + 32] = (v1 - mean)*inv*ww[lane + 32] + wb[lane + 32];
    if (lane < 8)
        dst[lane + 64] = (v2 - mean)*inv*ww[lane + 64] + wb[lane + 64];
}

// ------------------------- flash-style attention ----------------------------
__global__ void __launch_bounds__(128) attn_kernel() {
    __shared__ float Ks[32][72];
    __shared__ float Vs[32][72];
    __shared__ float Ss[128][33];
    int b = blockIdx.z, h = blockIdx.y, q0 = blockIdx.x * 128;
    int t = threadIdx.x;
    size_t base = (size_t)(b*NHEAD + h) * SEQ * HDIM;
    const float scale = 0.11785113019775793f;   // 72^-0.5

    float q[72], acc[72];
    const float* qp = &g_q[base + (size_t)(q0 + t)*HDIM];
    #pragma unroll
    for (int d = 0; d < 72; d++) { q[d] = qp[d]; acc[d] = 0.f; }
    float m = -INFINITY, l = 0.f;

    for (int k0 = 0; k0 < SEQ; k0 += 32) {
        __syncthreads();
        const float* kt = &g_k[base + (size_t)k0*HDIM];
        const float* vt = &g_v[base + (size_t)k0*HDIM];
        for (int i = t; i < 32*72; i += 128) {
            ((float*)Ks)[i] = kt[i];
            ((float*)Vs)[i] = vt[i];
        }
        __syncthreads();

        float tmax = -INFINITY;
        for (int j = 0; j < 32; j++) {
            float s = 0.f;
            const float4* kp = (const float4*)Ks[j];
            #pragma unroll
            for (int dd = 0; dd < 18; dd++) {
                float4 kv = kp[dd];
                s += q[dd*4+0]*kv.x + q[dd*4+1]*kv.y + q[dd*4+2]*kv.z + q[dd*4+3]*kv.w;
            }
            s *= scale;
            Ss[t][j] = s;
            tmax = fmaxf(tmax, s);
        }
        float mnew = fmaxf(m, tmax);
        float corr = expf(m - mnew);
        l *= corr;
        #pragma unroll
        for (int d = 0; d < 72; d++) acc[d] *= corr;

        for (int j = 0; j < 32; j++) {
            float p = expf(Ss[t][j] - mnew);
            l += p;
            const float4* vp = (const float4*)Vs[j];
            #pragma unroll
            for (int dd = 0; dd < 18; dd++) {
                float4 vv = vp[dd];
                acc[dd*4+0] += p*vv.x; acc[dd*4+1] += p*vv.y;
                acc[dd*4+2] += p*vv.z; acc[dd*4+3] += p*vv.w;
            }
        }
        m = mnew;
    }
    float invl = 1.f / l;
    float* op = &g_o[(size_t)(b*SEQ + q0 + t)*HID + h*HDIM];
    #pragma unroll
    for (int d = 0; d < 72; d++) op[d] = rna_tf32(acc[d] * invl);
}

// ------------------------- final gated residual -----------------------------
__global__ void final_kernel(float* __restrict__ out) {
    int i = blockIdx.x * 256 + threadIdx.x;
    if (i < MROWS*HID) {
        int b = i / (SEQ*HID);
        int ch = i % HID;
        out[i] = g_x1[i] + g_mod[b*MOD6 + 5*HID + ch] * g_mlp[i];
    }
}

// ---------------------------------------------------------------------------
extern "C" void kernel_launch(void* const* d_in, const int* in_sizes, int n_in,
                              void* d_out, int out_size) {
    const float* x      = (const float*)d_in[0];
    const float* c      = (const float*)d_in[1];
    const float* w_ada  = (const float*)d_in[2];
    const float* b_ada  = (const float*)d_in[3];
    const float* w_qkv  = (const float*)d_in[4];
    const float* b_qkv  = (const float*)d_in[5];
    const float* qn_w   = (const float*)d_in[6];
    const float* qn_b   = (const float*)d_in[7];
    const float* kn_w   = (const float*)d_in[8];
    const float* kn_b   = (const float*)d_in[9];
    const float* w_proj = (const float*)d_in[10];
    const float* b_proj = (const float*)d_in[11];
    const float* w_fc1  = (const float*)d_in[12];
    const float* b_fc1  = (const float*)d_in[13];
    const float* w_fc2  = (const float*)d_in[14];
    const float* b_fc2  = (const float*)d_in[15];
    float* out = (float*)d_out;

    float *p_ai, *p_qkv, *p_o, *p_proj, *p_x1, *p_mi, *p_h, *p_mlp;
    float *p_wqkv, *p_wproj, *p_wfc1, *p_wfc2;
    cudaGetSymbolAddress((void**)&p_ai,   g_ai);
    cudaGetSymbolAddress((void**)&p_qkv,  g_qkv);
    cudaGetSymbolAddress((void**)&p_o,    g_o);
    cudaGetSymbolAddress((void**)&p_proj, g_proj);
    cudaGetSymbolAddress((void**)&p_x1,   g_x1);
    cudaGetSymbolAddress((void**)&p_mi,   g_mi);
    cudaGetSymbolAddress((void**)&p_h,    g_hbuf);
    cudaGetSymbolAddress((void**)&p_mlp,  g_mlp);
    cudaGetSymbolAddress((void**)&p_wqkv, g_wqkv);
    cudaGetSymbolAddress((void**)&p_wproj,g_wproj);
    cudaGetSymbolAddress((void**)&p_wfc1, g_wfc1);
    cudaGetSymbolAddress((void**)&p_wfc2, g_wfc2);

    static int smem_set = 0;
    if (!smem_set) {
        cudaFuncSetAttribute(gemm_tc, cudaFuncAttributeMaxDynamicSharedMemorySize, GEMM_SMEM);
        smem_set = 1;
    }

    // 0. weight tf32 rounding
    cvt_tf32_kernel<<<(HID*3*HID + 255)/256, 256>>>(w_qkv, p_wqkv, HID*3*HID);
    cvt_tf32_kernel<<<(HID*HID + 255)/256, 256>>>(w_proj, p_wproj, HID*HID);
    cvt_tf32_kernel<<<(HID*DFF + 255)/256, 256>>>(w_fc1, p_wfc1, HID*DFF);
    cvt_tf32_kernel<<<(HID*DFF + 255)/256, 256>>>(w_fc2, p_wfc2, HID*DFF);
    // 1. silu(c)
    silu_kernel<<<(BB*HID + 255)/256, 256>>>(c);
    // 2. adaLN modulation vector
    adaln_kernel<<<dim3(MOD6/256, BB), 256>>>(w_ada, b_ada);
    // 3. ai = modulate(x, sh_msa, sc_msa)  (tf32-rounded)
    modulate_kernel<<<MROWS, 256>>>(x, nullptr, 0, 1, -1, nullptr, p_ai);
    // 4. qkv = ai @ w_qkv + b
    gemm_tc<<<dim3(3*HID/128, MROWS/128), 256, GEMM_SMEM>>>(p_ai, p_wqkv, b_qkv, p_qkv,
                                                            MROWS, 3*HID, HID, 0, 0);
    // 5. qk-norm + split/transpose
    qknorm_kernel<<<MROWS*48/8, 256>>>(qn_w, qn_b, kn_w, kn_b);
    // 6. attention (fp32; output tf32-rounded)
    attn_kernel<<<dim3(SEQ/128, NHEAD, BB), 128>>>();
    // 7. proj
    gemm_tc<<<dim3(HID/128, MROWS/128), 256, GEMM_SMEM>>>(p_o, p_wproj, b_proj, p_proj,
                                                          MROWS, HID, HID, 0, 0);
    // 8. x1 = x + g_msa*proj ; mi = modulate(x1, sh_mlp, sc_mlp) (tf32-rounded)
    modulate_kernel<<<MROWS, 256>>>(x, p_proj, 3, 4, 2, p_x1, p_mi);
    // 9. h = gelu(mi @ w_fc1 + b)  (output tf32-rounded: feeds fc2)
    gemm_tc<<<dim3(DFF/128, MROWS/128), 256, GEMM_SMEM>>>(p_mi, p_wfc1, b_fc1, p_h,
                                                          MROWS, DFF, HID, 1, 1);
    // 10. mlp = h @ w_fc2 + b
    gemm_tc<<<dim3(HID/128, MROWS/128), 256, GEMM_SMEM>>>(p_h, p_wfc2, b_fc2, p_mlp,
                                                          MROWS, HID, DFF, 0, 0);
    // 11. out = x1 + g_mlp*mlp
    final_kernel<<<(MROWS*HID + 255)/256, 256>>>(out);
}

// round 3
// speedup vs baseline: 3.9377x; 1.5740x over previous
#include <cuda_runtime.h>
#include <math.h>
#include <stdint.h>

#define BB 8
#define SEQ 1024
#define HID 1152
#define NHEAD 16
#define HDIM 72
#define DFF 4608
#define MROWS (BB*SEQ)      // 8192
#define MOD6 (6*HID)        // 6912

// ------------------------- scratch (__device__ globals, no allocs) ----------
__device__ float g_silu_c[BB*HID];
__device__ float g_mod[BB*MOD6];
__device__ float g_ai[MROWS*HID];
__device__ float g_qkv[(size_t)MROWS*3*HID];
__device__ float g_q[MROWS*HID];
__device__ float g_k[MROWS*HID];
__device__ float g_v[MROWS*HID];
__device__ float g_o[MROWS*HID];
__device__ float g_proj[MROWS*HID];
__device__ float g_x1[MROWS*HID];
__device__ float g_mi[MROWS*HID];
__device__ float g_hbuf[(size_t)MROWS*DFF];
// tf32-rounded weight copies
__device__ float g_wqkv[(size_t)HID*3*HID];
__device__ float g_wproj[(size_t)HID*HID];
__device__ float g_wfc1[(size_t)HID*DFF];
__device__ float g_wfc2[(size_t)DFF*HID];

// ------------------------- helpers ------------------------------------------
__device__ __forceinline__ float rna_tf32(float x) {
    float y;
    asm("cvt.rna.tf32.f32 %0, %1;" : "=f"(y) : "f"(x));
    return y;
}

__device__ __forceinline__ void cp16(float* smem_dst, const float* gsrc) {
    unsigned s = (unsigned)__cvta_generic_to_shared(smem_dst);
    asm volatile("cp.async.cg.shared.global [%0], [%1], 16;" :: "r"(s), "l"(gsrc));
}

__device__ __forceinline__ void mma_tf32(float4& d, const uint32_t* a, const uint32_t* b) {
    asm volatile(
        "mma.sync.aligned.m16n8k8.row.col.f32.tf32.tf32.f32 "
        "{%0,%1,%2,%3}, {%4,%5,%6,%7}, {%8,%9}, {%0,%1,%2,%3};"
        : "+f"(d.x), "+f"(d.y), "+f"(d.z), "+f"(d.w)
        : "r"(a[0]), "r"(a[1]), "r"(a[2]), "r"(a[3]), "r"(b[0]), "r"(b[1]));
}

// ------------------------- weight tf32 rounding -----------------------------
__global__ void cvt_tf32_kernel(const float* __restrict__ in, float* __restrict__ out, int n) {
    int i = blockIdx.x * 256 + threadIdx.x;
    if (i < n) out[i] = rna_tf32(in[i]);
}

// ------------------------- silu(c) ------------------------------------------
__global__ void silu_kernel(const float* __restrict__ c) {
    int i = blockIdx.x * 256 + threadIdx.x;
    if (i < BB*HID) {
        float s = c[i];
        g_silu_c[i] = s / (1.f + expf(-s));
    }
}

// ------------------------- adaLN: mod = silu_c @ w_ada + b_ada --------------
__global__ void adaln_kernel(const float* __restrict__ w_ada,
                             const float* __restrict__ b_ada) {
    int j = blockIdx.x * 256 + threadIdx.x;
    int b = blockIdx.y;
    if (j >= MOD6) return;
    float acc = b_ada[j];
    const float* cs = &g_silu_c[b*HID];
    for (int k = 0; k < HID; k++)
        acc += cs[k] * w_ada[(size_t)k*MOD6 + j];
    g_mod[b*MOD6 + j] = acc;
}

// --------------- fused (optional residual+gate) + LN + modulate -------------
__global__ void modulate_kernel(const float* __restrict__ x,
                                const float* __restrict__ res,
                                int sh_seg, int sc_seg, int g_seg,
                                float* __restrict__ x1_out,
                                float* __restrict__ mi_out) {
    int r = blockIdx.x;
    int b = r / SEQ;
    const float* modb = &g_mod[b*MOD6];
    const float* xr = x + (size_t)r*HID;
    const float* rr = res ? res + (size_t)r*HID : nullptr;

    float s = 0.f, ss = 0.f;
    for (int ch = threadIdx.x; ch < HID; ch += 256) {
        float val = xr[ch];
        if (rr) val += modb[g_seg*HID + ch] * rr[ch];
        s += val; ss += val*val;
    }
    int lane = threadIdx.x & 31, wid = threadIdx.x >> 5;
    #pragma unroll
    for (int o = 16; o; o >>= 1) {
        s  += __shfl_xor_sync(0xffffffffu, s, o);
        ss += __shfl_xor_sync(0xffffffffu, ss, o);
    }
    __shared__ float sh1[8], sh2[8];
    if (lane == 0) { sh1[wid] = s; sh2[wid] = ss; }
    __syncthreads();
    if (threadIdx.x == 0) {
        float a = 0.f, bb = 0.f;
        #pragma unroll
        for (int i = 0; i < 8; i++) { a += sh1[i]; bb += sh2[i]; }
        sh1[0] = a; sh2[0] = bb;
    }
    __syncthreads();
    float mean = sh1[0] * (1.f/HID);
    float var  = sh2[0] * (1.f/HID) - mean*mean;
    float inv  = rsqrtf(var + 1e-6f);

    for (int ch = threadIdx.x; ch < HID; ch += 256) {
        float val = xr[ch];
        if (rr) val += modb[g_seg*HID + ch] * rr[ch];
        if (x1_out) x1_out[(size_t)r*HID + ch] = val;
        float y = (val - mean) * inv;
        mi_out[(size_t)r*HID + ch] =
            rna_tf32(y * (1.f + modb[sc_seg*HID + ch]) + modb[sh_seg*HID + ch]);
    }
}

// ------------------------- tf32 tensor-core GEMM ----------------------------
// BM=128 BN=128 BK=32, 128 threads, 4 warps (2m x 2n), warp tile 64x64.
// act: 0 none, 1 gelu(tanh). roundOut: tf32-round C.
// resid/gate_seg: fused  C = resid + g_mod[gate]*C  epilogue (for fc2).
#define AS_STR 36
#define BS_STR 136
#define A_SZ (128*AS_STR)
#define B_SZ (32*BS_STR)
#define GEMM_SMEM ((2*A_SZ + 2*B_SZ)*4)

__global__ void __launch_bounds__(128)
gemm_tc(const float* __restrict__ A, const float* __restrict__ W,
        const float* __restrict__ bias, float* __restrict__ C,
        int M, int N, int K, int act, int roundOut,
        const float* __restrict__ resid, int gate_seg) {
    extern __shared__ float smp[];
    float* As = smp;
    float* Bs = smp + 2*A_SZ;

    int tid = threadIdx.x, lane = tid & 31, wid = tid >> 5;
    int wm = wid >> 1, wn = wid & 1;
    int row0 = blockIdx.y * 128, col0 = blockIdx.x * 128;
    int lr = lane >> 2, lc = lane & 3;

    float4 acc[4][8];
    #pragma unroll
    for (int i = 0; i < 4; i++)
        #pragma unroll
        for (int j = 0; j < 8; j++) acc[i][j] = make_float4(0.f,0.f,0.f,0.f);

    int KT = K >> 5;

    auto load_stage = [&](int kt, int buf) {
        const float* gA = A + (size_t)row0*K + kt*32;
        #pragma unroll
        for (int i = 0; i < 8; i++) {
            int chunk = tid + i*128;
            int r = chunk >> 3, c4 = (chunk & 7) * 4;
            cp16(&As[buf*A_SZ + r*AS_STR + c4], gA + (size_t)r*K + c4);
        }
        const float* gB = W + (size_t)(kt*32)*N + col0;
        #pragma unroll
        for (int i = 0; i < 8; i++) {
            int chunk = tid + i*128;
            int r = chunk >> 5, c4 = (chunk & 31) * 4;
            cp16(&Bs[buf*B_SZ + r*BS_STR + c4], gB + (size_t)r*N + c4);
        }
        asm volatile("cp.async.commit_group;");
    };

    load_stage(0, 0);

    for (int kt = 0; kt < KT; kt++) {
        int buf = kt & 1;
        asm volatile("cp.async.wait_group 0;");
        __syncthreads();
        if (kt + 1 < KT) load_stage(kt + 1, buf ^ 1);

        const float* as = &As[buf*A_SZ];
        const float* bs = &Bs[buf*B_SZ];
        #pragma unroll
        for (int k8 = 0; k8 < 4; k8++) {
            int c = k8*8 + lc;
            uint32_t af[4][4];
            #pragma unroll
            for (int mi = 0; mi < 4; mi++) {
                int r = wm*64 + mi*16 + lr;
                af[mi][0] = __float_as_uint(as[r*AS_STR + c]);
                af[mi][1] = __float_as_uint(as[(r+8)*AS_STR + c]);
                af[mi][2] = __float_as_uint(as[r*AS_STR + c + 4]);
                af[mi][3] = __float_as_uint(as[(r+8)*AS_STR + c + 4]);
            }
            uint32_t bf[8][2];
            #pragma unroll
            for (int nj = 0; nj < 8; nj++) {
                int cc = wn*64 + nj*8 + lr;
                bf[nj][0] = __float_as_uint(bs[c*BS_STR + cc]);
                bf[nj][1] = __float_as_uint(bs[(c+4)*BS_STR + cc]);
            }
            #pragma unroll
            for (int mi = 0; mi < 4; mi++)
                #pragma unroll
                for (int nj = 0; nj < 8; nj++)
                    mma_tf32(acc[mi][nj], af[mi], bf[nj]);
        }
        __syncthreads();
    }

    #pragma unroll
    for (int mi = 0; mi < 4; mi++) {
        #pragma unroll
        for (int nj = 0; nj < 8; nj++) {
            int r = row0 + wm*64 + mi*16 + lr;
            int c = col0 + wn*64 + nj*8 + 2*lc;
            float v[4] = {acc[mi][nj].x, acc[mi][nj].y, acc[mi][nj].z, acc[mi][nj].w};
            float b0 = bias[c], b1 = bias[c+1];
            v[0] += b0; v[1] += b1; v[2] += b0; v[3] += b1;
            if (act == 1) {
                #pragma unroll
                for (int q = 0; q < 4; q++) {
                    float u = v[q];
                    v[q] = 0.5f * u * (1.f + tanhf(0.7978845608028654f * (u + 0.044715f*u*u*u)));
                }
            }
            if (roundOut) {
                #pragma unroll
                for (int q = 0; q < 4; q++) v[q] = rna_tf32(v[q]);
            }
            if (resid) {
                int b = r / SEQ;
                float g0 = g_mod[b*MOD6 + gate_seg*HID + c];
                float g1 = g_mod[b*MOD6 + gate_seg*HID + c + 1];
                v[0] = resid[(size_t)r*N + c]     + g0*v[0];
                v[1] = resid[(size_t)r*N + c + 1] + g1*v[1];
                v[2] = resid[(size_t)(r+8)*N + c]     + g0*v[2];
                v[3] = resid[(size_t)(r+8)*N + c + 1] + g1*v[3];
            }
            *(float2*)&C[(size_t)r*N + c]     = make_float2(v[0], v[1]);
            *(float2*)&C[(size_t)(r+8)*N + c] = make_float2(v[2], v[3]);
        }
    }
}

// ------------------------- qk-norm + reshape to [B,NH,N,HD] -----------------
__global__ void qknorm_kernel(const float* __restrict__ qn_w, const float* __restrict__ qn_b,
                              const float* __restrict__ kn_w, const float* __restrict__ kn_b) {
    int id = blockIdx.x * 8 + (threadIdx.x >> 5);
    if (id >= MROWS*48) return;
    int lane = threadIdx.x & 31;
    int r = id / 48;
    int rem = id % 48;
    int w = rem / 16;
    int h = rem % 16;

    const float* src = &g_qkv[(size_t)r*3456 + w*1152 + h*72];
    float v0 = src[lane];
    float v1 = src[lane + 32];
    float v2 = (lane < 8) ? src[lane + 64] : 0.f;

    int b = r / SEQ, n = r % SEQ;
    float* dst = (w == 0 ? g_q : (w == 1 ? g_k : g_v))
                 + (((size_t)(b*NHEAD + h)*SEQ + n)*HDIM);

    if (w == 2) {
        dst[lane] = rna_tf32(v0); dst[lane+32] = rna_tf32(v1);
        if (lane < 8) dst[lane+64] = rna_tf32(v2);
        return;
    }
    float s = v0 + v1 + v2;
    float ss = v0*v0 + v1*v1 + v2*v2;
    #pragma unroll
    for (int o = 16; o; o >>= 1) {
        s  += __shfl_xor_sync(0xffffffffu, s, o);
        ss += __shfl_xor_sync(0xffffffffu, ss, o);
    }
    float mean = s * (1.f/72.f);
    float var  = ss * (1.f/72.f) - mean*mean;
    float inv  = rsqrtf(var + 1e-5f);
    const float* ww = (w == 0) ? qn_w : kn_w;
    const float* wb = (w == 0) ? qn_b : kn_b;
    dst[lane]      = rna_tf32((v0 - mean)*inv*ww[lane]      + wb[lane]);
    dst[lane + 32] = rna_tf32((v1 - mean)*inv*ww[lane + 32] + wb[lane + 32]);
    if (lane < 8)
        dst[lane + 64] = rna_tf32((v2 - mean)*inv*ww[lane + 64] + wb[lane + 64]);
}

// ------------------------- tensor-core flash attention ----------------------
// grid (8 qtiles, 16 heads, 8 batch), 256 threads = 8 warps, warp = 16 q-rows.
// key tile = 64.  S = Q K^T (tf32 mma), online softmax in regs, O += P V.
#define QS_STR 76
#define KT_STR 72
#define VS_STR 72
#define PS_STR 68
#define ATTN_SMEM ((128*QS_STR + 72*KT_STR + 64*VS_STR + 128*PS_STR)*4)

__global__ void __launch_bounds__(256) attn_tc() {
    extern __shared__ float sm[];
    float* Qs = sm;                          // [128][76]
    float* Kt = Qs + 128*QS_STR;             // [72][72]  (K transposed: [d][key])
    float* Vs = Kt + 72*KT_STR;              // [64][72]
    float* Ps = Vs + 64*VS_STR;              // [128][68]

    int b = blockIdx.z, h = blockIdx.y, q0 = blockIdx.x*128;
    int tid = threadIdx.x, lane = tid & 31, wid = tid >> 5;
    int lr = lane >> 2, lc = lane & 3;
    int wr = wid * 16;
    size_t base = (size_t)(b*NHEAD + h) * SEQ * HDIM;
    const float scale = 0.11785113019775793f;  // 72^-0.5

    // load Q tile
    for (int i = tid; i < 128*18; i += 256) {
        int r = i / 18, d4 = (i % 18) * 4;
        *(float4*)&Qs[r*QS_STR + d4] = *(const float4*)&g_q[base + (size_t)(q0 + r)*HDIM + d4];
    }

    float4 o[9];
    #pragma unroll
    for (int i = 0; i < 9; i++) o[i] = make_float4(0.f,0.f,0.f,0.f);
    float m_lo = -INFINITY, m_hi = -INFINITY, l_lo = 0.f, l_hi = 0.f;

    for (int t = 0; t < 16; t++) {
        __syncthreads();
        // load K tile transposed + V tile
        const float* kg = &g_k[base + (size_t)(t*64)*HDIM];
        for (int i = tid; i < 64*18; i += 256) {
            int j = i & 63, d4 = i >> 6;
            float4 kv = *(const float4*)&kg[(size_t)j*HDIM + d4*4];
            Kt[(4*d4+0)*KT_STR + j] = kv.x;
            Kt[(4*d4+1)*KT_STR + j] = kv.y;
            Kt[(4*d4+2)*KT_STR + j] = kv.z;
            Kt[(4*d4+3)*KT_STR + j] = kv.w;
        }
        const float* vg = &g_v[base + (size_t)(t*64)*HDIM];
        for (int i = tid; i < 64*18; i += 256) {
            int j = i / 18, d4 = (i % 18) * 4;
            *(float4*)&Vs[j*VS_STR + d4] = *(const float4*)&vg[(size_t)j*HDIM + d4];
        }
        __syncthreads();

        // S = Q K^T  (warp rows wr..wr+15, keys 0..63)
        float4 sc[8];
        #pragma unroll
        for (int i = 0; i < 8; i++) sc[i] = make_float4(0.f,0.f,0.f,0.f);
        #pragma unroll
        for (int k8 = 0; k8 < 9; k8++) {
            int c = k8*8 + lc;
            uint32_t af[4];
            af[0] = __float_as_uint(Qs[(wr+lr)*QS_STR + c]);
            af[1] = __float_as_uint(Qs[(wr+8+lr)*QS_STR + c]);
            af[2] = __float_as_uint(Qs[(wr+lr)*QS_STR + c + 4]);
            af[3] = __float_as_uint(Qs[(wr+8+lr)*QS_STR + c + 4]);
            #pragma unroll
            for (int nj = 0; nj < 8; nj++) {
                uint32_t bf[2];
                bf[0] = __float_as_uint(Kt[c*KT_STR + nj*8 + lr]);
                bf[1] = __float_as_uint(Kt[(c+4)*KT_STR + nj*8 + lr]);
                mma_tf32(sc[nj], af, bf);
            }
        }

        // online softmax (rows lr and lr+8 of this warp)
        float tmax_lo = -INFINITY, tmax_hi = -INFINITY;
        #pragma unroll
        for (int nj = 0; nj < 8; nj++) {
            sc[nj].x *= scale; sc[nj].y *= scale; sc[nj].z *= scale; sc[nj].w *= scale;
            tmax_lo = fmaxf(tmax_lo, fmaxf(sc[nj].x, sc[nj].y));
            tmax_hi = fmaxf(tmax_hi, fmaxf(sc[nj].z, sc[nj].w));
        }
        tmax_lo = fmaxf(tmax_lo, __shfl_xor_sync(0xffffffffu, tmax_lo, 1));
        tmax_lo = fmaxf(tmax_lo, __shfl_xor_sync(0xffffffffu, tmax_lo, 2));
        tmax_hi = fmaxf(tmax_hi, __shfl_xor_sync(0xffffffffu, tmax_hi, 1));
        tmax_hi = fmaxf(tmax_hi, __shfl_xor_sync(0xffffffffu, tmax_hi, 2));

        float mn_lo = fmaxf(m_lo, tmax_lo);
        float mn_hi = fmaxf(m_hi, tmax_hi);
        float corr_lo = __expf(m_lo - mn_lo);
        float corr_hi = __expf(m_hi - mn_hi);
        l_lo *= corr_lo; l_hi *= corr_hi;
        #pragma unroll
        for (int i = 0; i < 9; i++) {
            o[i].x *= corr_lo; o[i].y *= corr_lo;
            o[i].z *= corr_hi; o[i].w *= corr_hi;
        }
        float sum_lo = 0.f, sum_hi = 0.f;
        #pragma unroll
        for (int nj = 0; nj < 8; nj++) {
            float px = __expf(sc[nj].x - mn_lo);
            float py = __expf(sc[nj].y - mn_lo);
            float pz = __expf(sc[nj].z - mn_hi);
            float pw = __expf(sc[nj].w - mn_hi);
            sum_lo += px + py; sum_hi += pz + pw;
            *(float2*)&Ps[(wr+lr)*PS_STR + nj*8 + 2*lc]   = make_float2(px, py);
            *(float2*)&Ps[(wr+8+lr)*PS_STR + nj*8 + 2*lc] = make_float2(pz, pw);
        }
        sum_lo += __shfl_xor_sync(0xffffffffu, sum_lo, 1);
        sum_lo += __shfl_xor_sync(0xffffffffu, sum_lo, 2);
        sum_hi += __shfl_xor_sync(0xffffffffu, sum_hi, 1);
        sum_hi += __shfl_xor_sync(0xffffffffu, sum_hi, 2);
        l_lo += sum_lo; l_hi += sum_hi;
        m_lo = mn_lo; m_hi = mn_hi;
        __syncwarp();

        // O += P V   (K=64 keys, N=72)
        #pragma unroll
        for (int k8 = 0; k8 < 8; k8++) {
            int c = k8*8 + lc;
            uint32_t af[4];
            af[0] = __float_as_uint(Ps[(wr+lr)*PS_STR + c]);
            af[1] = __float_as_uint(Ps[(wr+8+lr)*PS_STR + c]);
            af[2] = __float_as_uint(Ps[(wr+lr)*PS_STR + c + 4]);
            af[3] = __float_as_uint(Ps[(wr+8+lr)*PS_STR + c + 4]);
            #pragma unroll
            for (int n9 = 0; n9 < 9; n9++) {
                uint32_t bf[2];
                bf[0] = __float_as_uint(Vs[c*VS_STR + n9*8 + lr]);
                bf[1] = __float_as_uint(Vs[(c+4)*VS_STR + n9*8 + lr]);
                mma_tf32(o[n9], af, bf);
            }
        }
    }

    // epilogue: O/l -> g_o (row-major [B*SEQ][HID], head slice), tf32-rounded
    float inv_lo = 1.f / l_lo, inv_hi = 1.f / l_hi;
    int r = b*SEQ + q0 + wr + lr;
    #pragma unroll
    for (int n9 = 0; n9 < 9; n9++) {
        int c = h*HDIM + n9*8 + 2*lc;
        *(float2*)&g_o[(size_t)r*HID + c] =
            make_float2(rna_tf32(o[n9].x*inv_lo), rna_tf32(o[n9].y*inv_lo));
        *(float2*)&g_o[(size_t)(r+8)*HID + c] =
            make_float2(rna_tf32(o[n9].z*inv_hi), rna_tf32(o[n9].w*inv_hi));
    }
}

// ---------------------------------------------------------------------------
extern "C" void kernel_launch(void* const* d_in, const int* in_sizes, int n_in,
                              void* d_out, int out_size) {
    const float* x      = (const float*)d_in[0];
    const float* c      = (const float*)d_in[1];
    const float* w_ada  = (const float*)d_in[2];
    const float* b_ada  = (const float*)d_in[3];
    const float* w_qkv  = (const float*)d_in[4];
    const float* b_qkv  = (const float*)d_in[5];
    const float* qn_w   = (const float*)d_in[6];
    const float* qn_b   = (const float*)d_in[7];
    const float* kn_w   = (const float*)d_in[8];
    const float* kn_b   = (const float*)d_in[9];
    const float* w_proj = (const float*)d_in[10];
    const float* b_proj = (const float*)d_in[11];
    const float* w_fc1  = (const float*)d_in[12];
    const float* b_fc1  = (const float*)d_in[13];
    const float* w_fc2  = (const float*)d_in[14];
    const float* b_fc2  = (const float*)d_in[15];
    float* out = (float*)d_out;

    float *p_ai, *p_qkv, *p_o, *p_proj, *p_x1, *p_mi, *p_h;
    float *p_wqkv, *p_wproj, *p_wfc1, *p_wfc2;
    cudaGetSymbolAddress((void**)&p_ai,   g_ai);
    cudaGetSymbolAddress((void**)&p_qkv,  g_qkv);
    cudaGetSymbolAddress((void**)&p_o,    g_o);
    cudaGetSymbolAddress((void**)&p_proj, g_proj);
    cudaGetSymbolAddress((void**)&p_x1,   g_x1);
    cudaGetSymbolAddress((void**)&p_mi,   g_mi);
    cudaGetSymbolAddress((void**)&p_h,    g_hbuf);
    cudaGetSymbolAddress((void**)&p_wqkv, g_wqkv);
    cudaGetSymbolAddress((void**)&p_wproj,g_wproj);
    cudaGetSymbolAddress((void**)&p_wfc1, g_wfc1);
    cudaGetSymbolAddress((void**)&p_wfc2, g_wfc2);

    static int attr_set = 0;
    if (!attr_set) {
        cudaFuncSetAttribute(gemm_tc, cudaFuncAttributeMaxDynamicSharedMemorySize, GEMM_SMEM);
        cudaFuncSetAttribute(attn_tc, cudaFuncAttributeMaxDynamicSharedMemorySize, ATTN_SMEM);
        attr_set = 1;
    }

    cvt_tf32_kernel<<<(HID*3*HID + 255)/256, 256>>>(w_qkv, p_wqkv, HID*3*HID);
    cvt_tf32_kernel<<<(HID*HID + 255)/256, 256>>>(w_proj, p_wproj, HID*HID);
    cvt_tf32_kernel<<<(HID*DFF + 255)/256, 256>>>(w_fc1, p_wfc1, HID*DFF);
    cvt_tf32_kernel<<<(HID*DFF + 255)/256, 256>>>(w_fc2, p_wfc2, HID*DFF);
    silu_kernel<<<(BB*HID + 255)/256, 256>>>(c);
    adaln_kernel<<<dim3(MOD6/256, BB), 256>>>(w_ada, b_ada);
    modulate_kernel<<<MROWS, 256>>>(x, nullptr, 0, 1, -1, nullptr, p_ai);
    gemm_tc<<<dim3(3*HID/128, MROWS/128), 128, GEMM_SMEM>>>(p_ai, p_wqkv, b_qkv, p_qkv,
                                                            MROWS, 3*HID, HID, 0, 0, nullptr, 0);
    qknorm_kernel<<<MROWS*48/8, 256>>>(qn_w, qn_b, kn_w, kn_b);
    attn_tc<<<dim3(SEQ/128, NHEAD, BB), 256, ATTN_SMEM>>>();
    gemm_tc<<<dim3(HID/128, MROWS/128), 128, GEMM_SMEM>>>(p_o, p_wproj, b_proj, p_proj,
                                                          MROWS, HID, HID, 0, 0, nullptr, 0);
    modulate_kernel<<<MROWS, 256>>>(x, p_proj, 3, 4, 2, p_x1, p_mi);
    gemm_tc<<<dim3(DFF/128, MROWS/128), 128, GEMM_SMEM>>>(p_mi, p_wfc1, b_fc1, p_h,
                                                          MROWS, DFF, HID, 1, 1, nullptr, 0);
    // fc2 with fused  out = x1 + g_mlp * (h @ w_fc2 + b)
    gemm_tc<<<dim3(HID/128, MROWS/128), 128, GEMM_SMEM>>>(p_h, p_wfc2, b_fc2, out,
                                                          MROWS, HID, DFF, 0, 0, p_x1, 5);
}

// round 5
// speedup vs baseline: 5.5694x; 1.4144x over previous
#include <cuda_runtime.h>
#include <cuda_bf16.h>
#include <math.h>
#include <stdint.h>

#define BB 8
#define SEQ 1024
#define HID 1152
#define NHEAD 16
#define HDIM 72
#define DFF 4608
#define MROWS (BB*SEQ)      // 8192
#define MOD6 (6*HID)        // 6912

// ------------------------- scratch (__device__ globals, no allocs) ----------
__device__ float g_silu_c[BB*HID];
__device__ float g_mod[BB*MOD6];
__device__ float g_qkv[(size_t)MROWS*3*HID];
__device__ float g_q[MROWS*HID];
__device__ float g_k[MROWS*HID];
__device__ float g_v[MROWS*HID];
__device__ float g_proj[MROWS*HID];
__device__ float g_x1[MROWS*HID];
// bf16 activations
__device__ __nv_bfloat16 g_aibf[(size_t)MROWS*HID];
__device__ __nv_bfloat16 g_obf[(size_t)MROWS*HID];
__device__ __nv_bfloat16 g_mibf[(size_t)MROWS*HID];
__device__ __nv_bfloat16 g_hbf[(size_t)MROWS*DFF];
// transposed bf16 weights  Wt[N][K]
__device__ __nv_bfloat16 g_wqkt[(size_t)3*HID*HID];
__device__ __nv_bfloat16 g_wpt[(size_t)HID*HID];
__device__ __nv_bfloat16 g_wf1t[(size_t)DFF*HID];
__device__ __nv_bfloat16 g_wf2t[(size_t)HID*DFF];

// ------------------------- helpers ------------------------------------------
__device__ __forceinline__ float rna_tf32(float x) {
    float y;
    asm("cvt.rna.tf32.f32 %0, %1;" : "=f"(y) : "f"(x));
    return y;
}
__device__ __forceinline__ void cp16(void* smem_dst, const void* gsrc) {
    unsigned s = (unsigned)__cvta_generic_to_shared(smem_dst);
    asm volatile("cp.async.cg.shared.global [%0], [%1], 16;" :: "r"(s), "l"(gsrc));
}
__device__ __forceinline__ void mma_tf32(float4& d, const uint32_t* a, const uint32_t* b) {
    asm volatile(
        "mma.sync.aligned.m16n8k8.row.col.f32.tf32.tf32.f32 "
        "{%0,%1,%2,%3}, {%4,%5,%6,%7}, {%8,%9}, {%0,%1,%2,%3};"
        : "+f"(d.x), "+f"(d.y), "+f"(d.z), "+f"(d.w)
        : "r"(a[0]), "r"(a[1]), "r"(a[2]), "r"(a[3]), "r"(b[0]), "r"(b[1]));
}
__device__ __forceinline__ void mma_bf16(float4& d, const uint32_t* a, const uint32_t* b) {
    asm volatile(
        "mma.sync.aligned.m16n8k16.row.col.f32.bf16.bf16.f32 "
        "{%0,%1,%2,%3}, {%4,%5,%6,%7}, {%8,%9}, {%0,%1,%2,%3};"
        : "+f"(d.x), "+f"(d.y), "+f"(d.z), "+f"(d.w)
        : "r"(a[0]), "r"(a[1]), "r"(a[2]), "r"(a[3]), "r"(b[0]), "r"(b[1]));
}

// ------------------------- weight transpose fp32[K][N] -> bf16[N][K] --------
__global__ void wtrans_kernel(const float* __restrict__ in, __nv_bfloat16* __restrict__ out,
                              int K, int N) {
    __shared__ float tile[32][33];
    int k0 = blockIdx.y*32, n0 = blockIdx.x*32;
    int tx = threadIdx.x;
    for (int i = threadIdx.y; i < 32; i += 8)
        tile[i][tx] = in[(size_t)(k0 + i)*N + n0 + tx];
    __syncthreads();
    for (int i = threadIdx.y; i < 32; i += 8)
        out[(size_t)(n0 + i)*K + k0 + tx] = __float2bfloat16(tile[tx][i]);
}

// ------------------------- silu(c) ------------------------------------------
__global__ void silu_kernel(const float* __restrict__ c) {
    int i = blockIdx.x * 256 + threadIdx.x;
    if (i < BB*HID) {
        float s = c[i];
        g_silu_c[i] = s / (1.f + expf(-s));
    }
}

// ------------------------- adaLN --------------------------------------------
__global__ void adaln_kernel(const float* __restrict__ w_ada,
                             const float* __restrict__ b_ada) {
    int j = blockIdx.x * 256 + threadIdx.x;
    int b = blockIdx.y;
    if (j >= MOD6) return;
    float acc = b_ada[j];
    const float* cs = &g_silu_c[b*HID];
    for (int k = 0; k < HID; k++)
        acc += cs[k] * w_ada[(size_t)k*MOD6 + j];
    g_mod[b*MOD6 + j] = acc;
}

// --------------- fused (optional residual+gate) + LN + modulate -> bf16 -----
__global__ void modulate_kernel(const float* __restrict__ x,
                                const float* __restrict__ res,
                                int sh_seg, int sc_seg, int g_seg,
                                float* __restrict__ x1_out,
                                __nv_bfloat16* __restrict__ mi_out) {
    int r = blockIdx.x;
    int b = r / SEQ;
    const float* modb = &g_mod[b*MOD6];
    const float* xr = x + (size_t)r*HID;
    const float* rr = res ? res + (size_t)r*HID : nullptr;

    float s = 0.f, ss = 0.f;
    for (int ch = threadIdx.x; ch < HID; ch += 256) {
        float val = xr[ch];
        if (rr) val += modb[g_seg*HID + ch] * rr[ch];
        s += val; ss += val*val;
    }
    int lane = threadIdx.x & 31, wid = threadIdx.x >> 5;
    #pragma unroll
    for (int o = 16; o; o >>= 1) {
        s  += __shfl_xor_sync(0xffffffffu, s, o);
        ss += __shfl_xor_sync(0xffffffffu, ss, o);
    }
    __shared__ float sh1[8], sh2[8];
    if (lane == 0) { sh1[wid] = s; sh2[wid] = ss; }
    __syncthreads();
    if (threadIdx.x == 0) {
        float a = 0.f, bb = 0.f;
        #pragma unroll
        for (int i = 0; i < 8; i++) { a += sh1[i]; bb += sh2[i]; }
        sh1[0] = a; sh2[0] = bb;
    }
    __syncthreads();
    float mean = sh1[0] * (1.f/HID);
    float var  = sh2[0] * (1.f/HID) - mean*mean;
    float inv  = rsqrtf(var + 1e-6f);

    for (int ch = threadIdx.x; ch < HID; ch += 256) {
        float val = xr[ch];
        if (rr) val += modb[g_seg*HID + ch] * rr[ch];
        if (x1_out) x1_out[(size_t)r*HID + ch] = val;
        float y = (val - mean) * inv;
        mi_out[(size_t)r*HID + ch] =
            __float2bfloat16(y * (1.f + modb[sc_seg*HID + ch]) + modb[sh_seg*HID + ch]);
    }
}

// ------------------------- bf16 HMMA GEMM -----------------------------------
// C[M,N] = A[M,K](bf16) @ Bt[N,K](bf16)^T + bias
// BM=128 BN=128 BK=64, 128 threads, 4 warps (2m x 2n), warp tile 64x64.
// Smem tiles: [128 rows][36 words], word = bf16x2, K-pairs. 36 % 32 == 4 =>
// fragment footprint (8 rows x 4 word-cols) hits 32 distinct banks.
#define AW 36
#define TILE_W (128*AW)
#define GEMM_SMEM (4*TILE_W*4)   // 2 stages * (A+B) * 4 bytes

__global__ void __launch_bounds__(128)
gemm_bf(const __nv_bfloat16* __restrict__ A, const __nv_bfloat16* __restrict__ Bt,
        const float* __restrict__ bias, void* __restrict__ Cout,
        int M, int N, int K, int act, int outBf,
        const float* __restrict__ resid, int gate_seg) {
    extern __shared__ uint32_t smw[];   // word-addressed

    int tid = threadIdx.x, lane = tid & 31, wid = tid >> 5;
    int wm = wid >> 1, wn = wid & 1;
    int row0 = blockIdx.y * 128, col0 = blockIdx.x * 128;
    int lr = lane >> 2, lc = lane & 3;

    float4 acc[4][8];
    #pragma unroll
    for (int i = 0; i < 4; i++)
        #pragma unroll
        for (int j = 0; j < 8; j++) acc[i][j] = make_float4(0.f,0.f,0.f,0.f);

    int KT = K >> 6;

    auto load_stage = [&](int kt, int buf) {
        const __nv_bfloat16* gA = A  + (size_t)row0*K + kt*64;
        const __nv_bfloat16* gB = Bt + (size_t)col0*K + kt*64;
        uint32_t* as = smw + buf*2*TILE_W;
        uint32_t* bs = as + TILE_W;
        // 128 rows x 8 chunks(16B) each, 1024 chunks, 8 per thread
        #pragma unroll
        for (int i = 0; i < 8; i++) {
            int chunk = tid + i*128;
            int r = chunk >> 3, c = chunk & 7;     // c*8 bf16 = c*4 words
            cp16(&as[r*AW + c*4], gA + (size_t)r*K + c*8);
            cp16(&bs[r*AW + c*4], gB + (size_t)r*K + c*8);
        }
        asm volatile("cp.async.commit_group;");
    };

    load_stage(0, 0);

    for (int kt = 0; kt < KT; kt++) {
        int buf = kt & 1;
        asm volatile("cp.async.wait_group 0;");
        __syncthreads();
        if (kt + 1 < KT) load_stage(kt + 1, buf ^ 1);

        const uint32_t* as = smw + buf*2*TILE_W;
        const uint32_t* bs = as + TILE_W;
        #pragma unroll
        for (int k16 = 0; k16 < 4; k16++) {
            int kw = k16*8 + lc;     // word col
            uint32_t af[4][4];
            #pragma unroll
            for (int mi = 0; mi < 4; mi++) {
                int r = wm*64 + mi*16 + lr;
                af[mi][0] = as[r*AW + kw];
                af[mi][1] = as[(r+8)*AW + kw];
                af[mi][2] = as[r*AW + kw + 4];
                af[mi][3] = as[(r+8)*AW + kw + 4];
            }
            uint32_t bf[8][2];
            #pragma unroll
            for (int nj = 0; nj < 8; nj++) {
                int cc = wn*64 + nj*8 + lr;
                bf[nj][0] = bs[cc*AW + kw];
                bf[nj][1] = bs[cc*AW + kw + 4];
            }
            #pragma unroll
            for (int mi = 0; mi < 4; mi++)
                #pragma unroll
                for (int nj = 0; nj < 8; nj++)
                    mma_bf16(acc[mi][nj], af[mi], bf[nj]);
        }
        __syncthreads();
    }

    #pragma unroll
    for (int mi = 0; mi < 4; mi++) {
        #pragma unroll
        for (int nj = 0; nj < 8; nj++) {
            int r = row0 + wm*64 + mi*16 + lr;
            int c = col0 + wn*64 + nj*8 + 2*lc;
            float v[4] = {acc[mi][nj].x, acc[mi][nj].y, acc[mi][nj].z, acc[mi][nj].w};
            float b0 = bias[c], b1 = bias[c+1];
            v[0] += b0; v[1] += b1; v[2] += b0; v[3] += b1;
            if (act == 1) {
                #pragma unroll
                for (int q = 0; q < 4; q++) {
                    float u = v[q];
                    v[q] = 0.5f * u * (1.f + tanhf(0.7978845608028654f * (u + 0.044715f*u*u*u)));
                }
            }
            if (outBf) {
                __nv_bfloat16* Cb = (__nv_bfloat16*)Cout;
                __nv_bfloat162 p0, p1;
                p0.x = __float2bfloat16(v[0]); p0.y = __float2bfloat16(v[1]);
                p1.x = __float2bfloat16(v[2]); p1.y = __float2bfloat16(v[3]);
                *(__nv_bfloat162*)&Cb[(size_t)r*N + c]     = p0;
                *(__nv_bfloat162*)&Cb[(size_t)(r+8)*N + c] = p1;
            } else {
                float* Cf = (float*)Cout;
                if (resid) {
                    int b = r / SEQ;
                    float g0 = g_mod[b*MOD6 + gate_seg*HID + c];
                    float g1 = g_mod[b*MOD6 + gate_seg*HID + c + 1];
                    v[0] = resid[(size_t)r*N + c]     + g0*v[0];
                    v[1] = resid[(size_t)r*N + c + 1] + g1*v[1];
                    v[2] = resid[(size_t)(r+8)*N + c]     + g0*v[2];
                    v[3] = resid[(size_t)(r+8)*N + c + 1] + g1*v[3];
                }
                *(float2*)&Cf[(size_t)r*N + c]     = make_float2(v[0], v[1]);
                *(float2*)&Cf[(size_t)(r+8)*N + c] = make_float2(v[2], v[3]);
            }
        }
    }
}

// ------------------------- qk-norm + reshape to [B,NH,N,HD] -----------------
__global__ void qknorm_kernel(const float* __restrict__ qn_w, const float* __restrict__ qn_b,
                              const float* __restrict__ kn_w, const float* __restrict__ kn_b) {
    int id = blockIdx.x * 8 + (threadIdx.x >> 5);
    if (id >= MROWS*48) return;
    int lane = threadIdx.x & 31;
    int r = id / 48;
    int rem = id % 48;
    int w = rem / 16;
    int h = rem % 16;

    const float* src = &g_qkv[(size_t)r*3456 + w*1152 + h*72];
    float v0 = src[lane];
    float v1 = src[lane + 32];
    float v2 = (lane < 8) ? src[lane + 64] : 0.f;

    int b = r / SEQ, n = r % SEQ;
    float* dst = (w == 0 ? g_q : (w == 1 ? g_k : g_v))
                 + (((size_t)(b*NHEAD + h)*SEQ + n)*HDIM);

    if (w == 2) {
        dst[lane] = rna_tf32(v0); dst[lane+32] = rna_tf32(v1);
        if (lane < 8) dst[lane+64] = rna_tf32(v2);
        return;
    }
    float s = v0 + v1 + v2;
    float ss = v0*v0 + v1*v1 + v2*v2;
    #pragma unroll
    for (int o = 16; o; o >>= 1) {
        s  += __shfl_xor_sync(0xffffffffu, s, o);
        ss += __shfl_xor_sync(0xffffffffu, ss, o);
    }
    float mean = s * (1.f/72.f);
    float var  = ss * (1.f/72.f) - mean*mean;
    float inv  = rsqrtf(var + 1e-5f);
    const float* ww = (w == 0) ? qn_w : kn_w;
    const float* wb = (w == 0) ? qn_b : kn_b;
    dst[lane]      = rna_tf32((v0 - mean)*inv*ww[lane]      + wb[lane]);
    dst[lane + 32] = rna_tf32((v1 - mean)*inv*ww[lane + 32] + wb[lane + 32]);
    if (lane < 8)
        dst[lane + 64] = rna_tf32((v2 - mean)*inv*ww[lane + 64] + wb[lane + 64]);
}

// ------------------------- tensor-core flash attention (tf32) ---------------
#define QS_STR 76
#define KT_STR 72
#define VS_STR 72
#define PS_STR 68
#define ATTN_SMEM ((128*QS_STR + 72*KT_STR + 64*VS_STR + 128*PS_STR)*4)

__global__ void __launch_bounds__(256) attn_tc() {
    extern __shared__ float sm[];
    float* Qs = sm;
    float* Kt = Qs + 128*QS_STR;
    float* Vs = Kt + 72*KT_STR;
    float* Ps = Vs + 64*VS_STR;

    int b = blockIdx.z, h = blockIdx.y, q0 = blockIdx.x*128;
    int tid = threadIdx.x, lane = tid & 31, wid = tid >> 5;
    int lr = lane >> 2, lc = lane & 3;
    int wr = wid * 16;
    size_t base = (size_t)(b*NHEAD + h) * SEQ * HDIM;
    const float scale = 0.11785113019775793f;

    for (int i = tid; i < 128*18; i += 256) {
        int r = i / 18, d4 = (i % 18) * 4;
        *(float4*)&Qs[r*QS_STR + d4] = *(const float4*)&g_q[base + (size_t)(q0 + r)*HDIM + d4];
    }

    float4 o[9];
    #pragma unroll
    for (int i = 0; i < 9; i++) o[i] = make_float4(0.f,0.f,0.f,0.f);
    float m_lo = -INFINITY, m_hi = -INFINITY, l_lo = 0.f, l_hi = 0.f;

    for (int t = 0; t < 16; t++) {
        __syncthreads();
        const float* kg = &g_k[base + (size_t)(t*64)*HDIM];
        for (int i = tid; i < 64*18; i += 256) {
            int j = i & 63, d4 = i >> 6;
            float4 kv = *(const float4*)&kg[(size_t)j*HDIM + d4*4];
            Kt[(4*d4+0)*KT_STR + j] = kv.x;
            Kt[(4*d4+1)*KT_STR + j] = kv.y;
            Kt[(4*d4+2)*KT_STR + j] = kv.z;
            Kt[(4*d4+3)*KT_STR + j] = kv.w;
        }
        const float* vg = &g_v[base + (size_t)(t*64)*HDIM];
        for (int i = tid; i < 64*18; i += 256) {
            int j = i / 18, d4 = (i % 18) * 4;
            *(float4*)&Vs[j*VS_STR + d4] = *(const float4*)&vg[(size_t)j*HDIM + d4];
        }
        __syncthreads();

        float4 sc[8];
        #pragma unroll
        for (int i = 0; i < 8; i++) sc[i] = make_float4(0.f,0.f,0.f,0.f);
        #pragma unroll
        for (int k8 = 0; k8 < 9; k8++) {
            int c = k8*8 + lc;
            uint32_t af[4];
            af[0] = __float_as_uint(Qs[(wr+lr)*QS_STR + c]);
            af[1] = __float_as_uint(Qs[(wr+8+lr)*QS_STR + c]);
            af[2] = __float_as_uint(Qs[(wr+lr)*QS_STR + c + 4]);
            af[3] = __float_as_uint(Qs[(wr+8+lr)*QS_STR + c + 4]);
            #pragma unroll
            for (int nj = 0; nj < 8; nj++) {
                uint32_t bf[2];
                bf[0] = __float_as_uint(Kt[c*KT_STR + nj*8 + lr]);
                bf[1] = __float_as_uint(Kt[(c+4)*KT_STR + nj*8 + lr]);
                mma_tf32(sc[nj], af, bf);
            }
        }

        float tmax_lo = -INFINITY, tmax_hi = -INFINITY;
        #pragma unroll
        for (int nj = 0; nj < 8; nj++) {
            sc[nj].x *= scale; sc[nj].y *= scale; sc[nj].z *= scale; sc[nj].w *= scale;
            tmax_lo = fmaxf(tmax_lo, fmaxf(sc[nj].x, sc[nj].y));
            tmax_hi = fmaxf(tmax_hi, fmaxf(sc[nj].z, sc[nj].w));
        }
        tmax_lo = fmaxf(tmax_lo, __shfl_xor_sync(0xffffffffu, tmax_lo, 1));
        tmax_lo = fmaxf(tmax_lo, __shfl_xor_sync(0xffffffffu, tmax_lo, 2));
        tmax_hi = fmaxf(tmax_hi, __shfl_xor_sync(0xffffffffu, tmax_hi, 1));
        tmax_hi = fmaxf(tmax_hi, __shfl_xor_sync(0xffffffffu, tmax_hi, 2));

        float mn_lo = fmaxf(m_lo, tmax_lo);
        float mn_hi = fmaxf(m_hi, tmax_hi);
        float corr_lo = __expf(m_lo - mn_lo);
        float corr_hi = __expf(m_hi - mn_hi);
        l_lo *= corr_lo; l_hi *= corr_hi;
        #pragma unroll
        for (int i = 0; i < 9; i++) {
            o[i].x *= corr_lo; o[i].y *= corr_lo;
            o[i].z *= corr_hi; o[i].w *= corr_hi;
        }
        float sum_lo = 0.f, sum_hi = 0.f;
        #pragma unroll
        for (int nj = 0; nj < 8; nj++) {
            float px = __expf(sc[nj].x - mn_lo);
            float py = __expf(sc[nj].y - mn_lo);
            float pz = __expf(sc[nj].z - mn_hi);
            float pw = __expf(sc[nj].w - mn_hi);
            sum_lo += px + py; sum_hi += pz + pw;
            *(float2*)&Ps[(wr+lr)*PS_STR + nj*8 + 2*lc]   = make_float2(px, py);
            *(float2*)&Ps[(wr+8+lr)*PS_STR + nj*8 + 2*lc] = make_float2(pz, pw);
        }
        sum_lo += __shfl_xor_sync(0xffffffffu, sum_lo, 1);
        sum_lo += __shfl_xor_sync(0xffffffffu, sum_lo, 2);
        sum_hi += __shfl_xor_sync(0xffffffffu, sum_hi, 1);
        sum_hi += __shfl_xor_sync(0xffffffffu, sum_hi, 2);
        l_lo += sum_lo; l_hi += sum_hi;
        m_lo = mn_lo; m_hi = mn_hi;
        __syncwarp();

        #pragma unroll
        for (int k8 = 0; k8 < 8; k8++) {
            int c = k8*8 + lc;
            uint32_t af[4];
            af[0] = __float_as_uint(Ps[(wr+lr)*PS_STR + c]);
            af[1] = __float_as_uint(Ps[(wr+8+lr)*PS_STR + c]);
            af[2] = __float_as_uint(Ps[(wr+lr)*PS_STR + c + 4]);
            af[3] = __float_as_uint(Ps[(wr+8+lr)*PS_STR + c + 4]);
            #pragma unroll
            for (int n9 = 0; n9 < 9; n9++) {
                uint32_t bf[2];
                bf[0] = __float_as_uint(Vs[c*VS_STR + n9*8 + lr]);
                bf[1] = __float_as_uint(Vs[(c+4)*VS_STR + n9*8 + lr]);
                mma_tf32(o[n9], af, bf);
            }
        }
    }

    // epilogue -> bf16 g_obf (row-major [B*SEQ][HID], head slice)
    float inv_lo = 1.f / l_lo, inv_hi = 1.f / l_hi;
    int r = b*SEQ + q0 + wr + lr;
    #pragma unroll
    for (int n9 = 0; n9 < 9; n9++) {
        int c = h*HDIM + n9*8 + 2*lc;
        __nv_bfloat162 p0, p1;
        p0.x = __float2bfloat16(o[n9].x*inv_lo);
        p0.y = __float2bfloat16(o[n9].y*inv_lo);
        p1.x = __float2bfloat16(o[n9].z*inv_hi);
        p1.y = __float2bfloat16(o[n9].w*inv_hi);
        *(__nv_bfloat162*)&g_obf[(size_t)r*HID + c]     = p0;
        *(__nv_bfloat162*)&g_obf[(size_t)(r+8)*HID + c] = p1;
    }
}

// ---------------------------------------------------------------------------
extern "C" void kernel_launch(void* const* d_in, const int* in_sizes, int n_in,
                              void* d_out, int out_size) {
    const float* x      = (const float*)d_in[0];
    const float* c      = (const float*)d_in[1];
    const float* w_ada  = (const float*)d_in[2];
    const float* b_ada  = (const float*)d_in[3];
    const float* w_qkv  = (const float*)d_in[4];
    const float* b_qkv  = (const float*)d_in[5];
    const float* qn_w   = (const float*)d_in[6];
    const float* qn_b   = (const float*)d_in[7];
    const float* kn_w   = (const float*)d_in[8];
    const float* kn_b   = (const float*)d_in[9];
    const float* w_proj = (const float*)d_in[10];
    const float* b_proj = (const float*)d_in[11];
    const float* w_fc1  = (const float*)d_in[12];
    const float* b_fc1  = (const float*)d_in[13];
    const float* w_fc2  = (const float*)d_in[14];
    const float* b_fc2  = (const float*)d_in[15];
    float* out = (float*)d_out;

    float *p_qkv, *p_proj, *p_x1;
    __nv_bfloat16 *p_aibf, *p_obf, *p_mibf, *p_hbf;
    __nv_bfloat16 *p_wqkt, *p_wpt, *p_wf1t, *p_wf2t;
    cudaGetSymbolAddress((void**)&p_qkv,  g_qkv);
    cudaGetSymbolAddress((void**)&p_proj, g_proj);
    cudaGetSymbolAddress((void**)&p_x1,   g_x1);
    cudaGetSymbolAddress((void**)&p_aibf, g_aibf);
    cudaGetSymbolAddress((void**)&p_obf,  g_obf);
    cudaGetSymbolAddress((void**)&p_mibf, g_mibf);
    cudaGetSymbolAddress((void**)&p_hbf,  g_hbf);
    cudaGetSymbolAddress((void**)&p_wqkt, g_wqkt);
    cudaGetSymbolAddress((void**)&p_wpt,  g_wpt);
    cudaGetSymbolAddress((void**)&p_wf1t, g_wf1t);
    cudaGetSymbolAddress((void**)&p_wf2t, g_wf2t);

    static int attr_set = 0;
    if (!attr_set) {
        cudaFuncSetAttribute(gemm_bf, cudaFuncAttributeMaxDynamicSharedMemorySize, GEMM_SMEM);
        cudaFuncSetAttribute(attn_tc, cudaFuncAttributeMaxDynamicSharedMemorySize, ATTN_SMEM);
        attr_set = 1;
    }

    // weight transposes (fp32 [K][N] -> bf16 [N][K])
    wtrans_kernel<<<dim3(3*HID/32, HID/32), dim3(32,8)>>>(w_qkv, p_wqkt, HID, 3*HID);
    wtrans_kernel<<<dim3(HID/32, HID/32), dim3(32,8)>>>(w_proj, p_wpt, HID, HID);
    wtrans_kernel<<<dim3(DFF/32, HID/32), dim3(32,8)>>>(w_fc1, p_wf1t, HID, DFF);
    wtrans_kernel<<<dim3(HID/32, DFF/32), dim3(32,8)>>>(w_fc2, p_wf2t, DFF, HID);

    silu_kernel<<<(BB*HID + 255)/256, 256>>>(c);
    adaln_kernel<<<dim3(MOD6/256, BB), 256>>>(w_ada, b_ada);
    modulate_kernel<<<MROWS, 256>>>(x, nullptr, 0, 1, -1, nullptr, p_aibf);
    // qkv = ai @ w_qkv + b  (fp32 out for qknorm)
    gemm_bf<<<dim3(3*HID/128, MROWS/128), 128, GEMM_SMEM>>>(p_aibf, p_wqkt, b_qkv, p_qkv,
                                                            MROWS, 3*HID, HID, 0, 0, nullptr, 0);
    qknorm_kernel<<<MROWS*48/8, 256>>>(qn_w, qn_b, kn_w, kn_b);
    attn_tc<<<dim3(SEQ/128, NHEAD, BB), 256, ATTN_SMEM>>>();
    // proj (fp32 out)
    gemm_bf<<<dim3(HID/128, MROWS/128), 128, GEMM_SMEM>>>(p_obf, p_wpt, b_proj, p_proj,
                                                          MROWS, HID, HID, 0, 0, nullptr, 0);
    modulate_kernel<<<MROWS, 256>>>(x, p_proj, 3, 4, 2, p_x1, p_mibf);
    // fc1 + gelu (bf16 out)
    gemm_bf<<<dim3(DFF/128, MROWS/128), 128, GEMM_SMEM>>>(p_mibf, p_wf1t, b_fc1, p_hbf,
                                                          MROWS, DFF, HID, 1, 1, nullptr, 0);
    // fc2 with fused  out = x1 + g_mlp * (h @ w_fc2 + b)   (fp32 out)
    gemm_bf<<<dim3(HID/128, MROWS/128), 128, GEMM_SMEM>>>(p_hbf, p_wf2t, b_fc2, out,
                                                          MROWS, HID, DFF, 0, 0, p_x1, 5);
}

// round 6
// speedup vs baseline: 6.5601x; 1.1779x over previous
#include <cuda_runtime.h>
#include <cuda_fp16.h>
#include <math.h>
#include <stdint.h>

#define BB 8
#define SEQ 1024
#define HID 1152
#define NHEAD 16
#define HDIM 72
#define DFF 4608
#define MROWS (BB*SEQ)      // 8192
#define MOD6 (6*HID)        // 6912

// ------------------------- scratch (__device__ globals, no allocs) ----------
__device__ float g_silu_c[BB*HID];
__device__ float g_mod[BB*MOD6];
__device__ float g_proj[MROWS*HID];
__device__ float g_x1[MROWS*HID];
// fp16 activations
__device__ __half g_aih[(size_t)MROWS*HID];
__device__ __half g_qkvh[(size_t)MROWS*3*HID];
__device__ __half g_qh[MROWS*HID];
__device__ __half g_kh[MROWS*HID];
__device__ __half g_vh[MROWS*HID];
__device__ __half g_oh[MROWS*HID];
__device__ __half g_mih[(size_t)MROWS*HID];
__device__ __half g_hh[(size_t)MROWS*DFF];
// transposed fp16 weights  Wt[N][K]
__device__ __half g_wqkt[(size_t)3*HID*HID];
__device__ __half g_wpt[(size_t)HID*HID];
__device__ __half g_wf1t[(size_t)DFF*HID];
__device__ __half g_wf2t[(size_t)HID*DFF];

// ------------------------- helpers ------------------------------------------
__device__ __forceinline__ void cp16(void* smem_dst, const void* gsrc) {
    unsigned s = (unsigned)__cvta_generic_to_shared(smem_dst);
    asm volatile("cp.async.cg.shared.global [%0], [%1], 16;" :: "r"(s), "l"(gsrc));
}
__device__ __forceinline__ void mma_f16(float4& d, const uint32_t* a, const uint32_t* b) {
    asm volatile(
        "mma.sync.aligned.m16n8k16.row.col.f32.f16.f16.f32 "
        "{%0,%1,%2,%3}, {%4,%5,%6,%7}, {%8,%9}, {%0,%1,%2,%3};"
        : "+f"(d.x), "+f"(d.y), "+f"(d.z), "+f"(d.w)
        : "r"(a[0]), "r"(a[1]), "r"(a[2]), "r"(a[3]), "r"(b[0]), "r"(b[1]));
}
__device__ __forceinline__ void mma_f16_k8(float4& d, uint32_t a0, uint32_t a1, uint32_t b0) {
    asm volatile(
        "mma.sync.aligned.m16n8k8.row.col.f32.f16.f16.f32 "
        "{%0,%1,%2,%3}, {%4,%5}, {%6}, {%0,%1,%2,%3};"
        : "+f"(d.x), "+f"(d.y), "+f"(d.z), "+f"(d.w)
        : "r"(a0), "r"(a1), "r"(b0));
}

// ------------------------- weight transpose fp32[K][N] -> fp16[N][K] --------
__global__ void wtrans_kernel(const float* __restrict__ in, __half* __restrict__ out,
                              int K, int N) {
    __shared__ float tile[32][33];
    int k0 = blockIdx.y*32, n0 = blockIdx.x*32;
    int tx = threadIdx.x;
    for (int i = threadIdx.y; i < 32; i += 8)
        tile[i][tx] = in[(size_t)(k0 + i)*N + n0 + tx];
    __syncthreads();
    for (int i = threadIdx.y; i < 32; i += 8)
        out[(size_t)(n0 + i)*K + k0 + tx] = __float2half(tile[tx][i]);
}

// ------------------------- silu(c) ------------------------------------------
__global__ void silu_kernel(const float* __restrict__ c) {
    int i = blockIdx.x * 256 + threadIdx.x;
    if (i < BB*HID) {
        float s = c[i];
        g_silu_c[i] = s / (1.f + expf(-s));
    }
}

// ------------------------- adaLN --------------------------------------------
__global__ void adaln_kernel(const float* __restrict__ w_ada,
                             const float* __restrict__ b_ada) {
    int j = blockIdx.x * 256 + threadIdx.x;
    int b = blockIdx.y;
    if (j >= MOD6) return;
    float acc = b_ada[j];
    const float* cs = &g_silu_c[b*HID];
    for (int k = 0; k < HID; k++)
        acc += cs[k] * w_ada[(size_t)k*MOD6 + j];
    g_mod[b*MOD6 + j] = acc;
}

// --------------- fused (optional residual+gate) + LN + modulate -> fp16 -----
__global__ void modulate_kernel(const float* __restrict__ x,
                                const float* __restrict__ res,
                                int sh_seg, int sc_seg, int g_seg,
                                float* __restrict__ x1_out,
                                __half* __restrict__ mi_out) {
    int r = blockIdx.x;
    int b = r / SEQ;
    const float* modb = &g_mod[b*MOD6];
    const float* xr = x + (size_t)r*HID;
    const float* rr = res ? res + (size_t)r*HID : nullptr;

    float s = 0.f, ss = 0.f;
    for (int ch = threadIdx.x; ch < HID; ch += 256) {
        float val = xr[ch];
        if (rr) val += modb[g_seg*HID + ch] * rr[ch];
        s += val; ss += val*val;
    }
    int lane = threadIdx.x & 31, wid = threadIdx.x >> 5;
    #pragma unroll
    for (int o = 16; o; o >>= 1) {
        s  += __shfl_xor_sync(0xffffffffu, s, o);
        ss += __shfl_xor_sync(0xffffffffu, ss, o);
    }
    __shared__ float sh1[8], sh2[8];
    if (lane == 0) { sh1[wid] = s; sh2[wid] = ss; }
    __syncthreads();
    if (threadIdx.x == 0) {
        float a = 0.f, bb = 0.f;
        #pragma unroll
        for (int i = 0; i < 8; i++) { a += sh1[i]; bb += sh2[i]; }
        sh1[0] = a; sh2[0] = bb;
    }
    __syncthreads();
    float mean = sh1[0] * (1.f/HID);
    float var  = sh2[0] * (1.f/HID) - mean*mean;
    float inv  = rsqrtf(var + 1e-6f);

    for (int ch = threadIdx.x; ch < HID; ch += 256) {
        float val = xr[ch];
        if (rr) val += modb[g_seg*HID + ch] * rr[ch];
        if (x1_out) x1_out[(size_t)r*HID + ch] = val;
        float y = (val - mean) * inv;
        mi_out[(size_t)r*HID + ch] =
            __float2half(y * (1.f + modb[sc_seg*HID + ch]) + modb[sh_seg*HID + ch]);
    }
}

// ------------------------- fp16 HMMA GEMM -----------------------------------
// C[M,N] = A[M,K](f16) @ Bt[N,K](f16)^T + bias
// BM=128 BN=128 BK=64, 128 threads, 4 warps (2m x 2n), warp tile 64x64.
#define AW 36
#define TILE_W (128*AW)
#define GEMM_SMEM (4*TILE_W*4)

__global__ void __launch_bounds__(128)
gemm_hf(const __half* __restrict__ A, const __half* __restrict__ Bt,
        const float* __restrict__ bias, void* __restrict__ Cout,
        int M, int N, int K, int act, int outH,
        const float* __restrict__ resid, int gate_seg) {
    extern __shared__ uint32_t smw[];

    int tid = threadIdx.x, lane = tid & 31, wid = tid >> 5;
    int wm = wid >> 1, wn = wid & 1;
    int row0 = blockIdx.y * 128, col0 = blockIdx.x * 128;
    int lr = lane >> 2, lc = lane & 3;

    float4 acc[4][8];
    #pragma unroll
    for (int i = 0; i < 4; i++)
        #pragma unroll
        for (int j = 0; j < 8; j++) acc[i][j] = make_float4(0.f,0.f,0.f,0.f);

    int KT = K >> 6;

    auto load_stage = [&](int kt, int buf) {
        const __half* gA = A  + (size_t)row0*K + kt*64;
        const __half* gB = Bt + (size_t)col0*K + kt*64;
        uint32_t* as = smw + buf*2*TILE_W;
        uint32_t* bs = as + TILE_W;
        #pragma unroll
        for (int i = 0; i < 8; i++) {
            int chunk = tid + i*128;
            int r = chunk >> 3, c = chunk & 7;
            cp16(&as[r*AW + c*4], gA + (size_t)r*K + c*8);
            cp16(&bs[r*AW + c*4], gB + (size_t)r*K + c*8);
        }
        asm volatile("cp.async.commit_group;");
    };

    load_stage(0, 0);

    for (int kt = 0; kt < KT; kt++) {
        int buf = kt & 1;
        asm volatile("cp.async.wait_group 0;");
        __syncthreads();
        if (kt + 1 < KT) load_stage(kt + 1, buf ^ 1);

        const uint32_t* as = smw + buf*2*TILE_W;
        const uint32_t* bs = as + TILE_W;
        #pragma unroll
        for (int k16 = 0; k16 < 4; k16++) {
            int kw = k16*8 + lc;
            uint32_t af[4][4];
            #pragma unroll
            for (int mi = 0; mi < 4; mi++) {
                int r = wm*64 + mi*16 + lr;
                af[mi][0] = as[r*AW + kw];
                af[mi][1] = as[(r+8)*AW + kw];
                af[mi][2] = as[r*AW + kw + 4];
                af[mi][3] = as[(r+8)*AW + kw + 4];
            }
            uint32_t bf[8][2];
            #pragma unroll
            for (int nj = 0; nj < 8; nj++) {
                int cc = wn*64 + nj*8 + lr;
                bf[nj][0] = bs[cc*AW + kw];
                bf[nj][1] = bs[cc*AW + kw + 4];
            }
            #pragma unroll
            for (int mi = 0; mi < 4; mi++)
                #pragma unroll
                for (int nj = 0; nj < 8; nj++)
                    mma_f16(acc[mi][nj], af[mi], bf[nj]);
        }
        __syncthreads();
    }

    #pragma unroll
    for (int mi = 0; mi < 4; mi++) {
        #pragma unroll
        for (int nj = 0; nj < 8; nj++) {
            int r = row0 + wm*64 + mi*16 + lr;
            int c = col0 + wn*64 + nj*8 + 2*lc;
            float v[4] = {acc[mi][nj].x, acc[mi][nj].y, acc[mi][nj].z, acc[mi][nj].w};
            float b0 = bias[c], b1 = bias[c+1];
            v[0] += b0; v[1] += b1; v[2] += b0; v[3] += b1;
            if (act == 1) {
                #pragma unroll
                for (int q = 0; q < 4; q++) {
                    float u = v[q];
                    v[q] = 0.5f * u * (1.f + tanhf(0.7978845608028654f * (u + 0.044715f*u*u*u)));
                }
            }
            if (outH) {
                __half* Cb = (__half*)Cout;
                __half2 p0 = __floats2half2_rn(v[0], v[1]);
                __half2 p1 = __floats2half2_rn(v[2], v[3]);
                *(__half2*)&Cb[(size_t)r*N + c]     = p0;
                *(__half2*)&Cb[(size_t)(r+8)*N + c] = p1;
            } else {
                float* Cf = (float*)Cout;
                if (resid) {
                    int b = r / SEQ;
                    float g0 = g_mod[b*MOD6 + gate_seg*HID + c];
                    float g1 = g_mod[b*MOD6 + gate_seg*HID + c + 1];
                    v[0] = resid[(size_t)r*N + c]     + g0*v[0];
                    v[1] = resid[(size_t)r*N + c + 1] + g1*v[1];
                    v[2] = resid[(size_t)(r+8)*N + c]     + g0*v[2];
                    v[3] = resid[(size_t)(r+8)*N + c + 1] + g1*v[3];
                }
                *(float2*)&Cf[(size_t)r*N + c]     = make_float2(v[0], v[1]);
                *(float2*)&Cf[(size_t)(r+8)*N + c] = make_float2(v[2], v[3]);
            }
        }
    }
}

// ------------------------- qk-norm + reshape to [B,NH,N,HD] (fp16) ----------
__global__ void qknorm_kernel(const float* __restrict__ qn_w, const float* __restrict__ qn_b,
                              const float* __restrict__ kn_w, const float* __restrict__ kn_b) {
    int id = blockIdx.x * 8 + (threadIdx.x >> 5);
    if (id >= MROWS*48) return;
    int lane = threadIdx.x & 31;
    int r = id / 48;
    int rem = id % 48;
    int w = rem / 16;
    int h = rem % 16;

    const __half* src = &g_qkvh[(size_t)r*3456 + w*1152 + h*72];
    float v0 = __half2float(src[lane]);
    float v1 = __half2float(src[lane + 32]);
    float v2 = (lane < 8) ? __half2float(src[lane + 64]) : 0.f;

    int b = r / SEQ, n = r % SEQ;
    __half* dst = (w == 0 ? g_qh : (w == 1 ? g_kh : g_vh))
                 + (((size_t)(b*NHEAD + h)*SEQ + n)*HDIM);

    if (w == 2) {
        dst[lane] = __float2half(v0); dst[lane+32] = __float2half(v1);
        if (lane < 8) dst[lane+64] = __float2half(v2);
        return;
    }
    float s = v0 + v1 + v2;
    float ss = v0*v0 + v1*v1 + v2*v2;
    #pragma unroll
    for (int o = 16; o; o >>= 1) {
        s  += __shfl_xor_sync(0xffffffffu, s, o);
        ss += __shfl_xor_sync(0xffffffffu, ss, o);
    }
    float mean = s * (1.f/72.f);
    float var  = ss * (1.f/72.f) - mean*mean;
    float inv  = rsqrtf(var + 1e-5f);
    const float* ww = (w == 0) ? qn_w : kn_w;
    const float* wb = (w == 0) ? qn_b : kn_b;
    dst[lane]      = __float2half((v0 - mean)*inv*ww[lane]      + wb[lane]);
    dst[lane + 32] = __float2half((v1 - mean)*inv*ww[lane + 32] + wb[lane + 32]);
    if (lane < 8)
        dst[lane + 64] = __float2half((v2 - mean)*inv*ww[lane + 64] + wb[lane + 64]);
}

// ------------------------- fp16 tensor-core flash attention -----------------
// 256 threads = 8 warps, warp = 16 q rows; key tile 64.
// Qs[128][36w], Ks[64][36w] (K natural layout = B operand), Vt[72][36w] (V^T),
// Ps[128][36w] (P as half2 k-pairs). All strides 36 words (conflict-free).
#define AT_QW (128*36)
#define AT_KW (64*36)
#define AT_VW (72*36)
#define AT_PW (128*36)
#define ATTN_SMEM ((AT_QW + AT_KW + AT_VW + AT_PW)*4)

__global__ void __launch_bounds__(256) attn_h() {
    extern __shared__ uint32_t smw[];
    uint32_t* Qs = smw;
    uint32_t* Ks = Qs + AT_QW;
    uint32_t* Vt = Ks + AT_KW;          // word view of __half Vt[72][72]
    uint32_t* Ps = Vt + AT_VW;
    __half* Vth = (__half*)Vt;

    int b = blockIdx.z, h = blockIdx.y, q0 = blockIdx.x*128;
    int tid = threadIdx.x, lane = tid & 31, wid = tid >> 5;
    int lr = lane >> 2, lc = lane & 3;
    int wr = wid * 16;
    size_t base = (size_t)(b*NHEAD + h) * SEQ * HDIM;
    const float scale = 0.11785113019775793f;  // 72^-0.5

    // load Q tile (rows contiguous: 36 words = 9 uint4 per row)
    {
        const uint4* qg = (const uint4*)&g_qh[base + (size_t)q0*HDIM];
        for (int i = tid; i < 128*9; i += 256) {
            int r = i / 9, c = i % 9;
            *(uint4*)&Qs[r*36 + c*4] = qg[i];
        }
    }

    float4 o[9];
    #pragma unroll
    for (int i = 0; i < 9; i++) o[i] = make_float4(0.f,0.f,0.f,0.f);
    float m_lo = -INFINITY, m_hi = -INFINITY, l_lo = 0.f, l_hi = 0.f;

    for (int t = 0; t < 16; t++) {
        __syncthreads();
        // K tile: natural [key][d] layout
        {
            const uint4* kg = (const uint4*)&g_kh[base + (size_t)(t*64)*HDIM];
            for (int i = tid; i < 64*9; i += 256) {
                int r = i / 9, c = i % 9;
                *(uint4*)&Ks[r*36 + c*4] = kg[i];
            }
        }
        // V tile transposed: Vth[d][key]
        {
            const uint32_t* vg = (const uint32_t*)&g_vh[base + (size_t)(t*64)*HDIM];
            for (int i = tid; i < 64*36; i += 256) {
                int key = i / 36, dw = i % 36;
                uint32_t wv = vg[i];
                __half2 hv = *(__half2*)&wv;
                Vth[(2*dw)*72 + key]     = hv.x;
                Vth[(2*dw+1)*72 + key]   = hv.y;
            }
        }
        __syncthreads();

        // S = Q K^T : 4 x k16 + 1 x k8 tail (d = 72)
        float4 sc[8];
        #pragma unroll
        for (int i = 0; i < 8; i++) sc[i] = make_float4(0.f,0.f,0.f,0.f);
        #pragma unroll
        for (int k16 = 0; k16 < 4; k16++) {
            int kw = k16*8 + lc;
            uint32_t af[4];
            af[0] = Qs[(wr+lr)*36 + kw];
            af[1] = Qs[(wr+8+lr)*36 + kw];
            af[2] = Qs[(wr+lr)*36 + kw + 4];
            af[3] = Qs[(wr+8+lr)*36 + kw + 4];
            #pragma unroll
            for (int nj = 0; nj < 8; nj++) {
                int cc = nj*8 + lr;
                uint32_t bf[2] = {Ks[cc*36 + kw], Ks[cc*36 + kw + 4]};
                mma_f16(sc[nj], af, bf);
            }
        }
        {   // k8 tail: d = 64..71 -> words 32..35
            int kw = 32 + lc;
            uint32_t a0 = Qs[(wr+lr)*36 + kw];
            uint32_t a1 = Qs[(wr+8+lr)*36 + kw];
            #pragma unroll
            for (int nj = 0; nj < 8; nj++) {
                int cc = nj*8 + lr;
                mma_f16_k8(sc[nj], a0, a1, Ks[cc*36 + kw]);
            }
        }

        // online softmax (rows wr+lr and wr+8+lr)
        float tmax_lo = -INFINITY, tmax_hi = -INFINITY;
        #pragma unroll
        for (int nj = 0; nj < 8; nj++) {
            sc[nj].x *= scale; sc[nj].y *= scale; sc[nj].z *= scale; sc[nj].w *= scale;
            tmax_lo = fmaxf(tmax_lo, fmaxf(sc[nj].x, sc[nj].y));
            tmax_hi = fmaxf(tmax_hi, fmaxf(sc[nj].z, sc[nj].w));
        }
        tmax_lo = fmaxf(tmax_lo, __shfl_xor_sync(0xffffffffu, tmax_lo, 1));
        tmax_lo = fmaxf(tmax_lo, __shfl_xor_sync(0xffffffffu, tmax_lo, 2));
        tmax_hi = fmaxf(tmax_hi, __shfl_xor_sync(0xffffffffu, tmax_hi, 1));
        tmax_hi = fmaxf(tmax_hi, __shfl_xor_sync(0xffffffffu, tmax_hi, 2));

        float mn_lo = fmaxf(m_lo, tmax_lo);
        float mn_hi = fmaxf(m_hi, tmax_hi);
        float corr_lo = __expf(m_lo - mn_lo);
        float corr_hi = __expf(m_hi - mn_hi);
        l_lo *= corr_lo; l_hi *= corr_hi;
        #pragma unroll
        for (int i = 0; i < 9; i++) {
            o[i].x *= corr_lo; o[i].y *= corr_lo;
            o[i].z *= corr_hi; o[i].w *= corr_hi;
        }
        float sum_lo = 0.f, sum_hi = 0.f;
        #pragma unroll
        for (int nj = 0; nj < 8; nj++) {
            float px = __expf(sc[nj].x - mn_lo);
            float py = __expf(sc[nj].y - mn_lo);
            float pz = __expf(sc[nj].z - mn_hi);
            float pw = __expf(sc[nj].w - mn_hi);
            sum_lo += px + py; sum_hi += pz + pw;
            __half2 plo = __floats2half2_rn(px, py);
            __half2 phi = __floats2half2_rn(pz, pw);
            Ps[(wr+lr)*36 + nj*4 + lc]   = *(uint32_t*)&plo;
            Ps[(wr+8+lr)*36 + nj*4 + lc] = *(uint32_t*)&phi;
        }
        sum_lo += __shfl_xor_sync(0xffffffffu, sum_lo, 1);
        sum_lo += __shfl_xor_sync(0xffffffffu, sum_lo, 2);
        sum_hi += __shfl_xor_sync(0xffffffffu, sum_hi, 1);
        sum_hi += __shfl_xor_sync(0xffffffffu, sum_hi, 2);
        l_lo += sum_lo; l_hi += sum_hi;
        m_lo = mn_lo; m_hi = mn_hi;
        __syncwarp();

        // O += P V  (K = 64 keys, N = 72 d)
        #pragma unroll
        for (int k16 = 0; k16 < 4; k16++) {
            int kw = k16*8 + lc;
            uint32_t af[4];
            af[0] = Ps[(wr+lr)*36 + kw];
            af[1] = Ps[(wr+8+lr)*36 + kw];
            af[2] = Ps[(wr+lr)*36 + kw + 4];
            af[3] = Ps[(wr+8+lr)*36 + kw + 4];
            #pragma unroll
            for (int n9 = 0; n9 < 9; n9++) {
                int cc = n9*8 + lr;
                uint32_t bf[2] = {Vt[cc*36 + kw], Vt[cc*36 + kw + 4]};
                mma_f16(o[n9], af, bf);
            }
        }
    }

    // epilogue -> fp16 g_oh (row-major [B*SEQ][HID], head slice)
    float inv_lo = 1.f / l_lo, inv_hi = 1.f / l_hi;
    int r = b*SEQ + q0 + wr + lr;
    #pragma unroll
    for (int n9 = 0; n9 < 9; n9++) {
        int c = h*HDIM + n9*8 + 2*lc;
        __half2 p0 = __floats2half2_rn(o[n9].x*inv_lo, o[n9].y*inv_lo);
        __half2 p1 = __floats2half2_rn(o[n9].z*inv_hi, o[n9].w*inv_hi);
        *(__half2*)&g_oh[(size_t)r*HID + c]     = p0;
        *(__half2*)&g_oh[(size_t)(r+8)*HID + c] = p1;
    }
}

// ---------------------------------------------------------------------------
extern "C" void kernel_launch(void* const* d_in, const int* in_sizes, int n_in,
                              void* d_out, int out_size) {
    const float* x      = (const float*)d_in[0];
    const float* c      = (const float*)d_in[1];
    const float* w_ada  = (const float*)d_in[2];
    const float* b_ada  = (const float*)d_in[3];
    const float* w_qkv  = (const float*)d_in[4];
    const float* b_qkv  = (const float*)d_in[5];
    const float* qn_w   = (const float*)d_in[6];
    const float* qn_b   = (const float*)d_in[7];
    const float* kn_w   = (const float*)d_in[8];
    const float* kn_b   = (const float*)d_in[9];
    const float* w_proj = (const float*)d_in[10];
    const float* b_proj = (const float*)d_in[11];
    const float* w_fc1  = (const float*)d_in[12];
    const float* b_fc1  = (const float*)d_in[13];
    const float* w_fc2  = (const float*)d_in[14];
    const float* b_fc2  = (const float*)d_in[15];
    float* out = (float*)d_out;

    float *p_proj, *p_x1;
    __half *p_aih, *p_qkvh, *p_oh, *p_mih, *p_hh;
    __half *p_wqkt, *p_wpt, *p_wf1t, *p_wf2t;
    cudaGetSymbolAddress((void**)&p_proj, g_proj);
    cudaGetSymbolAddress((void**)&p_x1,   g_x1);
    cudaGetSymbolAddress((void**)&p_aih,  g_aih);
    cudaGetSymbolAddress((void**)&p_qkvh, g_qkvh);
    cudaGetSymbolAddress((void**)&p_oh,   g_oh);
    cudaGetSymbolAddress((void**)&p_mih,  g_mih);
    cudaGetSymbolAddress((void**)&p_hh,   g_hh);
    cudaGetSymbolAddress((void**)&p_wqkt, g_wqkt);
    cudaGetSymbolAddress((void**)&p_wpt,  g_wpt);
    cudaGetSymbolAddress((void**)&p_wf1t, g_wf1t);
    cudaGetSymbolAddress((void**)&p_wf2t, g_wf2t);

    static int attr_set = 0;
    if (!attr_set) {
        cudaFuncSetAttribute(gemm_hf, cudaFuncAttributeMaxDynamicSharedMemorySize, GEMM_SMEM);
        cudaFuncSetAttribute(attn_h, cudaFuncAttributeMaxDynamicSharedMemorySize, ATTN_SMEM);
        attr_set = 1;
    }

    // weight transposes (fp32 [K][N] -> fp16 [N][K])
    wtrans_kernel<<<dim3(3*HID/32, HID/32), dim3(32,8)>>>(w_qkv, p_wqkt, HID, 3*HID);
    wtrans_kernel<<<dim3(HID/32, HID/32), dim3(32,8)>>>(w_proj, p_wpt, HID, HID);
    wtrans_kernel<<<dim3(DFF/32, HID/32), dim3(32,8)>>>(w_fc1, p_wf1t, HID, DFF);
    wtrans_kernel<<<dim3(HID/32, DFF/32), dim3(32,8)>>>(w_fc2, p_wf2t, DFF, HID);

    silu_kernel<<<(BB*HID + 255)/256, 256>>>(c);
    adaln_kernel<<<dim3(MOD6/256, BB), 256>>>(w_ada, b_ada);
    modulate_kernel<<<MROWS, 256>>>(x, nullptr, 0, 1, -1, nullptr, p_aih);
    // qkv = ai @ w_qkv + b  (fp16 out)
    gemm_hf<<<dim3(3*HID/128, MROWS/128), 128, GEMM_SMEM>>>(p_aih, p_wqkt, b_qkv, p_qkvh,
                                                            MROWS, 3*HID, HID, 0, 1, nullptr, 0);
    qknorm_kernel<<<MROWS*48/8, 256>>>(qn_w, qn_b, kn_w, kn_b);
    attn_h<<<dim3(SEQ/128, NHEAD, BB), 256, ATTN_SMEM>>>();
    // proj (fp32 out)
    gemm_hf<<<dim3(HID/128, MROWS/128), 128, GEMM_SMEM>>>(p_oh, p_wpt, b_proj, p_proj,
                                                          MROWS, HID, HID, 0, 0, nullptr, 0);
    modulate_kernel<<<MROWS, 256>>>(x, p_proj, 3, 4, 2, p_x1, p_mih);
    // fc1 + gelu (fp16 out)
    gemm_hf<<<dim3(DFF/128, MROWS/128), 128, GEMM_SMEM>>>(p_mih, p_wf1t, b_fc1, p_hh,
                                                          MROWS, DFF, HID, 1, 1, nullptr, 0);
    // fc2 with fused  out = x1 + g_mlp * (h @ w_fc2 + b)   (fp32 out)
    gemm_hf<<<dim3(HID/128, MROWS/128), 128, GEMM_SMEM>>>(p_hh, p_wf2t, b_fc2, out,
                                                          MROWS, HID, DFF, 0, 0, p_x1, 5);
}

// round 7
// speedup vs baseline: 6.7822x; 1.0338x over previous
#include <cuda_runtime.h>
#include <cuda_fp16.h>
#include <math.h>
#include <stdint.h>

#define BB 8
#define SEQ 1024
#define HID 1152
#define NHEAD 16
#define HDIM 72
#define DFF 4608
#define MROWS (BB*SEQ)      // 8192
#define MOD6 (6*HID)        // 6912

// ------------------------- scratch (__device__ globals, no allocs) ----------
__device__ float g_silu_c[BB*HID];
__device__ float g_mod[BB*MOD6];
__device__ float g_proj[MROWS*HID];
__device__ float g_x1[MROWS*HID];
// fp16 activations
__device__ __half g_aih[(size_t)MROWS*HID];
__device__ __half g_qkvh[(size_t)MROWS*3*HID];
__device__ __half g_qh[MROWS*HID];
__device__ __half g_kh[MROWS*HID];
__device__ __half g_vh[MROWS*HID];
__device__ __half g_oh[MROWS*HID];
__device__ __half g_mih[(size_t)MROWS*HID];
__device__ __half g_hh[(size_t)MROWS*DFF];
// transposed fp16 weights  Wt[N][K]
__device__ __half g_wqkt[(size_t)3*HID*HID];
__device__ __half g_wpt[(size_t)HID*HID];
__device__ __half g_wf1t[(size_t)DFF*HID];
__device__ __half g_wf2t[(size_t)HID*DFF];

// ------------------------- helpers ------------------------------------------
__device__ __forceinline__ void cp16(void* smem_dst, const void* gsrc) {
    unsigned s = (unsigned)__cvta_generic_to_shared(smem_dst);
    asm volatile("cp.async.cg.shared.global [%0], [%1], 16;" :: "r"(s), "l"(gsrc));
}
__device__ __forceinline__ void mma_f16(float4& d, const uint32_t* a, const uint32_t* b) {
    asm volatile(
        "mma.sync.aligned.m16n8k16.row.col.f32.f16.f16.f32 "
        "{%0,%1,%2,%3}, {%4,%5,%6,%7}, {%8,%9}, {%0,%1,%2,%3};"
        : "+f"(d.x), "+f"(d.y), "+f"(d.z), "+f"(d.w)
        : "r"(a[0]), "r"(a[1]), "r"(a[2]), "r"(a[3]), "r"(b[0]), "r"(b[1]));
}
__device__ __forceinline__ void mma_f16_k8(float4& d, uint32_t a0, uint32_t a1, uint32_t b0) {
    asm volatile(
        "mma.sync.aligned.m16n8k8.row.col.f32.f16.f16.f32 "
        "{%0,%1,%2,%3}, {%4,%5}, {%6}, {%0,%1,%2,%3};"
        : "+f"(d.x), "+f"(d.y), "+f"(d.z), "+f"(d.w)
        : "r"(a0), "r"(a1), "r"(b0));
}
__device__ __forceinline__ void ldsm4(uint32_t& r0, uint32_t& r1, uint32_t& r2, uint32_t& r3,
                                      uint32_t addr) {
    asm volatile("ldmatrix.sync.aligned.m8n8.x4.shared.b16 {%0,%1,%2,%3}, [%4];"
                 : "=r"(r0), "=r"(r1), "=r"(r2), "=r"(r3) : "r"(addr));
}

// ------------------------- weight transpose fp32[K][N] -> fp16[N][K] --------
__global__ void wtrans_kernel(const float* __restrict__ in, __half* __restrict__ out,
                              int K, int N) {
    __shared__ float tile[32][33];
    int k0 = blockIdx.y*32, n0 = blockIdx.x*32;
    int tx = threadIdx.x;
    for (int i = threadIdx.y; i < 32; i += 8)
        tile[i][tx] = in[(size_t)(k0 + i)*N + n0 + tx];
    __syncthreads();
    for (int i = threadIdx.y; i < 32; i += 8)
        out[(size_t)(n0 + i)*K + k0 + tx] = __float2half(tile[tx][i]);
}

// ------------------------- silu(c) ------------------------------------------
__global__ void silu_kernel(const float* __restrict__ c) {
    int i = blockIdx.x * 256 + threadIdx.x;
    if (i < BB*HID) {
        float s = c[i];
        g_silu_c[i] = s / (1.f + expf(-s));
    }
}

// ------------------------- adaLN --------------------------------------------
__global__ void adaln_kernel(const float* __restrict__ w_ada,
                             const float* __restrict__ b_ada) {
    int j = blockIdx.x * 256 + threadIdx.x;
    int b = blockIdx.y;
    if (j >= MOD6) return;
    float acc = b_ada[j];
    const float* cs = &g_silu_c[b*HID];
    for (int k = 0; k < HID; k++)
        acc += cs[k] * w_ada[(size_t)k*MOD6 + j];
    g_mod[b*MOD6 + j] = acc;
}

// --------------- fused (optional residual+gate) + LN + modulate -> fp16 -----
__global__ void modulate_kernel(const float* __restrict__ x,
                                const float* __restrict__ res,
                                int sh_seg, int sc_seg, int g_seg,
                                float* __restrict__ x1_out,
                                __half* __restrict__ mi_out) {
    int r = blockIdx.x;
    int b = r / SEQ;
    const float* modb = &g_mod[b*MOD6];
    const float* xr = x + (size_t)r*HID;
    const float* rr = res ? res + (size_t)r*HID : nullptr;

    float s = 0.f, ss = 0.f;
    for (int ch = threadIdx.x; ch < HID; ch += 256) {
        float val = xr[ch];
        if (rr) val += modb[g_seg*HID + ch] * rr[ch];
        s += val; ss += val*val;
    }
    int lane = threadIdx.x & 31, wid = threadIdx.x >> 5;
    #pragma unroll
    for (int o = 16; o; o >>= 1) {
        s  += __shfl_xor_sync(0xffffffffu, s, o);
        ss += __shfl_xor_sync(0xffffffffu, ss, o);
    }
    __shared__ float sh1[8], sh2[8];
    if (lane == 0) { sh1[wid] = s; sh2[wid] = ss; }
    __syncthreads();
    if (threadIdx.x == 0) {
        float a = 0.f, bb = 0.f;
        #pragma unroll
        for (int i = 0; i < 8; i++) { a += sh1[i]; bb += sh2[i]; }
        sh1[0] = a; sh2[0] = bb;
    }
    __syncthreads();
    float mean = sh1[0] * (1.f/HID);
    float var  = sh2[0] * (1.f/HID) - mean*mean;
    float inv  = rsqrtf(var + 1e-6f);

    for (int ch = threadIdx.x; ch < HID; ch += 256) {
        float val = xr[ch];
        if (rr) val += modb[g_seg*HID + ch] * rr[ch];
        if (x1_out) x1_out[(size_t)r*HID + ch] = val;
        float y = (val - mean) * inv;
        mi_out[(size_t)r*HID + ch] =
            __float2half(y * (1.f + modb[sc_seg*HID + ch]) + modb[sh_seg*HID + ch]);
    }
}

// ------------------------- fp16 HMMA GEMM (ldmatrix + 3-stage) ---------------
// C[M,N] = A[M,K](f16) @ Bt[N,K](f16)^T + bias
// BM=128 BN=128 BK=64, 128 threads, 4 warps (2m x 2n), warp tile 64x64.
#define AW 36
#define TILE_W (128*AW)
#define GEMM_SMEM (6*TILE_W*4)   // 3 stages * (A+B) * 4 bytes = 108 KB

__global__ void __launch_bounds__(128)
gemm_hf(const __half* __restrict__ A, const __half* __restrict__ Bt,
        const float* __restrict__ bias, void* __restrict__ Cout,
        int M, int N, int K, int act, int outH,
        const float* __restrict__ resid, int gate_seg) {
    extern __shared__ uint32_t smw[];
    uint32_t smw_b = (uint32_t)__cvta_generic_to_shared(smw);

    int tid = threadIdx.x, lane = tid & 31, wid = tid >> 5;
    int wm = wid >> 1, wn = wid & 1;
    int row0 = blockIdx.y * 128, col0 = blockIdx.x * 128;
    int lr = lane >> 2, lc = lane & 3;
    // ldmatrix lane decomposition
    int g = lane >> 3, lrow = lane & 7;
    int a_row = wm*64 + (g & 1)*8 + lrow;   // + mi*16
    int a_wc  = (g >> 1)*4;
    int b_row = wn*64 + (g >> 1)*8 + lrow;  // + njp*16
    int b_wc  = (g & 1)*4;

    float4 acc[4][8];
    #pragma unroll
    for (int i = 0; i < 4; i++)
        #pragma unroll
        for (int j = 0; j < 8; j++) acc[i][j] = make_float4(0.f,0.f,0.f,0.f);

    int KT = K >> 6;

    auto load_stage = [&](int kt, int buf) {
        const __half* gA = A  + (size_t)row0*K + kt*64;
        const __half* gB = Bt + (size_t)col0*K + kt*64;
        uint32_t* as = smw + buf*2*TILE_W;
        uint32_t* bs = as + TILE_W;
        #pragma unroll
        for (int i = 0; i < 8; i++) {
            int chunk = tid + i*128;
            int r = chunk >> 3, c = chunk & 7;
            cp16(&as[r*AW + c*4], gA + (size_t)r*K + c*8);
            cp16(&bs[r*AW + c*4], gB + (size_t)r*K + c*8);
        }
        asm volatile("cp.async.commit_group;");
    };

    load_stage(0, 0);
    if (KT > 1) load_stage(1, 1);

    for (int kt = 0; kt < KT; kt++) {
        if (kt < KT - 1) asm volatile("cp.async.wait_group 1;");
        else             asm volatile("cp.async.wait_group 0;");
        __syncthreads();
        if (kt + 2 < KT) load_stage(kt + 2, (kt + 2) % 3);

        int buf = kt % 3;
        uint32_t as_b = smw_b + buf*2*TILE_W*4;
        uint32_t bs_b = as_b + TILE_W*4;
        #pragma unroll
        for (int k16 = 0; k16 < 4; k16++) {
            uint32_t af[4][4];
            #pragma unroll
            for (int mi = 0; mi < 4; mi++)
                ldsm4(af[mi][0], af[mi][1], af[mi][2], af[mi][3],
                      as_b + (uint32_t)(((a_row + mi*16)*AW) + k16*8 + a_wc)*4);
            uint32_t bf[8][2];
            #pragma unroll
            for (int njp = 0; njp < 4; njp++)
                ldsm4(bf[2*njp][0], bf[2*njp][1], bf[2*njp+1][0], bf[2*njp+1][1],
                      bs_b + (uint32_t)(((b_row + njp*16)*AW) + k16*8 + b_wc)*4);
            #pragma unroll
            for (int mi = 0; mi < 4; mi++)
                #pragma unroll
                for (int nj = 0; nj < 8; nj++)
                    mma_f16(acc[mi][nj], af[mi], bf[nj]);
        }
        __syncthreads();
    }

    #pragma unroll
    for (int mi = 0; mi < 4; mi++) {
        #pragma unroll
        for (int nj = 0; nj < 8; nj++) {
            int r = row0 + wm*64 + mi*16 + lr;
            int c = col0 + wn*64 + nj*8 + 2*lc;
            float v[4] = {acc[mi][nj].x, acc[mi][nj].y, acc[mi][nj].z, acc[mi][nj].w};
            float b0 = bias[c], b1 = bias[c+1];
            v[0] += b0; v[1] += b1; v[2] += b0; v[3] += b1;
            if (act == 1) {
                #pragma unroll
                for (int q = 0; q < 4; q++) {
                    float u = v[q];
                    v[q] = 0.5f * u * (1.f + tanhf(0.7978845608028654f * (u + 0.044715f*u*u*u)));
                }
            }
            if (outH) {
                __half* Cb = (__half*)Cout;
                __half2 p0 = __floats2half2_rn(v[0], v[1]);
                __half2 p1 = __floats2half2_rn(v[2], v[3]);
                *(__half2*)&Cb[(size_t)r*N + c]     = p0;
                *(__half2*)&Cb[(size_t)(r+8)*N + c] = p1;
            } else {
                float* Cf = (float*)Cout;
                if (resid) {
                    int b = r / SEQ;
                    float g0 = g_mod[b*MOD6 + gate_seg*HID + c];
                    float g1 = g_mod[b*MOD6 + gate_seg*HID + c + 1];
                    v[0] = resid[(size_t)r*N + c]     + g0*v[0];
                    v[1] = resid[(size_t)r*N + c + 1] + g1*v[1];
                    v[2] = resid[(size_t)(r+8)*N + c]     + g0*v[2];
                    v[3] = resid[(size_t)(r+8)*N + c + 1] + g1*v[3];
                }
                *(float2*)&Cf[(size_t)r*N + c]     = make_float2(v[0], v[1]);
                *(float2*)&Cf[(size_t)(r+8)*N + c] = make_float2(v[2], v[3]);
            }
        }
    }
}

// ------------------------- qk-norm + reshape to [B,NH,N,HD] (fp16) ----------
__global__ void qknorm_kernel(const float* __restrict__ qn_w, const float* __restrict__ qn_b,
                              const float* __restrict__ kn_w, const float* __restrict__ kn_b) {
    int id = blockIdx.x * 8 + (threadIdx.x >> 5);
    if (id >= MROWS*48) return;
    int lane = threadIdx.x & 31;
    int r = id / 48;
    int rem = id % 48;
    int w = rem / 16;
    int h = rem % 16;

    const __half* src = &g_qkvh[(size_t)r*3456 + w*1152 + h*72];
    float v0 = __half2float(src[lane]);
    float v1 = __half2float(src[lane + 32]);
    float v2 = (lane < 8) ? __half2float(src[lane + 64]) : 0.f;

    int b = r / SEQ, n = r % SEQ;
    __half* dst = (w == 0 ? g_qh : (w == 1 ? g_kh : g_vh))
                 + (((size_t)(b*NHEAD + h)*SEQ + n)*HDIM);

    if (w == 2) {
        dst[lane] = __float2half(v0); dst[lane+32] = __float2half(v1);
        if (lane < 8) dst[lane+64] = __float2half(v2);
        return;
    }
    float s = v0 + v1 + v2;
    float ss = v0*v0 + v1*v1 + v2*v2;
    #pragma unroll
    for (int o = 16; o; o >>= 1) {
        s  += __shfl_xor_sync(0xffffffffu, s, o);
        ss += __shfl_xor_sync(0xffffffffu, ss, o);
    }
    float mean = s * (1.f/72.f);
    float var  = ss * (1.f/72.f) - mean*mean;
    float inv  = rsqrtf(var + 1e-5f);
    const float* ww = (w == 0) ? qn_w : kn_w;
    const float* wb = (w == 0) ? qn_b : kn_b;
    dst[lane]      = __float2half((v0 - mean)*inv*ww[lane]      + wb[lane]);
    dst[lane + 32] = __float2half((v1 - mean)*inv*ww[lane + 32] + wb[lane + 32]);
    if (lane < 8)
        dst[lane + 64] = __float2half((v2 - mean)*inv*ww[lane + 64] + wb[lane + 64]);
}

// ------------------------- fp16 tensor-core flash attention -----------------
#define AT_QW (128*36)
#define AT_KW (64*36)
#define AT_VW (72*36)
#define AT_PW (128*36)
#define ATTN_SMEM ((AT_QW + AT_KW + AT_VW + AT_PW)*4)

__global__ void __launch_bounds__(256) attn_h() {
    extern __shared__ uint32_t smw[];
    uint32_t* Qs = smw;
    uint32_t* Ks = Qs + AT_QW;
    uint32_t* Vt = Ks + AT_KW;
    uint32_t* Ps = Vt + AT_VW;
    __half* Vth = (__half*)Vt;

    int b = blockIdx.z, h = blockIdx.y, q0 = blockIdx.x*128;
    int tid = threadIdx.x, lane = tid & 31, wid = tid >> 5;
    int lr = lane >> 2, lc = lane & 3;
    int wr = wid * 16;
    size_t base = (size_t)(b*NHEAD + h) * SEQ * HDIM;
    const float scale = 0.11785113019775793f;

    {
        const uint4* qg = (const uint4*)&g_qh[base + (size_t)q0*HDIM];
        for (int i = tid; i < 128*9; i += 256) {
            int r = i / 9, c = i % 9;
            *(uint4*)&Qs[r*36 + c*4] = qg[i];
        }
    }

    float4 o[9];
    #pragma unroll
    for (int i = 0; i < 9; i++) o[i] = make_float4(0.f,0.f,0.f,0.f);
    float m_lo = -INFINITY, m_hi = -INFINITY, l_lo = 0.f, l_hi = 0.f;

    for (int t = 0; t < 16; t++) {
        __syncthreads();
        {
            const uint4* kg = (const uint4*)&g_kh[base + (size_t)(t*64)*HDIM];
            for (int i = tid; i < 64*9; i += 256) {
                int r = i / 9, c = i % 9;
                *(uint4*)&Ks[r*36 + c*4] = kg[i];
            }
        }
        {
            const uint32_t* vg = (const uint32_t*)&g_vh[base + (size_t)(t*64)*HDIM];
            for (int i = tid; i < 64*36; i += 256) {
                int key = i / 36, dw = i % 36;
                uint32_t wv = vg[i];
                __half2 hv = *(__half2*)&wv;
                Vth[(2*dw)*72 + key]     = hv.x;
                Vth[(2*dw+1)*72 + key]   = hv.y;
            }
        }
        __syncthreads();

        float4 sc[8];
        #pragma unroll
        for (int i = 0; i < 8; i++) sc[i] = make_float4(0.f,0.f,0.f,0.f);
        #pragma unroll
        for (int k16 = 0; k16 < 4; k16++) {
            int kw = k16*8 + lc;
            uint32_t af[4];
            af[0] = Qs[(wr+lr)*36 + kw];
            af[1] = Qs[(wr+8+lr)*36 + kw];
            af[2] = Qs[(wr+lr)*36 + kw + 4];
            af[3] = Qs[(wr+8+lr)*36 + kw + 4];
            #pragma unroll
            for (int nj = 0; nj < 8; nj++) {
                int cc = nj*8 + lr;
                uint32_t bf[2] = {Ks[cc*36 + kw], Ks[cc*36 + kw + 4]};
                mma_f16(sc[nj], af, bf);
            }
        }
        {
            int kw = 32 + lc;
            uint32_t a0 = Qs[(wr+lr)*36 + kw];
            uint32_t a1 = Qs[(wr+8+lr)*36 + kw];
            #pragma unroll
            for (int nj = 0; nj < 8; nj++) {
                int cc = nj*8 + lr;
                mma_f16_k8(sc[nj], a0, a1, Ks[cc*36 + kw]);
            }
        }

        float tmax_lo = -INFINITY, tmax_hi = -INFINITY;
        #pragma unroll
        for (int nj = 0; nj < 8; nj++) {
            sc[nj].x *= scale; sc[nj].y *= scale; sc[nj].z *= scale; sc[nj].w *= scale;
            tmax_lo = fmaxf(tmax_lo, fmaxf(sc[nj].x, sc[nj].y));
            tmax_hi = fmaxf(tmax_hi, fmaxf(sc[nj].z, sc[nj].w));
        }
        tmax_lo = fmaxf(tmax_lo, __shfl_xor_sync(0xffffffffu, tmax_lo, 1));
        tmax_lo = fmaxf(tmax_lo, __shfl_xor_sync(0xffffffffu, tmax_lo, 2));
        tmax_hi = fmaxf(tmax_hi, __shfl_xor_sync(0xffffffffu, tmax_hi, 1));
        tmax_hi = fmaxf(tmax_hi, __shfl_xor_sync(0xffffffffu, tmax_hi, 2));

        float mn_lo = fmaxf(m_lo, tmax_lo);
        float mn_hi = fmaxf(m_hi, tmax_hi);
        float corr_lo = __expf(m_lo - mn_lo);
        float corr_hi = __expf(m_hi - mn_hi);
        l_lo *= corr_lo; l_hi *= corr_hi;
        #pragma unroll
        for (int i = 0; i < 9; i++) {
            o[i].x *= corr_lo; o[i].y *= corr_lo;
            o[i].z *= corr_hi; o[i].w *= corr_hi;
        }
        float sum_lo = 0.f, sum_hi = 0.f;
        #pragma unroll
        for (int nj = 0; nj < 8; nj++) {
            float px = __expf(sc[nj].x - mn_lo);
            float py = __expf(sc[nj].y - mn_lo);
            float pz = __expf(sc[nj].z - mn_hi);
            float pw = __expf(sc[nj].w - mn_hi);
            sum_lo += px + py; sum_hi += pz + pw;
            __half2 plo = __floats2half2_rn(px, py);
            __half2 phi = __floats2half2_rn(pz, pw);
            Ps[(wr+lr)*36 + nj*4 + lc]   = *(uint32_t*)&plo;
            Ps[(wr+8+lr)*36 + nj*4 + lc] = *(uint32_t*)&phi;
        }
        sum_lo += __shfl_xor_sync(0xffffffffu, sum_lo, 1);
        sum_lo += __shfl_xor_sync(0xffffffffu, sum_lo, 2);
        sum_hi += __shfl_xor_sync(0xffffffffu, sum_hi, 1);
        sum_hi += __shfl_xor_sync(0xffffffffu, sum_hi, 2);
        l_lo += sum_lo; l_hi += sum_hi;
        m_lo = mn_lo; m_hi = mn_hi;
        __syncwarp();

        #pragma unroll
        for (int k16 = 0; k16 < 4; k16++) {
            int kw = k16*8 + lc;
            uint32_t af[4];
            af[0] = Ps[(wr+lr)*36 + kw];
            af[1] = Ps[(wr+8+lr)*36 + kw];
            af[2] = Ps[(wr+lr)*36 + kw + 4];
            af[3] = Ps[(wr+8+lr)*36 + kw + 4];
            #pragma unroll
            for (int n9 = 0; n9 < 9; n9++) {
                int cc = n9*8 + lr;
                uint32_t bf[2] = {Vt[cc*36 + kw], Vt[cc*36 + kw + 4]};
                mma_f16(o[n9], af, bf);
            }
        }
    }

    float inv_lo = 1.f / l_lo, inv_hi = 1.f / l_hi;
    int r = b*SEQ + q0 + wr + lr;
    #pragma unroll
    for (int n9 = 0; n9 < 9; n9++) {
        int c = h*HDIM + n9*8 + 2*lc;
        __half2 p0 = __floats2half2_rn(o[n9].x*inv_lo, o[n9].y*inv_lo);
        __half2 p1 = __floats2half2_rn(o[n9].z*inv_hi, o[n9].w*inv_hi);
        *(__half2*)&g_oh[(size_t)r*HID + c]     = p0;
        *(__half2*)&g_oh[(size_t)(r+8)*HID + c] = p1;
    }
}

// ---------------------------------------------------------------------------
extern "C" void kernel_launch(void* const* d_in, const int* in_sizes, int n_in,
                              void* d_out, int out_size) {
    const float* x      = (const float*)d_in[0];
    const float* c      = (const float*)d_in[1];
    const float* w_ada  = (const float*)d_in[2];
    const float* b_ada  = (const float*)d_in[3];
    const float* w_qkv  = (const float*)d_in[4];
    const float* b_qkv  = (const float*)d_in[5];
    const float* qn_w   = (const float*)d_in[6];
    const float* qn_b   = (const float*)d_in[7];
    const float* kn_w   = (const float*)d_in[8];
    const float* kn_b   = (const float*)d_in[9];
    const float* w_proj = (const float*)d_in[10];
    const float* b_proj = (const float*)d_in[11];
    const float* w_fc1  = (const float*)d_in[12];
    const float* b_fc1  = (const float*)d_in[13];
    const float* w_fc2  = (const float*)d_in[14];
    const float* b_fc2  = (const float*)d_in[15];
    float* out = (float*)d_out;

    float *p_proj, *p_x1;
    __half *p_aih, *p_qkvh, *p_oh, *p_mih, *p_hh;
    __half *p_wqkt, *p_wpt, *p_wf1t, *p_wf2t;
    cudaGetSymbolAddress((void**)&p_proj, g_proj);
    cudaGetSymbolAddress((void**)&p_x1,   g_x1);
    cudaGetSymbolAddress((void**)&p_aih,  g_aih);
    cudaGetSymbolAddress((void**)&p_qkvh, g_qkvh);
    cudaGetSymbolAddress((void**)&p_oh,   g_oh);
    cudaGetSymbolAddress((void**)&p_mih,  g_mih);
    cudaGetSymbolAddress((void**)&p_hh,   g_hh);
    cudaGetSymbolAddress((void**)&p_wqkt, g_wqkt);
    cudaGetSymbolAddress((void**)&p_wpt,  g_wpt);
    cudaGetSymbolAddress((void**)&p_wf1t, g_wf1t);
    cudaGetSymbolAddress((void**)&p_wf2t, g_wf2t);

    static int attr_set = 0;
    if (!attr_set) {
        cudaFuncSetAttribute(gemm_hf, cudaFuncAttributeMaxDynamicSharedMemorySize, GEMM_SMEM);
        cudaFuncSetAttribute(attn_h, cudaFuncAttributeMaxDynamicSharedMemorySize, ATTN_SMEM);
        attr_set = 1;
    }

    // Launch order arranged so gemm_hf(qkv) is launch #5 (0-based) for ncu -s 5 -c 1.
    wtrans_kernel<<<dim3(HID/32, DFF/32), dim3(32,8)>>>(w_fc2, p_wf2t, DFF, HID);      // 0
    silu_kernel<<<(BB*HID + 255)/256, 256>>>(c);                                        // 1
    adaln_kernel<<<dim3(MOD6/256, BB), 256>>>(w_ada, b_ada);                            // 2
    modulate_kernel<<<MROWS, 256>>>(x, nullptr, 0, 1, -1, nullptr, p_aih);              // 3
    wtrans_kernel<<<dim3(3*HID/32, HID/32), dim3(32,8)>>>(w_qkv, p_wqkt, HID, 3*HID);   // 4
    gemm_hf<<<dim3(3*HID/128, MROWS/128), 128, GEMM_SMEM>>>(p_aih, p_wqkt, b_qkv, p_qkvh,
                                                            MROWS, 3*HID, HID, 0, 1, nullptr, 0); // 5
    qknorm_kernel<<<MROWS*48/8, 256>>>(qn_w, qn_b, kn_w, kn_b);                         // 6
    wtrans_kernel<<<dim3(HID/32, HID/32), dim3(32,8)>>>(w_proj, p_wpt, HID, HID);       // 7
    wtrans_kernel<<<dim3(DFF/32, HID/32), dim3(32,8)>>>(w_fc1, p_wf1t, HID, DFF);       // 8
    attn_h<<<dim3(SEQ/128, NHEAD, BB), 256, ATTN_SMEM>>>();                             // 9
    gemm_hf<<<dim3(HID/128, MROWS/128), 128, GEMM_SMEM>>>(p_oh, p_wpt, b_proj, p_proj,
                                                          MROWS, HID, HID, 0, 0, nullptr, 0);
    modulate_kernel<<<MROWS, 256>>>(x, p_proj, 3, 4, 2, p_x1, p_mih);
    gemm_hf<<<dim3(DFF/128, MROWS/128), 128, GEMM_SMEM>>>(p_mih, p_wf1t, b_fc1, p_hh,
                                                          MROWS, DFF, HID, 1, 1, nullptr, 0);
    gemm_hf<<<dim3(HID/128, MROWS/128), 128, GEMM_SMEM>>>(p_hh, p_wf2t, b_fc2, out,
                                                          MROWS, HID, DFF, 0, 0, p_x1, 5);
}

// round 8
// speedup vs baseline: 7.2112x; 1.0633x over previous
#include <cuda_runtime.h>
#include <cuda_fp16.h>
#include <math.h>
#include <stdint.h>

#define BB 8
#define SEQ 1024
#define HID 1152
#define NHEAD 16
#define HDIM 72
#define DFF 4608
#define MROWS (BB*SEQ)      // 8192
#define MOD6 (6*HID)        // 6912

// ------------------------- scratch (__device__ globals, no allocs) ----------
__device__ float g_silu_c[BB*HID];
__device__ float g_mod[BB*MOD6];
__device__ float g_proj[MROWS*HID];
__device__ float g_x1[MROWS*HID];
// fp16 activations
__device__ __half g_aih[(size_t)MROWS*HID];
__device__ __half g_qkvh[(size_t)MROWS*3*HID];
__device__ __half g_qh[MROWS*HID];
__device__ __half g_kh[MROWS*HID];
__device__ __half g_vh[MROWS*HID];
__device__ __half g_oh[MROWS*HID];
__device__ __half g_mih[(size_t)MROWS*HID];
__device__ __half g_hh[(size_t)MROWS*DFF];
// transposed fp16 weights  Wt[N][K]
__device__ __half g_wqkt[(size_t)3*HID*HID];
__device__ __half g_wpt[(size_t)HID*HID];
__device__ __half g_wf1t[(size_t)DFF*HID];
__device__ __half g_wf2t[(size_t)HID*DFF];

// ------------------------- helpers ------------------------------------------
__device__ __forceinline__ void cp16(void* smem_dst, const void* gsrc) {
    unsigned s = (unsigned)__cvta_generic_to_shared(smem_dst);
    asm volatile("cp.async.cg.shared.global [%0], [%1], 16;" :: "r"(s), "l"(gsrc));
}
__device__ __forceinline__ void mma_f16(float4& d, const uint32_t* a, const uint32_t* b) {
    asm volatile(
        "mma.sync.aligned.m16n8k16.row.col.f32.f16.f16.f32 "
        "{%0,%1,%2,%3}, {%4,%5,%6,%7}, {%8,%9}, {%0,%1,%2,%3};"
        : "+f"(d.x), "+f"(d.y), "+f"(d.z), "+f"(d.w)
        : "r"(a[0]), "r"(a[1]), "r"(a[2]), "r"(a[3]), "r"(b[0]), "r"(b[1]));
}
__device__ __forceinline__ void mma_f16_k8(float4& d, uint32_t a0, uint32_t a1, uint32_t b0) {
    asm volatile(
        "mma.sync.aligned.m16n8k8.row.col.f32.f16.f16.f32 "
        "{%0,%1,%2,%3}, {%4,%5}, {%6}, {%0,%1,%2,%3};"
        : "+f"(d.x), "+f"(d.y), "+f"(d.z), "+f"(d.w)
        : "r"(a0), "r"(a1), "r"(b0));
}
__device__ __forceinline__ void ldsm4(uint32_t& r0, uint32_t& r1, uint32_t& r2, uint32_t& r3,
                                      uint32_t addr) {
    asm volatile("ldmatrix.sync.aligned.m8n8.x4.shared.b16 {%0,%1,%2,%3}, [%4];"
                 : "=r"(r0), "=r"(r1), "=r"(r2), "=r"(r3) : "r"(addr));
}
__device__ __forceinline__ float fast_gelu(float u) {
    // 0.5u(1+tanh(v)) == u * sigmoid(2v),  v = 0.79788456(u + 0.044715 u^3)
    float e = __expf(-1.5957691216057308f * fmaf(0.044715f*u*u, u, u));
    return __fdividef(u, 1.f + e);
}

// ------------------------- weight transpose fp32[K][N] -> fp16[N][K] --------
__global__ void __launch_bounds__(256)
wtrans_kernel(const float* __restrict__ in, __half* __restrict__ out, int K, int N) {
    __shared__ float tile[64][65];
    int k0 = blockIdx.y*64, n0 = blockIdx.x*64;
    int t = threadIdx.x;
    #pragma unroll
    for (int i = 0; i < 4; i++) {
        int idx = t + i*256;
        int r = idx >> 4, c = idx & 15;
        float4 v = *(const float4*)&in[(size_t)(k0 + r)*N + n0 + c*4];
        tile[r][c*4+0] = v.x; tile[r][c*4+1] = v.y;
        tile[r][c*4+2] = v.z; tile[r][c*4+3] = v.w;
    }
    __syncthreads();
    #pragma unroll
    for (int i = 0; i < 8; i++) {
        int idx = t + i*256;
        int n = idx >> 5, c = idx & 31;   // c = k-pair
        __half2 h = __floats2half2_rn(tile[2*c][n], tile[2*c+1][n]);
        *(__half2*)&out[(size_t)(n0 + n)*K + k0 + 2*c] = h;
    }
}

// ------------------------- silu(c) ------------------------------------------
__global__ void silu_kernel(const float* __restrict__ c) {
    int i = blockIdx.x * 256 + threadIdx.x;
    if (i < BB*HID) {
        float s = c[i];
        g_silu_c[i] = s / (1.f + expf(-s));
    }
}

// ------------------------- adaLN --------------------------------------------
__global__ void adaln_kernel(const float* __restrict__ w_ada,
                             const float* __restrict__ b_ada) {
    int j = blockIdx.x * 256 + threadIdx.x;
    int b = blockIdx.y;
    if (j >= MOD6) return;
    float acc = b_ada[j];
    const float* cs = &g_silu_c[b*HID];
    for (int k = 0; k < HID; k++)
        acc += cs[k] * w_ada[(size_t)k*MOD6 + j];
    g_mod[b*MOD6 + j] = acc;
}

// --------------- fused (optional residual+gate) + LN + modulate -> fp16 -----
// 288 threads, one float4 per thread, single pass (row lives in registers).
__global__ void __launch_bounds__(288)
modulate_kernel(const float* __restrict__ x, const float* __restrict__ res,
                int sh_seg, int sc_seg, int g_seg,
                float* __restrict__ x1_out, __half* __restrict__ mi_out) {
    int r = blockIdx.x, b = r / SEQ, t = threadIdx.x;
    const float* modb = &g_mod[b*MOD6];

    float4 val = *(const float4*)&x[(size_t)r*HID + t*4];
    if (res) {
        float4 rv = *(const float4*)&res[(size_t)r*HID + t*4];
        float4 gv = *(const float4*)&modb[g_seg*HID + t*4];
        val.x = fmaf(gv.x, rv.x, val.x); val.y = fmaf(gv.y, rv.y, val.y);
        val.z = fmaf(gv.z, rv.z, val.z); val.w = fmaf(gv.w, rv.w, val.w);
    }
    if (x1_out) *(float4*)&x1_out[(size_t)r*HID + t*4] = val;

    float s  = val.x + val.y + val.z + val.w;
    float ss = val.x*val.x + val.y*val.y + val.z*val.z + val.w*val.w;
    int lane = t & 31, wid = t >> 5;
    #pragma unroll
    for (int o = 16; o; o >>= 1) {
        s  += __shfl_xor_sync(0xffffffffu, s, o);
        ss += __shfl_xor_sync(0xffffffffu, ss, o);
    }
    __shared__ float sh1[9], sh2[9];
    if (lane == 0) { sh1[wid] = s; sh2[wid] = ss; }
    __syncthreads();
    if (t == 0) {
        float a = 0.f, bb = 0.f;
        #pragma unroll
        for (int i = 0; i < 9; i++) { a += sh1[i]; bb += sh2[i]; }
        sh1[0] = a; sh2[0] = bb;
    }
    __syncthreads();
    float mean = sh1[0] * (1.f/HID);
    float var  = sh2[0] * (1.f/HID) - mean*mean;
    float inv  = rsqrtf(var + 1e-6f);

    float4 sc4 = *(const float4*)&modb[sc_seg*HID + t*4];
    float4 sh4 = *(const float4*)&modb[sh_seg*HID + t*4];
    float y0 = (val.x - mean)*inv*(1.f + sc4.x) + sh4.x;
    float y1 = (val.y - mean)*inv*(1.f + sc4.y) + sh4.y;
    float y2 = (val.z - mean)*inv*(1.f + sc4.z) + sh4.z;
    float y3 = (val.w - mean)*inv*(1.f + sc4.w) + sh4.w;
    __half2 h0 = __floats2half2_rn(y0, y1);
    __half2 h1 = __floats2half2_rn(y2, y3);
    uint2 pk; pk.x = *(uint32_t*)&h0; pk.y = *(uint32_t*)&h1;
    *(uint2*)&mi_out[(size_t)r*HID + t*4] = pk;
}

// ------------------------- fp16 HMMA GEMM (ldmatrix + 3-stage) ---------------
#define AW 36
#define TILE_W (128*AW)
#define GEMM_SMEM (6*TILE_W*4)   // 108 KB

__global__ void __launch_bounds__(128)
gemm_hf(const __half* __restrict__ A, const __half* __restrict__ Bt,
        const float* __restrict__ bias, void* __restrict__ Cout,
        int M, int N, int K, int act, int outH,
        const float* __restrict__ resid, int gate_seg) {
    extern __shared__ uint32_t smw[];
    uint32_t smw_b = (uint32_t)__cvta_generic_to_shared(smw);

    int tid = threadIdx.x, lane = tid & 31, wid = tid >> 5;
    int wm = wid >> 1, wn = wid & 1;
    int row0 = blockIdx.y * 128, col0 = blockIdx.x * 128;
    int lr = lane >> 2, lc = lane & 3;
    int g = lane >> 3, lrow = lane & 7;
    int a_row = wm*64 + (g & 1)*8 + lrow;
    int a_wc  = (g >> 1)*4;
    int b_row = wn*64 + (g >> 1)*8 + lrow;
    int b_wc  = (g & 1)*4;

    float4 acc[4][8];
    #pragma unroll
    for (int i = 0; i < 4; i++)
        #pragma unroll
        for (int j = 0; j < 8; j++) acc[i][j] = make_float4(0.f,0.f,0.f,0.f);

    int KT = K >> 6;

    auto load_stage = [&](int kt, int buf) {
        const __half* gA = A  + (size_t)row0*K + kt*64;
        const __half* gB = Bt + (size_t)col0*K + kt*64;
        uint32_t* as = smw + buf*2*TILE_W;
        uint32_t* bs = as + TILE_W;
        #pragma unroll
        for (int i = 0; i < 8; i++) {
            int chunk = tid + i*128;
            int r = chunk >> 3, c = chunk & 7;
            cp16(&as[r*AW + c*4], gA + (size_t)r*K + c*8);
            cp16(&bs[r*AW + c*4], gB + (size_t)r*K + c*8);
        }
        asm volatile("cp.async.commit_group;");
    };

    load_stage(0, 0);
    if (KT > 1) load_stage(1, 1);

    for (int kt = 0; kt < KT; kt++) {
        if (kt < KT - 1) asm volatile("cp.async.wait_group 1;");
        else             asm volatile("cp.async.wait_group 0;");
        __syncthreads();
        if (kt + 2 < KT) load_stage(kt + 2, (kt + 2) % 3);

        int buf = kt % 3;
        uint32_t as_b = smw_b + buf*2*TILE_W*4;
        uint32_t bs_b = as_b + TILE_W*4;
        #pragma unroll
        for (int k16 = 0; k16 < 4; k16++) {
            uint32_t af[4][4];
            #pragma unroll
            for (int mi = 0; mi < 4; mi++)
                ldsm4(af[mi][0], af[mi][1], af[mi][2], af[mi][3],
                      as_b + (uint32_t)(((a_row + mi*16)*AW) + k16*8 + a_wc)*4);
            uint32_t bf[8][2];
            #pragma unroll
            for (int njp = 0; njp < 4; njp++)
                ldsm4(bf[2*njp][0], bf[2*njp][1], bf[2*njp+1][0], bf[2*njp+1][1],
                      bs_b + (uint32_t)(((b_row + njp*16)*AW) + k16*8 + b_wc)*4);
            #pragma unroll
            for (int mi = 0; mi < 4; mi++)
                #pragma unroll
                for (int nj = 0; nj < 8; nj++)
                    mma_f16(acc[mi][nj], af[mi], bf[nj]);
        }
        __syncthreads();
    }

    #pragma unroll
    for (int mi = 0; mi < 4; mi++) {
        #pragma unroll
        for (int nj = 0; nj < 8; nj++) {
            int r = row0 + wm*64 + mi*16 + lr;
            int c = col0 + wn*64 + nj*8 + 2*lc;
            float v[4] = {acc[mi][nj].x, acc[mi][nj].y, acc[mi][nj].z, acc[mi][nj].w};
            float b0 = bias[c], b1 = bias[c+1];
            v[0] += b0; v[1] += b1; v[2] += b0; v[3] += b1;
            if (act == 1) {
                #pragma unroll
                for (int q = 0; q < 4; q++) v[q] = fast_gelu(v[q]);
            }
            if (outH) {
                __half* Cb = (__half*)Cout;
                __half2 p0 = __floats2half2_rn(v[0], v[1]);
                __half2 p1 = __floats2half2_rn(v[2], v[3]);
                *(__half2*)&Cb[(size_t)r*N + c]     = p0;
                *(__half2*)&Cb[(size_t)(r+8)*N + c] = p1;
            } else {
                float* Cf = (float*)Cout;
                if (resid) {
                    int b = r / SEQ;
                    float g0 = g_mod[b*MOD6 + gate_seg*HID + c];
                    float g1 = g_mod[b*MOD6 + gate_seg*HID + c + 1];
                    v[0] = resid[(size_t)r*N + c]     + g0*v[0];
                    v[1] = resid[(size_t)r*N + c + 1] + g1*v[1];
                    v[2] = resid[(size_t)(r+8)*N + c]     + g0*v[2];
                    v[3] = resid[(size_t)(r+8)*N + c + 1] + g1*v[3];
                }
                *(float2*)&Cf[(size_t)r*N + c]     = make_float2(v[0], v[1]);
                *(float2*)&Cf[(size_t)(r+8)*N + c] = make_float2(v[2], v[3]);
            }
        }
    }
}

// ------------------------- qk-norm + reshape to [B,NH,N,HD] (fp16) ----------
__global__ void qknorm_kernel(const float* __restrict__ qn_w, const float* __restrict__ qn_b,
                              const float* __restrict__ kn_w, const float* __restrict__ kn_b) {
    int id = blockIdx.x * 8 + (threadIdx.x >> 5);
    if (id >= MROWS*48) return;
    int lane = threadIdx.x & 31;
    int r = id / 48;
    int rem = id % 48;
    int w = rem / 16;
    int h = rem % 16;

    const __half* src = &g_qkvh[(size_t)r*3456 + w*1152 + h*72];
    float v0 = __half2float(src[lane]);
    float v1 = __half2float(src[lane + 32]);
    float v2 = (lane < 8) ? __half2float(src[lane + 64]) : 0.f;

    int b = r / SEQ, n = r % SEQ;
    __half* dst = (w == 0 ? g_qh : (w == 1 ? g_kh : g_vh))
                 + (((size_t)(b*NHEAD + h)*SEQ + n)*HDIM);

    if (w == 2) {
        dst[lane] = __float2half(v0); dst[lane+32] = __float2half(v1);
        if (lane < 8) dst[lane+64] = __float2half(v2);
        return;
    }
    float s = v0 + v1 + v2;
    float ss = v0*v0 + v1*v1 + v2*v2;
    #pragma unroll
    for (int o = 16; o; o >>= 1) {
        s  += __shfl_xor_sync(0xffffffffu, s, o);
        ss += __shfl_xor_sync(0xffffffffu, ss, o);
    }
    float mean = s * (1.f/72.f);
    float var  = ss * (1.f/72.f) - mean*mean;
    float inv  = rsqrtf(var + 1e-5f);
    const float* ww = (w == 0) ? qn_w : kn_w;
    const float* wb = (w == 0) ? qn_b : kn_b;
    dst[lane]      = __float2half((v0 - mean)*inv*ww[lane]      + wb[lane]);
    dst[lane + 32] = __float2half((v1 - mean)*inv*ww[lane + 32] + wb[lane + 32]);
    if (lane < 8)
        dst[lane + 64] = __float2half((v2 - mean)*inv*ww[lane + 64] + wb[lane + 64]);
}

// ------------------------- fp16 tensor-core flash attention -----------------
#define AT_QW (128*36)
#define AT_KW (64*36)
#define AT_VW (72*36)
#define AT_PW (128*36)
#define ATTN_SMEM ((AT_QW + AT_KW + AT_VW + AT_PW)*4)

__global__ void __launch_bounds__(256) attn_h() {
    extern __shared__ uint32_t smw[];
    uint32_t* Qs = smw;
    uint32_t* Ks = Qs + AT_QW;
    uint32_t* Vt = Ks + AT_KW;
    uint32_t* Ps = Vt + AT_VW;
    __half* Vth = (__half*)Vt;

    int b = blockIdx.z, h = blockIdx.y, q0 = blockIdx.x*128;
    int tid = threadIdx.x, lane = tid & 31, wid = tid >> 5;
    int lr = lane >> 2, lc = lane & 3;
    int wr = wid * 16;
    size_t base = (size_t)(b*NHEAD + h) * SEQ * HDIM;
    const float scale = 0.11785113019775793f;

    {
        const uint4* qg = (const uint4*)&g_qh[base + (size_t)q0*HDIM];
        for (int i = tid; i < 128*9; i += 256) {
            int r = i / 9, c = i % 9;
            *(uint4*)&Qs[r*36 + c*4] = qg[i];
        }
    }

    float4 o[9];
    #pragma unroll
    for (int i = 0; i < 9; i++) o[i] = make_float4(0.f,0.f,0.f,0.f);
    float m_lo = -INFINITY, m_hi = -INFINITY, l_lo = 0.f, l_hi = 0.f;

    for (int t = 0; t < 16; t++) {
        __syncthreads();
        {
            const uint4* kg = (const uint4*)&g_kh[base + (size_t)(t*64)*HDIM];
            for (int i = tid; i < 64*9; i += 256) {
                int r = i / 9, c = i % 9;
                *(uint4*)&Ks[r*36 + c*4] = kg[i];
            }
        }
        {
            const uint32_t* vg = (const uint32_t*)&g_vh[base + (size_t)(t*64)*HDIM];
            for (int i = tid; i < 64*36; i += 256) {
                int key = i / 36, dw = i % 36;
                uint32_t wv = vg[i];
                __half2 hv = *(__half2*)&wv;
                Vth[(2*dw)*72 + key]     = hv.x;
                Vth[(2*dw+1)*72 + key]   = hv.y;
            }
        }
        __syncthreads();

        float4 sc[8];
        #pragma unroll
        for (int i = 0; i < 8; i++) sc[i] = make_float4(0.f,0.f,0.f,0.f);
        #pragma unroll
        for (int k16 = 0; k16 < 4; k16++) {
            int kw = k16*8 + lc;
            uint32_t af[4];
            af[0] = Qs[(wr+lr)*36 + kw];
            af[1] = Qs[(wr+8+lr)*36 + kw];
            af[2] = Qs[(wr+lr)*36 + kw + 4];
            af[3] = Qs[(wr+8+lr)*36 + kw + 4];
            #pragma unroll
            for (int nj = 0; nj < 8; nj++) {
                int cc = nj*8 + lr;
                uint32_t bf[2] = {Ks[cc*36 + kw], Ks[cc*36 + kw + 4]};
                mma_f16(sc[nj], af, bf);
            }
        }
        {
            int kw = 32 + lc;
            uint32_t a0 = Qs[(wr+lr)*36 + kw];
            uint32_t a1 = Qs[(wr+8+lr)*36 + kw];
            #pragma unroll
            for (int nj = 0; nj < 8; nj++) {
                int cc = nj*8 + lr;
                mma_f16_k8(sc[nj], a0, a1, Ks[cc*36 + kw]);
            }
        }

        float tmax_lo = -INFINITY, tmax_hi = -INFINITY;
        #pragma unroll
        for (int nj = 0; nj < 8; nj++) {
            sc[nj].x *= scale; sc[nj].y *= scale; sc[nj].z *= scale; sc[nj].w *= scale;
            tmax_lo = fmaxf(tmax_lo, fmaxf(sc[nj].x, sc[nj].y));
            tmax_hi = fmaxf(tmax_hi, fmaxf(sc[nj].z, sc[nj].w));
        }
        tmax_lo = fmaxf(tmax_lo, __shfl_xor_sync(0xffffffffu, tmax_lo, 1));
        tmax_lo = fmaxf(tmax_lo, __shfl_xor_sync(0xffffffffu, tmax_lo, 2));
        tmax_hi = fmaxf(tmax_hi, __shfl_xor_sync(0xffffffffu, tmax_hi, 1));
        tmax_hi = fmaxf(tmax_hi, __shfl_xor_sync(0xffffffffu, tmax_hi, 2));

        float mn_lo = fmaxf(m_lo, tmax_lo);
        float mn_hi = fmaxf(m_hi, tmax_hi);
        float corr_lo = __expf(m_lo - mn_lo);
        float corr_hi = __expf(m_hi - mn_hi);
        l_lo *= corr_lo; l_hi *= corr_hi;
        #pragma unroll
        for (int i = 0; i < 9; i++) {
            o[i].x *= corr_lo; o[i].y *= corr_lo;
            o[i].z *= corr_hi; o[i].w *= corr_hi;
        }
        float sum_lo = 0.f, sum_hi = 0.f;
        #pragma unroll
        for (int nj = 0; nj < 8; nj++) {
            float px = __expf(sc[nj].x - mn_lo);
            float py = __expf(sc[nj].y - mn_lo);
            float pz = __expf(sc[nj].z - mn_hi);
            float pw = __expf(sc[nj].w - mn_hi);
            sum_lo += px + py; sum_hi += pz + pw;
            __half2 plo = __floats2half2_rn(px, py);
            __half2 phi = __floats2half2_rn(pz, pw);
            Ps[(wr+lr)*36 + nj*4 + lc]   = *(uint32_t*)&plo;
            Ps[(wr+8+lr)*36 + nj*4 + lc] = *(uint32_t*)&phi;
        }
        sum_lo += __shfl_xor_sync(0xffffffffu, sum_lo, 1);
        sum_lo += __shfl_xor_sync(0xffffffffu, sum_lo, 2);
        sum_hi += __shfl_xor_sync(0xffffffffu, sum_hi, 1);
        sum_hi += __shfl_xor_sync(0xffffffffu, sum_hi, 2);
        l_lo += sum_lo; l_hi += sum_hi;
        m_lo = mn_lo; m_hi = mn_hi;
        __syncwarp();

        #pragma unroll
        for (int k16 = 0; k16 < 4; k16++) {
            int kw = k16*8 + lc;
            uint32_t af[4];
            af[0] = Ps[(wr+lr)*36 + kw];
            af[1] = Ps[(wr+8+lr)*36 + kw];
            af[2] = Ps[(wr+lr)*36 + kw + 4];
            af[3] = Ps[(wr+8+lr)*36 + kw + 4];
            #pragma unroll
            for (int n9 = 0; n9 < 9; n9++) {
                int cc = n9*8 + lr;
                uint32_t bf[2] = {Vt[cc*36 + kw], Vt[cc*36 + kw + 4]};
                mma_f16(o[n9], af, bf);
            }
        }
    }

    float inv_lo = 1.f / l_lo, inv_hi = 1.f / l_hi;
    int r = b*SEQ + q0 + wr + lr;
    #pragma unroll
    for (int n9 = 0; n9 < 9; n9++) {
        int c = h*HDIM + n9*8 + 2*lc;
        __half2 p0 = __floats2half2_rn(o[n9].x*inv_lo, o[n9].y*inv_lo);
        __half2 p1 = __floats2half2_rn(o[n9].z*inv_hi, o[n9].w*inv_hi);
        *(__half2*)&g_oh[(size_t)r*HID + c]     = p0;
        *(__half2*)&g_oh[(size_t)(r+8)*HID + c] = p1;
    }
}

// ---------------------------------------------------------------------------
extern "C" void kernel_launch(void* const* d_in, const int* in_sizes, int n_in,
                              void* d_out, int out_size) {
    const float* x      = (const float*)d_in[0];
    const float* c      = (const float*)d_in[1];
    const float* w_ada  = (const float*)d_in[2];
    const float* b_ada  = (const float*)d_in[3];
    const float* w_qkv  = (const float*)d_in[4];
    const float* b_qkv  = (const float*)d_in[5];
    const float* qn_w   = (const float*)d_in[6];
    const float* qn_b   = (const float*)d_in[7];
    const float* kn_w   = (const float*)d_in[8];
    const float* kn_b   = (const float*)d_in[9];
    const float* w_proj = (const float*)d_in[10];
    const float* b_proj = (const float*)d_in[11];
    const float* w_fc1  = (const float*)d_in[12];
    const float* b_fc1  = (const float*)d_in[13];
    const float* w_fc2  = (const float*)d_in[14];
    const float* b_fc2  = (const float*)d_in[15];
    float* out = (float*)d_out;

    float *p_proj, *p_x1;
    __half *p_aih, *p_qkvh, *p_oh, *p_mih, *p_hh;
    __half *p_wqkt, *p_wpt, *p_wf1t, *p_wf2t;
    cudaGetSymbolAddress((void**)&p_proj, g_proj);
    cudaGetSymbolAddress((void**)&p_x1,   g_x1);
    cudaGetSymbolAddress((void**)&p_aih,  g_aih);
    cudaGetSymbolAddress((void**)&p_qkvh, g_qkvh);
    cudaGetSymbolAddress((void**)&p_oh,   g_oh);
    cudaGetSymbolAddress((void**)&p_mih,  g_mih);
    cudaGetSymbolAddress((void**)&p_hh,   g_hh);
    cudaGetSymbolAddress((void**)&p_wqkt, g_wqkt);
    cudaGetSymbolAddress((void**)&p_wpt,  g_wpt);
    cudaGetSymbolAddress((void**)&p_wf1t, g_wf1t);
    cudaGetSymbolAddress((void**)&p_wf2t, g_wf2t);

    static int attr_set = 0;
    if (!attr_set) {
        cudaFuncSetAttribute(gemm_hf, cudaFuncAttributeMaxDynamicSharedMemorySize, GEMM_SMEM);
        cudaFuncSetAttribute(attn_h, cudaFuncAttributeMaxDynamicSharedMemorySize, ATTN_SMEM);
        attr_set = 1;
    }

    wtrans_kernel<<<dim3(HID/64, DFF/64), 256>>>(w_fc2, p_wf2t, DFF, HID);
    silu_kernel<<<(BB*HID + 255)/256, 256>>>(c);
    adaln_kernel<<<dim3(MOD6/256, BB), 256>>>(w_ada, b_ada);
    modulate_kernel<<<MROWS, 288>>>(x, nullptr, 0, 1, -1, nullptr, p_aih);
    wtrans_kernel<<<dim3(3*HID/64, HID/64), 256>>>(w_qkv, p_wqkt, HID, 3*HID);
    gemm_hf<<<dim3(3*HID/128, MROWS/128), 128, GEMM_SMEM>>>(p_aih, p_wqkt, b_qkv, p_qkvh,
                                                            MROWS, 3*HID, HID, 0, 1, nullptr, 0);
    qknorm_kernel<<<MROWS*48/8, 256>>>(qn_w, qn_b, kn_w, kn_b);
    wtrans_kernel<<<dim3(HID/64, HID/64), 256>>>(w_proj, p_wpt, HID, HID);
    wtrans_kernel<<<dim3(DFF/64, HID/64), 256>>>(w_fc1, p_wf1t, HID, DFF);
    attn_h<<<dim3(SEQ/128, NHEAD, BB), 256, ATTN_SMEM>>>();
    gemm_hf<<<dim3(HID/128, MROWS/128), 128, GEMM_SMEM>>>(p_oh, p_wpt, b_proj, p_proj,
                                                          MROWS, HID, HID, 0, 0, nullptr, 0);
    modulate_kernel<<<MROWS, 288>>>(x, p_proj, 3, 4, 2, p_x1, p_mih);
    gemm_hf<<<dim3(DFF/128, MROWS/128), 128, GEMM_SMEM>>>(p_mih, p_wf1t, b_fc1, p_hh,
                                                          MROWS, DFF, HID, 1, 1, nullptr, 0);
    gemm_hf<<<dim3(HID/128, MROWS/128), 128, GEMM_SMEM>>>(p_hh, p_wf2t, b_fc2, out,
                                                          MROWS, HID, DFF, 0, 0, p_x1, 5);
}

// round 9
// speedup vs baseline: 8.2825x; 1.1486x over previous
#include <cuda_runtime.h>
#include <cuda_fp16.h>
#include <math.h>
#include <stdint.h>

#define BB 8
#define SEQ 1024
#define HID 1152
#define NHEAD 16
#define HDIM 72
#define DFF 4608
#define MROWS (BB*SEQ)      // 8192
#define MOD6 (6*HID)        // 6912

// ------------------------- scratch (__device__ globals, no allocs) ----------
__device__ float g_silu_c[BB*HID];
__device__ float g_mod[BB*MOD6];
__device__ float g_proj[MROWS*HID];
__device__ float g_x1[MROWS*HID];
// fp16 activations
__device__ __half g_aih[(size_t)MROWS*HID];
__device__ __half g_qkvh[(size_t)MROWS*3*HID];
__device__ __half g_qh[MROWS*HID];
__device__ __half g_kh[MROWS*HID];
__device__ __half g_vth[MROWS*HID];          // V transposed per head: [b][h][d][SEQ]
__device__ __half g_oh[MROWS*HID];
__device__ __half g_mih[(size_t)MROWS*HID];
__device__ __half g_hh[(size_t)MROWS*DFF];
// transposed fp16 weights  Wt[N][K]
__device__ __half g_wqkt[(size_t)3*HID*HID];
__device__ __half g_wpt[(size_t)HID*HID];
__device__ __half g_wf1t[(size_t)DFF*HID];
__device__ __half g_wf2t[(size_t)HID*DFF];

// ------------------------- helpers ------------------------------------------
__device__ __forceinline__ void cp16(void* smem_dst, const void* gsrc) {
    unsigned s = (unsigned)__cvta_generic_to_shared(smem_dst);
    asm volatile("cp.async.cg.shared.global [%0], [%1], 16;" :: "r"(s), "l"(gsrc));
}
__device__ __forceinline__ void mma_f16(float4& d, const uint32_t* a, const uint32_t* b) {
    asm volatile(
        "mma.sync.aligned.m16n8k16.row.col.f32.f16.f16.f32 "
        "{%0,%1,%2,%3}, {%4,%5,%6,%7}, {%8,%9}, {%0,%1,%2,%3};"
        : "+f"(d.x), "+f"(d.y), "+f"(d.z), "+f"(d.w)
        : "r"(a[0]), "r"(a[1]), "r"(a[2]), "r"(a[3]), "r"(b[0]), "r"(b[1]));
}
__device__ __forceinline__ void mma_f16_k8(float4& d, uint32_t a0, uint32_t a1, uint32_t b0) {
    asm volatile(
        "mma.sync.aligned.m16n8k8.row.col.f32.f16.f16.f32 "
        "{%0,%1,%2,%3}, {%4,%5}, {%6}, {%0,%1,%2,%3};"
        : "+f"(d.x), "+f"(d.y), "+f"(d.z), "+f"(d.w)
        : "r"(a0), "r"(a1), "r"(b0));
}
__device__ __forceinline__ void ldsm4(uint32_t& r0, uint32_t& r1, uint32_t& r2, uint32_t& r3,
                                      uint32_t addr) {
    asm volatile("ldmatrix.sync.aligned.m8n8.x4.shared.b16 {%0,%1,%2,%3}, [%4];"
                 : "=r"(r0), "=r"(r1), "=r"(r2), "=r"(r3) : "r"(addr));
}
__device__ __forceinline__ float fast_gelu(float u) {
    float e = __expf(-1.5957691216057308f * fmaf(0.044715f*u*u, u, u));
    return __fdividef(u, 1.f + e);
}

// ------------------------- weight transpose fp32[K][N] -> fp16[N][K] --------
__global__ void __launch_bounds__(256)
wtrans_kernel(const float* __restrict__ in, __half* __restrict__ out, int K, int N) {
    __shared__ float tile[64][65];
    int k0 = blockIdx.y*64, n0 = blockIdx.x*64;
    int t = threadIdx.x;
    #pragma unroll
    for (int i = 0; i < 4; i++) {
        int idx = t + i*256;
        int r = idx >> 4, c = idx & 15;
        float4 v = *(const float4*)&in[(size_t)(k0 + r)*N + n0 + c*4];
        tile[r][c*4+0] = v.x; tile[r][c*4+1] = v.y;
        tile[r][c*4+2] = v.z; tile[r][c*4+3] = v.w;
    }
    __syncthreads();
    #pragma unroll
    for (int i = 0; i < 8; i++) {
        int idx = t + i*256;
        int n = idx >> 5, c = idx & 31;
        __half2 h = __floats2half2_rn(tile[2*c][n], tile[2*c+1][n]);
        *(__half2*)&out[(size_t)(n0 + n)*K + k0 + 2*c] = h;
    }
}

// ------------------------- silu(c) ------------------------------------------
__global__ void silu_kernel(const float* __restrict__ c) {
    int i = blockIdx.x * 256 + threadIdx.x;
    if (i < BB*HID) {
        float s = c[i];
        g_silu_c[i] = s / (1.f + expf(-s));
    }
}

// ------------------------- adaLN --------------------------------------------
__global__ void adaln_kernel(const float* __restrict__ w_ada,
                             const float* __restrict__ b_ada) {
    int j = blockIdx.x * 256 + threadIdx.x;
    int b = blockIdx.y;
    if (j >= MOD6) return;
    float acc = b_ada[j];
    const float* cs = &g_silu_c[b*HID];
    for (int k = 0; k < HID; k++)
        acc += cs[k] * w_ada[(size_t)k*MOD6 + j];
    g_mod[b*MOD6 + j] = acc;
}

// --------------- fused (optional residual+gate) + LN + modulate -> fp16 -----
__global__ void __launch_bounds__(288)
modulate_kernel(const float* __restrict__ x, const float* __restrict__ res,
                int sh_seg, int sc_seg, int g_seg,
                float* __restrict__ x1_out, __half* __restrict__ mi_out) {
    int r = blockIdx.x, b = r / SEQ, t = threadIdx.x;
    const float* modb = &g_mod[b*MOD6];

    float4 val = *(const float4*)&x[(size_t)r*HID + t*4];
    if (res) {
        float4 rv = *(const float4*)&res[(size_t)r*HID + t*4];
        float4 gv = *(const float4*)&modb[g_seg*HID + t*4];
        val.x = fmaf(gv.x, rv.x, val.x); val.y = fmaf(gv.y, rv.y, val.y);
        val.z = fmaf(gv.z, rv.z, val.z); val.w = fmaf(gv.w, rv.w, val.w);
    }
    if (x1_out) *(float4*)&x1_out[(size_t)r*HID + t*4] = val;

    float s  = val.x + val.y + val.z + val.w;
    float ss = val.x*val.x + val.y*val.y + val.z*val.z + val.w*val.w;
    int lane = t & 31, wid = t >> 5;
    #pragma unroll
    for (int o = 16; o; o >>= 1) {
        s  += __shfl_xor_sync(0xffffffffu, s, o);
        ss += __shfl_xor_sync(0xffffffffu, ss, o);
    }
    __shared__ float sh1[9], sh2[9];
    if (lane == 0) { sh1[wid] = s; sh2[wid] = ss; }
    __syncthreads();
    if (t == 0) {
        float a = 0.f, bb = 0.f;
        #pragma unroll
        for (int i = 0; i < 9; i++) { a += sh1[i]; bb += sh2[i]; }
        sh1[0] = a; sh2[0] = bb;
    }
    __syncthreads();
    float mean = sh1[0] * (1.f/HID);
    float var  = sh2[0] * (1.f/HID) - mean*mean;
    float inv  = rsqrtf(var + 1e-6f);

    float4 sc4 = *(const float4*)&modb[sc_seg*HID + t*4];
    float4 sh4 = *(const float4*)&modb[sh_seg*HID + t*4];
    float y0 = (val.x - mean)*inv*(1.f + sc4.x) + sh4.x;
    float y1 = (val.y - mean)*inv*(1.f + sc4.y) + sh4.y;
    float y2 = (val.z - mean)*inv*(1.f + sc4.z) + sh4.z;
    float y3 = (val.w - mean)*inv*(1.f + sc4.w) + sh4.w;
    __half2 h0 = __floats2half2_rn(y0, y1);
    __half2 h1 = __floats2half2_rn(y2, y3);
    uint2 pk; pk.x = *(uint32_t*)&h0; pk.y = *(uint32_t*)&h1;
    *(uint2*)&mi_out[(size_t)r*HID + t*4] = pk;
}

// ------------------------- fp16 HMMA GEMM (ldmatrix + 3-stage) ---------------
#define AW 36
#define TILE_W (128*AW)
#define GEMM_SMEM (6*TILE_W*4)   // 108 KB

__global__ void __launch_bounds__(128)
gemm_hf(const __half* __restrict__ A, const __half* __restrict__ Bt,
        const float* __restrict__ bias, void* __restrict__ Cout,
        int M, int N, int K, int act, int outH,
        const float* __restrict__ resid, int gate_seg) {
    extern __shared__ uint32_t smw[];
    uint32_t smw_b = (uint32_t)__cvta_generic_to_shared(smw);

    int tid = threadIdx.x, lane = tid & 31, wid = tid >> 5;
    int wm = wid >> 1, wn = wid & 1;
    int row0 = blockIdx.y * 128, col0 = blockIdx.x * 128;
    int lr = lane >> 2, lc = lane & 3;
    int g = lane >> 3, lrow = lane & 7;
    int a_row = wm*64 + (g & 1)*8 + lrow;
    int a_wc  = (g >> 1)*4;
    int b_row = wn*64 + (g >> 1)*8 + lrow;
    int b_wc  = (g & 1)*4;

    float4 acc[4][8];
    #pragma unroll
    for (int i = 0; i < 4; i++)
        #pragma unroll
        for (int j = 0; j < 8; j++) acc[i][j] = make_float4(0.f,0.f,0.f,0.f);

    int KT = K >> 6;

    auto load_stage = [&](int kt, int buf) {
        const __half* gA = A  + (size_t)row0*K + kt*64;
        const __half* gB = Bt + (size_t)col0*K + kt*64;
        uint32_t* as = smw + buf*2*TILE_W;
        uint32_t* bs = as + TILE_W;
        #pragma unroll
        for (int i = 0; i < 8; i++) {
            int chunk = tid + i*128;
            int r = chunk >> 3, c = chunk & 7;
            cp16(&as[r*AW + c*4], gA + (size_t)r*K + c*8);
            cp16(&bs[r*AW + c*4], gB + (size_t)r*K + c*8);
        }
        asm volatile("cp.async.commit_group;");
    };

    load_stage(0, 0);
    if (KT > 1) load_stage(1, 1);

    for (int kt = 0; kt < KT; kt++) {
        if (kt < KT - 1) asm volatile("cp.async.wait_group 1;");
        else             asm volatile("cp.async.wait_group 0;");
        __syncthreads();
        if (kt + 2 < KT) load_stage(kt + 2, (kt + 2) % 3);

        int buf = kt % 3;
        uint32_t as_b = smw_b + buf*2*TILE_W*4;
        uint32_t bs_b = as_b + TILE_W*4;
        #pragma unroll
        for (int k16 = 0; k16 < 4; k16++) {
            uint32_t af[4][4];
            #pragma unroll
            for (int mi = 0; mi < 4; mi++)
                ldsm4(af[mi][0], af[mi][1], af[mi][2], af[mi][3],
                      as_b + (uint32_t)(((a_row + mi*16)*AW) + k16*8 + a_wc)*4);
            uint32_t bf[8][2];
            #pragma unroll
            for (int njp = 0; njp < 4; njp++)
                ldsm4(bf[2*njp][0], bf[2*njp][1], bf[2*njp+1][0], bf[2*njp+1][1],
                      bs_b + (uint32_t)(((b_row + njp*16)*AW) + k16*8 + b_wc)*4);
            #pragma unroll
            for (int mi = 0; mi < 4; mi++)
                #pragma unroll
                for (int nj = 0; nj < 8; nj++)
                    mma_f16(acc[mi][nj], af[mi], bf[nj]);
        }
        __syncthreads();
    }

    #pragma unroll
    for (int mi = 0; mi < 4; mi++) {
        #pragma unroll
        for (int nj = 0; nj < 8; nj++) {
            int r = row0 + wm*64 + mi*16 + lr;
            int c = col0 + wn*64 + nj*8 + 2*lc;
            float v[4] = {acc[mi][nj].x, acc[mi][nj].y, acc[mi][nj].z, acc[mi][nj].w};
            float b0 = bias[c], b1 = bias[c+1];
            v[0] += b0; v[1] += b1; v[2] += b0; v[3] += b1;
            if (act == 1) {
                #pragma unroll
                for (int q = 0; q < 4; q++) v[q] = fast_gelu(v[q]);
            }
            if (outH) {
                __half* Cb = (__half*)Cout;
                __half2 p0 = __floats2half2_rn(v[0], v[1]);
                __half2 p1 = __floats2half2_rn(v[2], v[3]);
                *(__half2*)&Cb[(size_t)r*N + c]     = p0;
                *(__half2*)&Cb[(size_t)(r+8)*N + c] = p1;
            } else {
                float* Cf = (float*)Cout;
                if (resid) {
                    int b = r / SEQ;
                    float g0 = g_mod[b*MOD6 + gate_seg*HID + c];
                    float g1 = g_mod[b*MOD6 + gate_seg*HID + c + 1];
                    v[0] = resid[(size_t)r*N + c]     + g0*v[0];
                    v[1] = resid[(size_t)r*N + c + 1] + g1*v[1];
                    v[2] = resid[(size_t)(r+8)*N + c]     + g0*v[2];
                    v[3] = resid[(size_t)(r+8)*N + c + 1] + g1*v[3];
                }
                *(float2*)&Cf[(size_t)r*N + c]     = make_float2(v[0], v[1]);
                *(float2*)&Cf[(size_t)(r+8)*N + c] = make_float2(v[2], v[3]);
            }
        }
    }
}

// ------------------------- qk-norm (q,k only) -> [B,NH,N,HD] fp16 -----------
__global__ void qknorm_kernel(const float* __restrict__ qn_w, const float* __restrict__ qn_b,
                              const float* __restrict__ kn_w, const float* __restrict__ kn_b) {
    int id = blockIdx.x * 8 + (threadIdx.x >> 5);
    if (id >= MROWS*32) return;
    int lane = threadIdx.x & 31;
    int r = id >> 5;
    int rem = id & 31;
    int w = rem >> 4;      // 0=q, 1=k
    int h = rem & 15;

    const __half* src = &g_qkvh[(size_t)r*3456 + w*1152 + h*72];
    float v0 = __half2float(src[lane]);
    float v1 = __half2float(src[lane + 32]);
    float v2 = (lane < 8) ? __half2float(src[lane + 64]) : 0.f;

    int b = r / SEQ, n = r % SEQ;
    __half* dst = (w == 0 ? g_qh : g_kh)
                 + (((size_t)(b*NHEAD + h)*SEQ + n)*HDIM);

    float s = v0 + v1 + v2;
    float ss = v0*v0 + v1*v1 + v2*v2;
    #pragma unroll
    for (int o = 16; o; o >>= 1) {
        s  += __shfl_xor_sync(0xffffffffu, s, o);
        ss += __shfl_xor_sync(0xffffffffu, ss, o);
    }
    float mean = s * (1.f/72.f);
    float var  = ss * (1.f/72.f) - mean*mean;
    float inv  = rsqrtf(var + 1e-5f);
    const float* ww = (w == 0) ? qn_w : kn_w;
    const float* wb = (w == 0) ? qn_b : kn_b;
    dst[lane]      = __float2half((v0 - mean)*inv*ww[lane]      + wb[lane]);
    dst[lane + 32] = __float2half((v1 - mean)*inv*ww[lane + 32] + wb[lane + 32]);
    if (lane < 8)
        dst[lane + 64] = __float2half((v2 - mean)*inv*ww[lane + 64] + wb[lane + 64]);
}

// ------------------------- V transpose: qkv v-slice -> [b][h][d][SEQ] -------
__global__ void __launch_bounds__(128) vtrans_kernel() {
    __shared__ uint32_t tile[64*37];   // stride 37 words = 74 halves
    int kt = blockIdx.x, h = blockIdx.y, b = blockIdx.z;
    int t = threadIdx.x;
    const uint32_t* src32 = (const uint32_t*)g_qkvh;

    for (int i = t; i < 64*36; i += 128) {
        int key = i / 36, w = i % 36;
        size_t off = ((size_t)(b*SEQ + kt*64 + key)*3456 + 2304 + h*72) / 2 + w;
        tile[key*37 + w] = src32[off];
    }
    __syncthreads();
    const __half* tileh = (const __half*)tile;
    uint32_t* dst32 = (uint32_t*)g_vth;
    for (int i = t; i < 72*32; i += 128) {
        int d = i / 32, w2 = i % 32;
        __half2 p;
        p.x = tileh[(2*w2)*74 + d];
        p.y = tileh[(2*w2 + 1)*74 + d];
        dst32[((size_t)((b*NHEAD + h)*HDIM + d)*SEQ)/2 + kt*32 + w2] = *(uint32_t*)&p;
    }
}

// ------------------------- fp16 tensor-core flash attention -----------------
// cp.async double-buffered K + pre-transposed V; one syncthreads per tile.
#define AT_QW (128*36)
#define AT_KW (64*36)
#define AT_VW (72*36)
#define AT_PW (128*36)
#define ATTN_SMEM ((AT_QW + 2*AT_KW + 2*AT_VW + AT_PW)*4)   // 76 KB

__global__ void __launch_bounds__(256) attn_h() {
    extern __shared__ uint32_t smw[];
    uint32_t* Qs = smw;
    uint32_t* Kb = Qs + AT_QW;           // [2][64][36]
    uint32_t* Vb = Kb + 2*AT_KW;         // [2][72][36] (V^T rows = d)
    uint32_t* Ps = Vb + 2*AT_VW;

    int b = blockIdx.z, h = blockIdx.y, q0 = blockIdx.x*128;
    int tid = threadIdx.x, lane = tid & 31, wid = tid >> 5;
    int lr = lane >> 2, lc = lane & 3;
    int wr = wid * 16;
    size_t base = (size_t)(b*NHEAD + h) * SEQ * HDIM;
    const __half* vbase = &g_vth[(size_t)(b*NHEAD + h) * HDIM * SEQ];
    const float scale = 0.11785113019775793f;

    auto load_stage = [&](int t, int buf) {
        const __half* kg = &g_kh[base + (size_t)(t*64)*HDIM];
        for (int i = tid; i < 576; i += 256) {
            int r = i / 9, c = i % 9;
            cp16(&Kb[buf*AT_KW + r*36 + c*4], kg + r*HDIM + c*8);
        }
        const __half* vg = vbase + t*64;
        for (int i = tid; i < 576; i += 256) {
            int d = i >> 3, c = i & 7;
            cp16(&Vb[buf*AT_VW + d*36 + c*4], vg + (size_t)d*SEQ + c*8);
        }
        asm volatile("cp.async.commit_group;");
    };

    // Q tile (plain loads; first loop syncthreads publishes it)
    {
        const uint4* qg = (const uint4*)&g_qh[base + (size_t)q0*HDIM];
        for (int i = tid; i < 128*9; i += 256) {
            int r = i / 9, c = i % 9;
            *(uint4*)&Qs[r*36 + c*4] = qg[i];
        }
    }
    load_stage(0, 0);

    float4 o[9];
    #pragma unroll
    for (int i = 0; i < 9; i++) o[i] = make_float4(0.f,0.f,0.f,0.f);
    float m_lo = -INFINITY, m_hi = -INFINITY, l_lo = 0.f, l_hi = 0.f;

    for (int t = 0; t < 16; t++) {
        asm volatile("cp.async.wait_group 0;");
        __syncthreads();
        if (t + 1 < 16) load_stage(t + 1, (t + 1) & 1);
        int buf = t & 1;
        const uint32_t* Ks = &Kb[buf*AT_KW];
        const uint32_t* Vt = &Vb[buf*AT_VW];

        float4 sc[8];
        #pragma unroll
        for (int i = 0; i < 8; i++) sc[i] = make_float4(0.f,0.f,0.f,0.f);
        #pragma unroll
        for (int k16 = 0; k16 < 4; k16++) {
            int kw = k16*8 + lc;
            uint32_t af[4];
            af[0] = Qs[(wr+lr)*36 + kw];
            af[1] = Qs[(wr+8+lr)*36 + kw];
            af[2] = Qs[(wr+lr)*36 + kw + 4];
            af[3] = Qs[(wr+8+lr)*36 + kw + 4];
            #pragma unroll
            for (int nj = 0; nj < 8; nj++) {
                int cc = nj*8 + lr;
                uint32_t bf[2] = {Ks[cc*36 + kw], Ks[cc*36 + kw + 4]};
                mma_f16(sc[nj], af, bf);
            }
        }
        {
            int kw = 32 + lc;
            uint32_t a0 = Qs[(wr+lr)*36 + kw];
            uint32_t a1 = Qs[(wr+8+lr)*36 + kw];
            #pragma unroll
            for (int nj = 0; nj < 8; nj++) {
                int cc = nj*8 + lr;
                mma_f16_k8(sc[nj], a0, a1, Ks[cc*36 + kw]);
            }
        }

        float tmax_lo = -INFINITY, tmax_hi = -INFINITY;
        #pragma unroll
        for (int nj = 0; nj < 8; nj++) {
            sc[nj].x *= scale; sc[nj].y *= scale; sc[nj].z *= scale; sc[nj].w *= scale;
            tmax_lo = fmaxf(tmax_lo, fmaxf(sc[nj].x, sc[nj].y));
            tmax_hi = fmaxf(tmax_hi, fmaxf(sc[nj].z, sc[nj].w));
        }
        tmax_lo = fmaxf(tmax_lo, __shfl_xor_sync(0xffffffffu, tmax_lo, 1));
        tmax_lo = fmaxf(tmax_lo, __shfl_xor_sync(0xffffffffu, tmax_lo, 2));
        tmax_hi = fmaxf(tmax_hi, __shfl_xor_sync(0xffffffffu, tmax_hi, 1));
        tmax_hi = fmaxf(tmax_hi, __shfl_xor_sync(0xffffffffu, tmax_hi, 2));

        float mn_lo = fmaxf(m_lo, tmax_lo);
        float mn_hi = fmaxf(m_hi, tmax_hi);
        float corr_lo = __expf(m_lo - mn_lo);
        float corr_hi = __expf(m_hi - mn_hi);
        l_lo *= corr_lo; l_hi *= corr_hi;
        #pragma unroll
        for (int i = 0; i < 9; i++) {
            o[i].x *= corr_lo; o[i].y *= corr_lo;
            o[i].z *= corr_hi; o[i].w *= corr_hi;
        }
        float sum_lo = 0.f, sum_hi = 0.f;
        #pragma unroll
        for (int nj = 0; nj < 8; nj++) {
            float px = __expf(sc[nj].x - mn_lo);
            float py = __expf(sc[nj].y - mn_lo);
            float pz = __expf(sc[nj].z - mn_hi);
            float pw = __expf(sc[nj].w - mn_hi);
            sum_lo += px + py; sum_hi += pz + pw;
            __half2 plo = __floats2half2_rn(px, py);
            __half2 phi = __floats2half2_rn(pz, pw);
            Ps[(wr+lr)*36 + nj*4 + lc]   = *(uint32_t*)&plo;
            Ps[(wr+8+lr)*36 + nj*4 + lc] = *(uint32_t*)&phi;
        }
        sum_lo += __shfl_xor_sync(0xffffffffu, sum_lo, 1);
        sum_lo += __shfl_xor_sync(0xffffffffu, sum_lo, 2);
        sum_hi += __shfl_xor_sync(0xffffffffu, sum_hi, 1);
        sum_hi += __shfl_xor_sync(0xffffffffu, sum_hi, 2);
        l_lo += sum_lo; l_hi += sum_hi;
        m_lo = mn_lo; m_hi = mn_hi;
        __syncwarp();

        #pragma unroll
        for (int k16 = 0; k16 < 4; k16++) {
            int kw = k16*8 + lc;
            uint32_t af[4];
            af[0] = Ps[(wr+lr)*36 + kw];
            af[1] = Ps[(wr+8+lr)*36 + kw];
            af[2] = Ps[(wr+lr)*36 + kw + 4];
            af[3] = Ps[(wr+8+lr)*36 + kw + 4];
            #pragma unroll
            for (int n9 = 0; n9 < 9; n9++) {
                int cc = n9*8 + lr;
                uint32_t bf[2] = {Vt[cc*36 + kw], Vt[cc*36 + kw + 4]};
                mma_f16(o[n9], af, bf);
            }
        }
    }

    float inv_lo = 1.f / l_lo, inv_hi = 1.f / l_hi;
    int r = b*SEQ + q0 + wr + lr;
    #pragma unroll
    for (int n9 = 0; n9 < 9; n9++) {
        int c = h*HDIM + n9*8 + 2*lc;
        __half2 p0 = __floats2half2_rn(o[n9].x*inv_lo, o[n9].y*inv_lo);
        __half2 p1 = __floats2half2_rn(o[n9].z*inv_hi, o[n9].w*inv_hi);
        *(__half2*)&g_oh[(size_t)r*HID + c]     = p0;
        *(__half2*)&g_oh[(size_t)(r+8)*HID + c] = p1;
    }
}

// ---------------------------------------------------------------------------
extern "C" void kernel_launch(void* const* d_in, const int* in_sizes, int n_in,
                              void* d_out, int out_size) {
    const float* x      = (const float*)d_in[0];
    const float* c      = (const float*)d_in[1];
    const float* w_ada  = (const float*)d_in[2];
    const float* b_ada  = (const float*)d_in[3];
    const float* w_qkv  = (const float*)d_in[4];
    const float* b_qkv  = (const float*)d_in[5];
    const float* qn_w   = (const float*)d_in[6];
    const float* qn_b   = (const float*)d_in[7];
    const float* kn_w   = (const float*)d_in[8];
    const float* kn_b   = (const float*)d_in[9];
    const float* w_proj = (const float*)d_in[10];
    const float* b_proj = (const float*)d_in[11];
    const float* w_fc1  = (const float*)d_in[12];
    const float* b_fc1  = (const float*)d_in[13];
    const float* w_fc2  = (const float*)d_in[14];
    const float* b_fc2  = (const float*)d_in[15];
    float* out = (float*)d_out;

    float *p_proj, *p_x1;
    __half *p_aih, *p_qkvh, *p_oh, *p_mih, *p_hh;
    __half *p_wqkt, *p_wpt, *p_wf1t, *p_wf2t;
    cudaGetSymbolAddress((void**)&p_proj, g_proj);
    cudaGetSymbolAddress((void**)&p_x1,   g_x1);
    cudaGetSymbolAddress((void**)&p_aih,  g_aih);
    cudaGetSymbolAddress((void**)&p_qkvh, g_qkvh);
    cudaGetSymbolAddress((void**)&p_oh,   g_oh);
    cudaGetSymbolAddress((void**)&p_mih,  g_mih);
    cudaGetSymbolAddress((void**)&p_hh,   g_hh);
    cudaGetSymbolAddress((void**)&p_wqkt, g_wqkt);
    cudaGetSymbolAddress((void**)&p_wpt,  g_wpt);
    cudaGetSymbolAddress((void**)&p_wf1t, g_wf1t);
    cudaGetSymbolAddress((void**)&p_wf2t, g_wf2t);

    static int attr_set = 0;
    if (!attr_set) {
        cudaFuncSetAttribute(gemm_hf, cudaFuncAttributeMaxDynamicSharedMemorySize, GEMM_SMEM);
        cudaFuncSetAttribute(attn_h, cudaFuncAttributeMaxDynamicSharedMemorySize, ATTN_SMEM);
        attr_set = 1;
    }

    wtrans_kernel<<<dim3(HID/64, DFF/64), 256>>>(w_fc2, p_wf2t, DFF, HID);               // 0
    silu_kernel<<<(BB*HID + 255)/256, 256>>>(c);                                          // 1
    adaln_kernel<<<dim3(MOD6/256, BB), 256>>>(w_ada, b_ada);                              // 2
    modulate_kernel<<<MROWS, 288>>>(x, nullptr, 0, 1, -1, nullptr, p_aih);                // 3
    wtrans_kernel<<<dim3(3*HID/64, HID/64), 256>>>(w_qkv, p_wqkt, HID, 3*HID);            // 4
    gemm_hf<<<dim3(3*HID/128, MROWS/128), 128, GEMM_SMEM>>>(p_aih, p_wqkt, b_qkv, p_qkvh,
                                                            MROWS, 3*HID, HID, 0, 1, nullptr, 0); // 5
    qknorm_kernel<<<MROWS*32/8, 256>>>(qn_w, qn_b, kn_w, kn_b);                           // 6
    vtrans_kernel<<<dim3(SEQ/64, NHEAD, BB), 128>>>();                                    // 7
    wtrans_kernel<<<dim3(HID/64, HID/64), 256>>>(w_proj, p_wpt, HID, HID);                // 8
    wtrans_kernel<<<dim3(DFF/64, HID/64), 256>>>(w_fc1, p_wf1t, HID, DFF);                // 9
    attn_h<<<dim3(SEQ/128, NHEAD, BB), 256, ATTN_SMEM>>>();                               // 10
    gemm_hf<<<dim3(HID/128, MROWS/128), 128, GEMM_SMEM>>>(p_oh, p_wpt, b_proj, p_proj,
                                                          MROWS, HID, HID, 0, 0, nullptr, 0);
    modulate_kernel<<<MROWS, 288>>>(x, p_proj, 3, 4, 2, p_x1, p_mih);
    gemm_hf<<<dim3(DFF/128, MROWS/128), 128, GEMM_SMEM>>>(p_mih, p_wf1t, b_fc1, p_hh,
                                                          MROWS, DFF, HID, 1, 1, nullptr, 0);
    gemm_hf<<<dim3(HID/128, MROWS/128), 128, GEMM_SMEM>>>(p_hh, p_wf2t, b_fc2, out,
                                                          MROWS, HID, DFF, 0, 0, p_x1, 5);
}

// round 10
// speedup vs baseline: 8.3402x; 1.0070x over previous
#include <cuda_runtime.h>
#include <cuda_fp16.h>
#include <math.h>
#include <stdint.h>

#define BB 8
#define SEQ 1024
#define HID 1152
#define NHEAD 16
#define HDIM 72
#define DFF 4608
#define MROWS (BB*SEQ)      // 8192
#define MOD6 (6*HID)        // 6912

// ------------------------- scratch (__device__ globals, no allocs) ----------
__device__ float g_silu_c[BB*HID];
__device__ float g_mod[BB*MOD6];
__device__ float g_x1[MROWS*HID];
// fp16 activations
__device__ __half g_aih[(size_t)MROWS*HID];
__device__ __half g_qkvh[(size_t)MROWS*3*HID];
__device__ __half g_qh[MROWS*HID];
__device__ __half g_kh[MROWS*HID];
__device__ __half g_vth[MROWS*HID];          // V transposed per head: [b][h][d][SEQ]
__device__ __half g_oh[MROWS*HID];
__device__ __half g_mih[(size_t)MROWS*HID];
__device__ __half g_hh[(size_t)MROWS*DFF];
// transposed fp16 weights  Wt[N][K]
__device__ __half g_wqkt[(size_t)3*HID*HID];
__device__ __half g_wpt[(size_t)HID*HID];
__device__ __half g_wf1t[(size_t)DFF*HID];
__device__ __half g_wf2t[(size_t)HID*DFF];

// ------------------------- helpers ------------------------------------------
__device__ __forceinline__ void cp16(void* smem_dst, const void* gsrc) {
    unsigned s = (unsigned)__cvta_generic_to_shared(smem_dst);
    asm volatile("cp.async.cg.shared.global [%0], [%1], 16;" :: "r"(s), "l"(gsrc));
}
__device__ __forceinline__ void mma_f16(float4& d, const uint32_t* a, const uint32_t* b) {
    asm volatile(
        "mma.sync.aligned.m16n8k16.row.col.f32.f16.f16.f32 "
        "{%0,%1,%2,%3}, {%4,%5,%6,%7}, {%8,%9}, {%0,%1,%2,%3};"
        : "+f"(d.x), "+f"(d.y), "+f"(d.z), "+f"(d.w)
        : "r"(a[0]), "r"(a[1]), "r"(a[2]), "r"(a[3]), "r"(b[0]), "r"(b[1]));
}
__device__ __forceinline__ void mma_f16_k8(float4& d, uint32_t a0, uint32_t a1, uint32_t b0) {
    asm volatile(
        "mma.sync.aligned.m16n8k8.row.col.f32.f16.f16.f32 "
        "{%0,%1,%2,%3}, {%4,%5}, {%6}, {%0,%1,%2,%3};"
        : "+f"(d.x), "+f"(d.y), "+f"(d.z), "+f"(d.w)
        : "r"(a0), "r"(a1), "r"(b0));
}
__device__ __forceinline__ void ldsm4(uint32_t& r0, uint32_t& r1, uint32_t& r2, uint32_t& r3,
                                      uint32_t addr) {
    asm volatile("ldmatrix.sync.aligned.m8n8.x4.shared.b16 {%0,%1,%2,%3}, [%4];"
                 : "=r"(r0), "=r"(r1), "=r"(r2), "=r"(r3) : "r"(addr));
}
__device__ __forceinline__ float fast_gelu(float u) {
    float e = __expf(-1.5957691216057308f * fmaf(0.044715f*u*u, u, u));
    return __fdividef(u, 1.f + e);
}

// ------------------------- weight transpose fp32[K][N] -> fp16[N][K] --------
__global__ void __launch_bounds__(256)
wtrans_kernel(const float* __restrict__ in, __half* __restrict__ out, int K, int N) {
    __shared__ float tile[64][65];
    int k0 = blockIdx.y*64, n0 = blockIdx.x*64;
    int t = threadIdx.x;
    #pragma unroll
    for (int i = 0; i < 4; i++) {
        int idx = t + i*256;
        int r = idx >> 4, c = idx & 15;
        float4 v = *(const float4*)&in[(size_t)(k0 + r)*N + n0 + c*4];
        tile[r][c*4+0] = v.x; tile[r][c*4+1] = v.y;
        tile[r][c*4+2] = v.z; tile[r][c*4+3] = v.w;
    }
    __syncthreads();
    #pragma unroll
    for (int i = 0; i < 8; i++) {
        int idx = t + i*256;
        int n = idx >> 5, c = idx & 31;
        __half2 h = __floats2half2_rn(tile[2*c][n], tile[2*c+1][n]);
        *(__half2*)&out[(size_t)(n0 + n)*K + k0 + 2*c] = h;
    }
}

// ------------------------- silu(c) ------------------------------------------
__global__ void silu_kernel(const float* __restrict__ c) {
    int i = blockIdx.x * 256 + threadIdx.x;
    if (i < BB*HID) {
        float s = c[i];
        g_silu_c[i] = s / (1.f + expf(-s));
    }
}

// ------------------------- adaLN --------------------------------------------
__global__ void adaln_kernel(const float* __restrict__ w_ada,
                             const float* __restrict__ b_ada) {
    int j = blockIdx.x * 256 + threadIdx.x;
    int b = blockIdx.y;
    if (j >= MOD6) return;
    float acc = b_ada[j];
    const float* cs = &g_silu_c[b*HID];
    for (int k = 0; k < HID; k++)
        acc += cs[k] * w_ada[(size_t)k*MOD6 + j];
    g_mod[b*MOD6 + j] = acc;
}

// --------------- fused (optional residual+gate) + LN + modulate -> fp16 -----
__global__ void __launch_bounds__(288)
modulate_kernel(const float* __restrict__ x, const float* __restrict__ res,
                int sh_seg, int sc_seg, int g_seg,
                float* __restrict__ x1_out, __half* __restrict__ mi_out) {
    int r = blockIdx.x, b = r / SEQ, t = threadIdx.x;
    const float* modb = &g_mod[b*MOD6];

    float4 val = *(const float4*)&x[(size_t)r*HID + t*4];
    if (res) {
        float4 rv = *(const float4*)&res[(size_t)r*HID + t*4];
        float4 gv = *(const float4*)&modb[g_seg*HID + t*4];
        val.x = fmaf(gv.x, rv.x, val.x); val.y = fmaf(gv.y, rv.y, val.y);
        val.z = fmaf(gv.z, rv.z, val.z); val.w = fmaf(gv.w, rv.w, val.w);
    }
    if (x1_out) *(float4*)&x1_out[(size_t)r*HID + t*4] = val;

    float s  = val.x + val.y + val.z + val.w;
    float ss = val.x*val.x + val.y*val.y + val.z*val.z + val.w*val.w;
    int lane = t & 31, wid = t >> 5;
    #pragma unroll
    for (int o = 16; o; o >>= 1) {
        s  += __shfl_xor_sync(0xffffffffu, s, o);
        ss += __shfl_xor_sync(0xffffffffu, ss, o);
    }
    __shared__ float sh1[9], sh2[9];
    if (lane == 0) { sh1[wid] = s; sh2[wid] = ss; }
    __syncthreads();
    if (t == 0) {
        float a = 0.f, bb = 0.f;
        #pragma unroll
        for (int i = 0; i < 9; i++) { a += sh1[i]; bb += sh2[i]; }
        sh1[0] = a; sh2[0] = bb;
    }
    __syncthreads();
    float mean = sh1[0] * (1.f/HID);
    float var  = sh2[0] * (1.f/HID) - mean*mean;
    float inv  = rsqrtf(var + 1e-6f);

    float4 sc4 = *(const float4*)&modb[sc_seg*HID + t*4];
    float4 sh4 = *(const float4*)&modb[sh_seg*HID + t*4];
    float y0 = (val.x - mean)*inv*(1.f + sc4.x) + sh4.x;
    float y1 = (val.y - mean)*inv*(1.f + sc4.y) + sh4.y;
    float y2 = (val.z - mean)*inv*(1.f + sc4.z) + sh4.z;
    float y3 = (val.w - mean)*inv*(1.f + sc4.w) + sh4.w;
    __half2 h0 = __floats2half2_rn(y0, y1);
    __half2 h1 = __floats2half2_rn(y2, y3);
    uint2 pk; pk.x = *(uint32_t*)&h0; pk.y = *(uint32_t*)&h1;
    *(uint2*)&mi_out[(size_t)r*HID + t*4] = pk;
}

// ------------------------- fp16 HMMA GEMM (ldmatrix + 3-stage) ---------------
#define AW 36
#define TILE_W (128*AW)
#define GEMM_SMEM (6*TILE_W*4)   // 108 KB

__global__ void __launch_bounds__(128)
gemm_hf(const __half* __restrict__ A, const __half* __restrict__ Bt,
        const float* __restrict__ bias, void* __restrict__ Cout,
        int M, int N, int K, int act, int outH,
        const float* __restrict__ resid, int gate_seg) {
    extern __shared__ uint32_t smw[];
    uint32_t smw_b = (uint32_t)__cvta_generic_to_shared(smw);

    int tid = threadIdx.x, lane = tid & 31, wid = tid >> 5;
    int wm = wid >> 1, wn = wid & 1;
    int row0 = blockIdx.y * 128, col0 = blockIdx.x * 128;
    int lr = lane >> 2, lc = lane & 3;
    int g = lane >> 3, lrow = lane & 7;
    int a_row = wm*64 + (g & 1)*8 + lrow;
    int a_wc  = (g >> 1)*4;
    int b_row = wn*64 + (g >> 1)*8 + lrow;
    int b_wc  = (g & 1)*4;

    float4 acc[4][8];
    #pragma unroll
    for (int i = 0; i < 4; i++)
        #pragma unroll
        for (int j = 0; j < 8; j++) acc[i][j] = make_float4(0.f,0.f,0.f,0.f);

    int KT = K >> 6;

    auto load_stage = [&](int kt, int buf) {
        const __half* gA = A  + (size_t)row0*K + kt*64;
        const __half* gB = Bt + (size_t)col0*K + kt*64;
        uint32_t* as = smw + buf*2*TILE_W;
        uint32_t* bs = as + TILE_W;
        #pragma unroll
        for (int i = 0; i < 8; i++) {
            int chunk = tid + i*128;
            int r = chunk >> 3, c = chunk & 7;
            cp16(&as[r*AW + c*4], gA + (size_t)r*K + c*8);
            cp16(&bs[r*AW + c*4], gB + (size_t)r*K + c*8);
        }
        asm volatile("cp.async.commit_group;");
    };

    load_stage(0, 0);
    if (KT > 1) load_stage(1, 1);

    for (int kt = 0; kt < KT; kt++) {
        if (kt < KT - 1) asm volatile("cp.async.wait_group 1;");
        else             asm volatile("cp.async.wait_group 0;");
        __syncthreads();
        if (kt + 2 < KT) load_stage(kt + 2, (kt + 2) % 3);

        int buf = kt % 3;
        uint32_t as_b = smw_b + buf*2*TILE_W*4;
        uint32_t bs_b = as_b + TILE_W*4;
        #pragma unroll
        for (int k16 = 0; k16 < 4; k16++) {
            uint32_t af[4][4];
            #pragma unroll
            for (int mi = 0; mi < 4; mi++)
                ldsm4(af[mi][0], af[mi][1], af[mi][2], af[mi][3],
                      as_b + (uint32_t)(((a_row + mi*16)*AW) + k16*8 + a_wc)*4);
            uint32_t bf[8][2];
            #pragma unroll
            for (int njp = 0; njp < 4; njp++)
                ldsm4(bf[2*njp][0], bf[2*njp][1], bf[2*njp+1][0], bf[2*njp+1][1],
                      bs_b + (uint32_t)(((b_row + njp*16)*AW) + k16*8 + b_wc)*4);
            #pragma unroll
            for (int mi = 0; mi < 4; mi++)
                #pragma unroll
                for (int nj = 0; nj < 8; nj++)
                    mma_f16(acc[mi][nj], af[mi], bf[nj]);
        }
        __syncthreads();
    }

    #pragma unroll
    for (int mi = 0; mi < 4; mi++) {
        #pragma unroll
        for (int nj = 0; nj < 8; nj++) {
            int r = row0 + wm*64 + mi*16 + lr;
            int c = col0 + wn*64 + nj*8 + 2*lc;
            float v[4] = {acc[mi][nj].x, acc[mi][nj].y, acc[mi][nj].z, acc[mi][nj].w};
            float b0 = bias[c], b1 = bias[c+1];
            v[0] += b0; v[1] += b1; v[2] += b0; v[3] += b1;
            if (act == 1) {
                #pragma unroll
                for (int q = 0; q < 4; q++) v[q] = fast_gelu(v[q]);
            }
            if (outH) {
                __half* Cb = (__half*)Cout;
                __half2 p0 = __floats2half2_rn(v[0], v[1]);
                __half2 p1 = __floats2half2_rn(v[2], v[3]);
                *(__half2*)&Cb[(size_t)r*N + c]     = p0;
                *(__half2*)&Cb[(size_t)(r+8)*N + c] = p1;
            } else {
                float* Cf = (float*)Cout;
                if (resid) {
                    int b = r / SEQ;
                    float g0 = g_mod[b*MOD6 + gate_seg*HID + c];
                    float g1 = g_mod[b*MOD6 + gate_seg*HID + c + 1];
                    v[0] = resid[(size_t)r*N + c]     + g0*v[0];
                    v[1] = resid[(size_t)r*N + c + 1] + g1*v[1];
                    v[2] = resid[(size_t)(r+8)*N + c]     + g0*v[2];
                    v[3] = resid[(size_t)(r+8)*N + c + 1] + g1*v[3];
                }
                *(float2*)&Cf[(size_t)r*N + c]     = make_float2(v[0], v[1]);
                *(float2*)&Cf[(size_t)(r+8)*N + c] = make_float2(v[2], v[3]);
            }
        }
    }
}

// ------------------------- qk-norm (q,k only) -> [B,NH,N,HD] fp16 -----------
__global__ void qknorm_kernel(const float* __restrict__ qn_w, const float* __restrict__ qn_b,
                              const float* __restrict__ kn_w, const float* __restrict__ kn_b) {
    int id = blockIdx.x * 8 + (threadIdx.x >> 5);
    if (id >= MROWS*32) return;
    int lane = threadIdx.x & 31;
    int r = id >> 5;
    int rem = id & 31;
    int w = rem >> 4;      // 0=q, 1=k
    int h = rem & 15;

    const __half* src = &g_qkvh[(size_t)r*3456 + w*1152 + h*72];
    float v0 = __half2float(src[lane]);
    float v1 = __half2float(src[lane + 32]);
    float v2 = (lane < 8) ? __half2float(src[lane + 64]) : 0.f;

    int b = r / SEQ, n = r % SEQ;
    __half* dst = (w == 0 ? g_qh : g_kh)
                 + (((size_t)(b*NHEAD + h)*SEQ + n)*HDIM);

    float s = v0 + v1 + v2;
    float ss = v0*v0 + v1*v1 + v2*v2;
    #pragma unroll
    for (int o = 16; o; o >>= 1) {
        s  += __shfl_xor_sync(0xffffffffu, s, o);
        ss += __shfl_xor_sync(0xffffffffu, ss, o);
    }
    float mean = s * (1.f/72.f);
    float var  = ss * (1.f/72.f) - mean*mean;
    float inv  = rsqrtf(var + 1e-5f);
    const float* ww = (w == 0) ? qn_w : kn_w;
    const float* wb = (w == 0) ? qn_b : kn_b;
    dst[lane]      = __float2half((v0 - mean)*inv*ww[lane]      + wb[lane]);
    dst[lane + 32] = __float2half((v1 - mean)*inv*ww[lane + 32] + wb[lane + 32]);
    if (lane < 8)
        dst[lane + 64] = __float2half((v2 - mean)*inv*ww[lane + 64] + wb[lane + 64]);
}

// ------------------------- V transpose: qkv v-slice -> [b][h][d][SEQ] -------
__global__ void __launch_bounds__(128) vtrans_kernel() {
    __shared__ uint32_t tile[64*37];   // stride 37 words = 74 halves
    int kt = blockIdx.x, h = blockIdx.y, b = blockIdx.z;
    int t = threadIdx.x;
    const uint32_t* src32 = (const uint32_t*)g_qkvh;

    for (int i = t; i < 64*36; i += 128) {
        int key = i / 36, w = i % 36;
        size_t off = ((size_t)(b*SEQ + kt*64 + key)*3456 + 2304 + h*72) / 2 + w;
        tile[key*37 + w] = src32[off];
    }
    __syncthreads();
    const __half* tileh = (const __half*)tile;
    uint32_t* dst32 = (uint32_t*)g_vth;
    for (int i = t; i < 72*32; i += 128) {
        int d = i / 32, w2 = i % 32;
        __half2 p;
        p.x = tileh[(2*w2)*74 + d];
        p.y = tileh[(2*w2 + 1)*74 + d];
        dst32[((size_t)((b*NHEAD + h)*HDIM + d)*SEQ)/2 + kt*32 + w2] = *(uint32_t*)&p;
    }
}

// ------------------------- fp16 tensor-core flash attention -----------------
// cp.async double-buffered K/V (V pre-transposed); P kept in REGISTERS
// (S-accumulator layout == PV A-fragment layout), no P smem round trip.
#define AT_QW (128*36)
#define AT_KW (64*36)
#define AT_VW (72*36)
#define ATTN_SMEM ((AT_QW + 2*AT_KW + 2*AT_VW)*4)   // 57.6 KB -> 3 CTAs/SM

__global__ void __launch_bounds__(256) attn_h() {
    extern __shared__ uint32_t smw[];
    uint32_t* Qs = smw;
    uint32_t* Kb = Qs + AT_QW;           // [2][64][36]
    uint32_t* Vb = Kb + 2*AT_KW;         // [2][72][36] (V^T rows = d)

    int b = blockIdx.z, h = blockIdx.y, q0 = blockIdx.x*128;
    int tid = threadIdx.x, lane = tid & 31, wid = tid >> 5;
    int lr = lane >> 2, lc = lane & 3;
    int wr = wid * 16;
    size_t base = (size_t)(b*NHEAD + h) * SEQ * HDIM;
    const __half* vbase = &g_vth[(size_t)(b*NHEAD + h) * HDIM * SEQ];
    const float scale = 0.11785113019775793f;

    auto load_stage = [&](int t, int buf) {
        const __half* kg = &g_kh[base + (size_t)(t*64)*HDIM];
        for (int i = tid; i < 576; i += 256) {
            int r = i / 9, c = i % 9;
            cp16(&Kb[buf*AT_KW + r*36 + c*4], kg + r*HDIM + c*8);
        }
        const __half* vg = vbase + t*64;
        for (int i = tid; i < 576; i += 256) {
            int d = i >> 3, c = i & 7;
            cp16(&Vb[buf*AT_VW + d*36 + c*4], vg + (size_t)d*SEQ + c*8);
        }
        asm volatile("cp.async.commit_group;");
    };

    {
        const uint4* qg = (const uint4*)&g_qh[base + (size_t)q0*HDIM];
        for (int i = tid; i < 128*9; i += 256) {
            int r = i / 9, c = i % 9;
            *(uint4*)&Qs[r*36 + c*4] = qg[i];
        }
    }
    load_stage(0, 0);

    float4 o[9];
    #pragma unroll
    for (int i = 0; i < 9; i++) o[i] = make_float4(0.f,0.f,0.f,0.f);
    float m_lo = -INFINITY, m_hi = -INFINITY, l_lo = 0.f, l_hi = 0.f;

    for (int t = 0; t < 16; t++) {
        asm volatile("cp.async.wait_group 0;");
        __syncthreads();
        if (t + 1 < 16) load_stage(t + 1, (t + 1) & 1);
        int buf = t & 1;
        const uint32_t* Ks = &Kb[buf*AT_KW];
        const uint32_t* Vt = &Vb[buf*AT_VW];

        float4 sc[8];
        #pragma unroll
        for (int i = 0; i < 8; i++) sc[i] = make_float4(0.f,0.f,0.f,0.f);
        #pragma unroll
        for (int k16 = 0; k16 < 4; k16++) {
            int kw = k16*8 + lc;
            uint32_t af[4];
            af[0] = Qs[(wr+lr)*36 + kw];
            af[1] = Qs[(wr+8+lr)*36 + kw];
            af[2] = Qs[(wr+lr)*36 + kw + 4];
            af[3] = Qs[(wr+8+lr)*36 + kw + 4];
            #pragma unroll
            for (int nj = 0; nj < 8; nj++) {
                int cc = nj*8 + lr;
                uint32_t bf[2] = {Ks[cc*36 + kw], Ks[cc*36 + kw + 4]};
                mma_f16(sc[nj], af, bf);
            }
        }
        {
            int kw = 32 + lc;
            uint32_t a0 = Qs[(wr+lr)*36 + kw];
            uint32_t a1 = Qs[(wr+8+lr)*36 + kw];
            #pragma unroll
            for (int nj = 0; nj < 8; nj++) {
                int cc = nj*8 + lr;
                mma_f16_k8(sc[nj], a0, a1, Ks[cc*36 + kw]);
            }
        }

        float tmax_lo = -INFINITY, tmax_hi = -INFINITY;
        #pragma unroll
        for (int nj = 0; nj < 8; nj++) {
            sc[nj].x *= scale; sc[nj].y *= scale; sc[nj].z *= scale; sc[nj].w *= scale;
            tmax_lo = fmaxf(tmax_lo, fmaxf(sc[nj].x, sc[nj].y));
            tmax_hi = fmaxf(tmax_hi, fmaxf(sc[nj].z, sc[nj].w));
        }
        tmax_lo = fmaxf(tmax_lo, __shfl_xor_sync(0xffffffffu, tmax_lo, 1));
        tmax_lo = fmaxf(tmax_lo, __shfl_xor_sync(0xffffffffu, tmax_lo, 2));
        tmax_hi = fmaxf(tmax_hi, __shfl_xor_sync(0xffffffffu, tmax_hi, 1));
        tmax_hi = fmaxf(tmax_hi, __shfl_xor_sync(0xffffffffu, tmax_hi, 2));

        float mn_lo = fmaxf(m_lo, tmax_lo);
        float mn_hi = fmaxf(m_hi, tmax_hi);
        float corr_lo = __expf(m_lo - mn_lo);
        float corr_hi = __expf(m_hi - mn_hi);
        l_lo *= corr_lo; l_hi *= corr_hi;
        #pragma unroll
        for (int i = 0; i < 9; i++) {
            o[i].x *= corr_lo; o[i].y *= corr_lo;
            o[i].z *= corr_hi; o[i].w *= corr_hi;
        }
        // P in registers: ph[nj][0] = rows lr (cols nj*8+2lc..), ph[nj][1] = rows lr+8
        uint32_t ph[8][2];
        float sum_lo = 0.f, sum_hi = 0.f;
        #pragma unroll
        for (int nj = 0; nj < 8; nj++) {
            float px = __expf(sc[nj].x - mn_lo);
            float py = __expf(sc[nj].y - mn_lo);
            float pz = __expf(sc[nj].z - mn_hi);
            float pw = __expf(sc[nj].w - mn_hi);
            sum_lo += px + py; sum_hi += pz + pw;
            __half2 plo = __floats2half2_rn(px, py);
            __half2 phi = __floats2half2_rn(pz, pw);
            ph[nj][0] = *(uint32_t*)&plo;
            ph[nj][1] = *(uint32_t*)&phi;
        }
        sum_lo += __shfl_xor_sync(0xffffffffu, sum_lo, 1);
        sum_lo += __shfl_xor_sync(0xffffffffu, sum_lo, 2);
        sum_hi += __shfl_xor_sync(0xffffffffu, sum_hi, 1);
        sum_hi += __shfl_xor_sync(0xffffffffu, sum_hi, 2);
        l_lo += sum_lo; l_hi += sum_hi;
        m_lo = mn_lo; m_hi = mn_hi;

        // O += P V  (A fragment comes straight from ph registers)
        #pragma unroll
        for (int k16 = 0; k16 < 4; k16++) {
            int kw = k16*8 + lc;
            uint32_t af[4];
            af[0] = ph[2*k16][0];
            af[1] = ph[2*k16][1];
            af[2] = ph[2*k16+1][0];
            af[3] = ph[2*k16+1][1];
            #pragma unroll
            for (int n9 = 0; n9 < 9; n9++) {
                int cc = n9*8 + lr;
                uint32_t bf[2] = {Vt[cc*36 + kw], Vt[cc*36 + kw + 4]};
                mma_f16(o[n9], af, bf);
            }
        }
    }

    float inv_lo = 1.f / l_lo, inv_hi = 1.f / l_hi;
    int r = b*SEQ + q0 + wr + lr;
    #pragma unroll
    for (int n9 = 0; n9 < 9; n9++) {
        int c = h*HDIM + n9*8 + 2*lc;
        __half2 p0 = __floats2half2_rn(o[n9].x*inv_lo, o[n9].y*inv_lo);
        __half2 p1 = __floats2half2_rn(o[n9].z*inv_hi, o[n9].w*inv_hi);
        *(__half2*)&g_oh[(size_t)r*HID + c]     = p0;
        *(__half2*)&g_oh[(size_t)(r+8)*HID + c] = p1;
    }
}

// ---------------------------------------------------------------------------
extern "C" void kernel_launch(void* const* d_in, const int* in_sizes, int n_in,
                              void* d_out, int out_size) {
    const float* x      = (const float*)d_in[0];
    const float* c      = (const float*)d_in[1];
    const float* w_ada  = (const float*)d_in[2];
    const float* b_ada  = (const float*)d_in[3];
    const float* w_qkv  = (const float*)d_in[4];
    const float* b_qkv  = (const float*)d_in[5];
    const float* qn_w   = (const float*)d_in[6];
    const float* qn_b   = (const float*)d_in[7];
    const float* kn_w   = (const float*)d_in[8];
    const float* kn_b   = (const float*)d_in[9];
    const float* w_proj = (const float*)d_in[10];
    const float* b_proj = (const float*)d_in[11];
    const float* w_fc1  = (const float*)d_in[12];
    const float* b_fc1  = (const float*)d_in[13];
    const float* w_fc2  = (const float*)d_in[14];
    const float* b_fc2  = (const float*)d_in[15];
    float* out = (float*)d_out;

    float *p_x1;
    __half *p_aih, *p_qkvh, *p_oh, *p_mih, *p_hh;
    __half *p_wqkt, *p_wpt, *p_wf1t, *p_wf2t;
    cudaGetSymbolAddress((void**)&p_x1,   g_x1);
    cudaGetSymbolAddress((void**)&p_aih,  g_aih);
    cudaGetSymbolAddress((void**)&p_qkvh, g_qkvh);
    cudaGetSymbolAddress((void**)&p_oh,   g_oh);
    cudaGetSymbolAddress((void**)&p_mih,  g_mih);
    cudaGetSymbolAddress((void**)&p_hh,   g_hh);
    cudaGetSymbolAddress((void**)&p_wqkt, g_wqkt);
    cudaGetSymbolAddress((void**)&p_wpt,  g_wpt);
    cudaGetSymbolAddress((void**)&p_wf1t, g_wf1t);
    cudaGetSymbolAddress((void**)&p_wf2t, g_wf2t);

    static int attr_set = 0;
    if (!attr_set) {
        cudaFuncSetAttribute(gemm_hf, cudaFuncAttributeMaxDynamicSharedMemorySize, GEMM_SMEM);
        cudaFuncSetAttribute(attn_h, cudaFuncAttributeMaxDynamicSharedMemorySize, ATTN_SMEM);
        attr_set = 1;
    }

    wtrans_kernel<<<dim3(HID/64, DFF/64), 256>>>(w_fc2, p_wf2t, DFF, HID);
    silu_kernel<<<(BB*HID + 255)/256, 256>>>(c);
    adaln_kernel<<<dim3(MOD6/256, BB), 256>>>(w_ada, b_ada);
    modulate_kernel<<<MROWS, 288>>>(x, nullptr, 0, 1, -1, nullptr, p_aih);
    wtrans_kernel<<<dim3(3*HID/64, HID/64), 256>>>(w_qkv, p_wqkt, HID, 3*HID);
    gemm_hf<<<dim3(3*HID/128, MROWS/128), 128, GEMM_SMEM>>>(p_aih, p_wqkt, b_qkv, p_qkvh,
                                                            MROWS, 3*HID, HID, 0, 1, nullptr, 0);
    qknorm_kernel<<<MROWS*32/8, 256>>>(qn_w, qn_b, kn_w, kn_b);
    vtrans_kernel<<<dim3(SEQ/64, NHEAD, BB), 128>>>();
    wtrans_kernel<<<dim3(HID/64, HID/64), 256>>>(w_proj, p_wpt, HID, HID);
    wtrans_kernel<<<dim3(DFF/64, HID/64), 256>>>(w_fc1, p_wf1t, HID, DFF);
    attn_h<<<dim3(SEQ/128, NHEAD, BB), 256, ATTN_SMEM>>>();
    // proj with fused residual: x1 = x + g_msa * (o @ w_proj + b)
    gemm_hf<<<dim3(HID/128, MROWS/128), 128, GEMM_SMEM>>>(p_oh, p_wpt, b_proj, p_x1,
                                                          MROWS, HID, HID, 0, 0, x, 2);
    // mi = modulate(x1)  (no residual pass needed)
    modulate_kernel<<<MROWS, 288>>>(p_x1, nullptr, 3, 4, -1, nullptr, p_mih);
    gemm_hf<<<dim3(DFF/128, MROWS/128), 128, GEMM_SMEM>>>(p_mih, p_wf1t, b_fc1, p_hh,
                                                          MROWS, DFF, HID, 1, 1, nullptr, 0);
    gemm_hf<<<dim3(HID/128, MROWS/128), 128, GEMM_SMEM>>>(p_hh, p_wf2t, b_fc2, out,
                                                          MROWS, HID, DFF, 0, 0, p_x1, 5);
}